// round 10
// baseline (speedup 1.0000x reference)
#include <cuda_runtime.h>
#include <cuda_bf16.h>
#include <cstdint>

#define BB 16
#define DD 1024
#define QQ 128
#define HH 1024

// ---------------- scratch (device globals) ----------------------------------
__device__ float g_S [BB * DD * QQ];
__device__ float g_sq[BB * QQ];
__device__ float g_cmax[BB * 16 * 128];
__device__ float g_csum[BB * 16 * 128];
// bf16 hi/lo operand arrays (all NATURAL orientation)
__device__ __nv_bfloat16 g_Uqwh[BB * QQ * HH], g_Uqwl[BB * QQ * HH];  // Uq*wdot [b,q,h]
__device__ __nv_bfloat16 g_Uqph[BB * QQ * HH], g_Uqpl[BB * QQ * HH];  // Uq plain [b,q,h]
__device__ __nv_bfloat16 g_P1h [BB * DD * QQ], g_P1l [BB * DD * QQ];  // S_d2q [b,d,q]
__device__ __nv_bfloat16 g_P2th[BB * QQ * DD], g_P2tl[BB * QQ * DD];  // S_q2d^T [b,q,d]
__device__ __nv_bfloat16 g_Th  [BB * QQ * HH], g_Tl  [BB * QQ * HH];  // T [b,q,h]

// ---------------- helpers ----------------------------------------------------
__device__ __forceinline__ uint32_t smem_u32(const void* p) {
    uint32_t a;
    asm("{ .reg .u64 t; cvta.to.shared.u64 t, %1; cvt.u32.u64 %0, t; }" : "=r"(a) : "l"(p));
    return a;
}
__device__ __forceinline__ uint32_t L32(const __nv_bfloat16* p) {
    return *(const uint32_t*)p;
}
__device__ __forceinline__ void mma_bf16(float* c, const uint32_t* a, const uint32_t* b) {
    asm volatile(
        "mma.sync.aligned.m16n8k16.row.col.f32.bf16.bf16.f32 "
        "{%0,%1,%2,%3}, {%4,%5,%6,%7}, {%8,%9}, {%0,%1,%2,%3};"
        : "+f"(c[0]), "+f"(c[1]), "+f"(c[2]), "+f"(c[3])
        : "r"(a[0]), "r"(a[1]), "r"(a[2]), "r"(a[3]), "r"(b[0]), "r"(b[1]));
}
__device__ __forceinline__ void ldmx4t(uint32_t& r0, uint32_t& r1,
                                       uint32_t& r2, uint32_t& r3, uint32_t a) {
    asm volatile("ldmatrix.sync.aligned.m8n8.x4.trans.shared.b16 {%0,%1,%2,%3}, [%4];"
        : "=r"(r0), "=r"(r1), "=r"(r2), "=r"(r3) : "r"(a));
}
__device__ __forceinline__ void bsplit(float x, __nv_bfloat16& h, __nv_bfloat16& l) {
    h = __float2bfloat16(x);
    l = __float2bfloat16(x - __bfloat162float(h));
}
#define CPA16(sa, g) \
    asm volatile("cp.async.cg.shared.global [%0], [%1], 16;" :: "r"(sa), "l"(g))
#define CPA_COMMIT() asm volatile("cp.async.commit_group;" ::: "memory")
#define CPA_WAIT0()  asm volatile("cp.async.wait_group 0;" ::: "memory")

// A fragments: MI m16-tiles, warp m base MB, K-contiguous layout stride ST
#define LOAD_AFR(sAh, sAl, ST, MI, MB)                                        \
    uint32_t ah[4][4], al[4][4];                                              \
    _Pragma("unroll")                                                         \
    for (int i = 0; i < (MI); i++) {                                          \
        int r = (MB) + i * 16 + gr;                                           \
        const __nv_bfloat16* p = (sAh) + r * (ST) + kb + 2 * qp;              \
        const __nv_bfloat16* q = (sAl) + r * (ST) + kb + 2 * qp;              \
        ah[i][0] = L32(p);            ah[i][1] = L32(p + 8 * (ST));           \
        ah[i][2] = L32(p + 8);        ah[i][3] = L32(p + 8 * (ST) + 8);       \
        al[i][0] = L32(q);            al[i][1] = L32(q + 8 * (ST));           \
        al[i][2] = L32(q + 8);        al[i][3] = L32(q + 8 * (ST) + 8);       \
    }

#define MMA3P(ACC, MI, NJ, BH, BL)                                            \
    _Pragma("unroll")                                                         \
    for (int i = 0; i < (MI); i++)                                            \
        _Pragma("unroll")                                                     \
        for (int j = 0; j < (NJ); j++) mma_bf16((ACC)[i][j], ah[i], (BH)[j]); \
    _Pragma("unroll")                                                         \
    for (int i = 0; i < (MI); i++)                                            \
        _Pragma("unroll")                                                     \
        for (int j = 0; j < (NJ); j++) mma_bf16((ACC)[i][j], ah[i], (BL)[j]); \
    _Pragma("unroll")                                                         \
    for (int i = 0; i < (MI); i++)                                            \
        _Pragma("unroll")                                                     \
        for (int j = 0; j < (NJ); j++) mma_bf16((ACC)[i][j], al[i], (BH)[j]);

// K-contiguous B fragments
#define LOAD_BFR_K(sBh, sBl, ST, NJ, NB, BH, BL)                              \
    _Pragma("unroll")                                                         \
    for (int j = 0; j < (NJ); j++) {                                          \
        int c = (NB) + j * 8 + gr;                                            \
        const __nv_bfloat16* p = (sBh) + c * (ST) + kb + 2 * qp;              \
        const __nv_bfloat16* q = (sBl) + c * (ST) + kb + 2 * qp;              \
        BH[j][0] = L32(p); BH[j][1] = L32(p + 8);                             \
        BL[j][0] = L32(q); BL[j][1] = L32(q + 8);                             \
    }

// [k][n]-layout B fragments via ldmatrix.trans; NJ2 groups of 16 columns
#define LOAD_BFR_T(bBh, bBl, STB, NJ2, NB, BH, BL)                            \
    _Pragma("unroll")                                                         \
    for (int jj = 0; jj < (NJ2); jj++) {                                      \
        int c0 = (NB) + jj * 16;                                              \
        uint32_t off = (uint32_t)(((kb + (lane & 15)) * (STB) + c0 +          \
                                   ((lane >> 4) * 8)) * 2);                   \
        ldmx4t(BH[2*jj][0], BH[2*jj][1], BH[2*jj+1][0], BH[2*jj+1][1], (bBh) + off); \
        ldmx4t(BL[2*jj][0], BL[2*jj][1], BL[2*jj+1][0], BL[2*jj+1][1], (bBl) + off); \
    }

#define GEMM_IDS                                                              \
    int t = threadIdx.x;                                                      \
    int wid = t >> 5, lane = t & 31;                                          \
    int wm = wid >> 2, wn = wid & 3;                                          \
    int gr = lane >> 2, qp = lane & 3;                                        \
    int srow = t >> 2, srow2 = (t >> 2) + 64, kc = (t & 3) * 8;

#define ACC_INITN(A, MI, NJ)                                                  \
    _Pragma("unroll")                                                         \
    for (int i = 0; i < (MI); i++)                                            \
        _Pragma("unroll")                                                     \
        for (int j = 0; j < (NJ); j++)                                        \
            _Pragma("unroll")                                                 \
            for (int e = 0; e < 4; e++) (A)[i][j][e] = 0.f;

// ---------------- conv_uq: Uq -> Uqw(hi/lo) + Uqp(hi/lo), plus s_q -----------
__global__ void conv_uq_kernel(const float* __restrict__ Uq,
                               const float* __restrict__ wcw) {
    __shared__ float red[8];
    int row = blockIdx.x;
    int t = threadIdx.x;
    const float* src = Uq + (size_t)row * HH;
    float4 v = *(const float4*)(src + t * 4);
    float4 wd = *(const float4*)(wcw + 2 * HH + t * 4);
    float4 wq = *(const float4*)(wcw + HH + t * 4);
    __nv_bfloat16 h0, l0, h1, l1, h2, l2, h3, l3;
    bsplit(v.x, h0, l0); bsplit(v.y, h1, l1);
    bsplit(v.z, h2, l2); bsplit(v.w, h3, l3);
    size_t o = (size_t)row * HH + t * 4;
    *(__nv_bfloat162*)(g_Uqph + o)     = __nv_bfloat162(h0, h1);
    *(__nv_bfloat162*)(g_Uqph + o + 2) = __nv_bfloat162(h2, h3);
    *(__nv_bfloat162*)(g_Uqpl + o)     = __nv_bfloat162(l0, l1);
    *(__nv_bfloat162*)(g_Uqpl + o + 2) = __nv_bfloat162(l2, l3);
    float4 s = make_float4(v.x * wd.x, v.y * wd.y, v.z * wd.z, v.w * wd.w);
    bsplit(s.x, h0, l0); bsplit(s.y, h1, l1);
    bsplit(s.z, h2, l2); bsplit(s.w, h3, l3);
    *(__nv_bfloat162*)(g_Uqwh + o)     = __nv_bfloat162(h0, h1);
    *(__nv_bfloat162*)(g_Uqwh + o + 2) = __nv_bfloat162(h2, h3);
    *(__nv_bfloat162*)(g_Uqwl + o)     = __nv_bfloat162(l0, l1);
    *(__nv_bfloat162*)(g_Uqwl + o + 2) = __nv_bfloat162(l2, l3);
    float p = v.x * wq.x + v.y * wq.y + v.z * wq.z + v.w * wq.w;
    #pragma unroll
    for (int off = 16; off; off >>= 1) p += __shfl_xor_sync(0xffffffffu, p, off);
    if ((t & 31) == 0) red[t >> 5] = p;
    __syncthreads();
    if (t == 0) {
        float sum = 0.f;
        #pragma unroll
        for (int j = 0; j < 8; j++) sum += red[j];
        g_sq[row] = sum;
    }
}

// ---------------- GEMM1 fused: m-tile 64, 256 CTAs, 2 CTA/SM -----------------
// stage bytes: Ah@0 5120 | Al@5120 | Bh@10240 10240 | Bl@20480 10240 = 30720; x2
__global__ __launch_bounds__(256, 2) void gemm1_mma(
    const float* __restrict__ Ud, const float* __restrict__ wcw,
    const float* __restrict__ wcb,
    const int* __restrict__ qm, const int* __restrict__ dmk) {
    extern __shared__ __nv_bfloat16 dyn[];
    __shared__ float redM[64][4], redS[64][4];
    __shared__ float2 colp[2][128];
    __shared__ int s_qm[128];
    __shared__ float s_sdv[64];
    __shared__ float s_wd[HH];
    GEMM_IDS
    int b = blockIdx.y, m0 = blockIdx.x * 64;
    const float* A = Ud + (size_t)b * DD * HH + (size_t)m0 * HH;
    const __nv_bfloat16* Bh = g_Uqwh + (size_t)b * QQ * HH;
    const __nv_bfloat16* Bl = g_Uqwl + (size_t)b * QQ * HH;
    float acc[2][4][4];
    ACC_INITN(acc, 2, 4)
    float sdp[2] = {0.f, 0.f};
    if (t < 128) s_qm[t] = qm[b * QQ + t];
    #pragma unroll
    for (int i = t; i < HH; i += 256) s_wd[i] = wcw[i];
    uint32_t sb = smem_u32(dyn);

    float4 pref[2];
    #pragma unroll
    for (int v = 0; v < 2; v++) {
        int idx = v * 256 + t;
        pref[v] = *(const float4*)(A + (size_t)(idx >> 3) * HH + (idx & 7) * 4);
    }
    {
        uint32_t sbB = sb + 10240;
        CPA16(sbB +         srow  * 80 + kc * 2, Bh + (size_t)srow  * HH + kc);
        CPA16(sbB +         srow2 * 80 + kc * 2, Bh + (size_t)srow2 * HH + kc);
        CPA16(sbB + 10240 + srow  * 80 + kc * 2, Bl + (size_t)srow  * HH + kc);
        CPA16(sbB + 10240 + srow2 * 80 + kc * 2, Bl + (size_t)srow2 * HH + kc);
        CPA_COMMIT();
    }
    __syncthreads();   // s_wd ready

    for (int it = 0; it < HH / 32; it++) {
        CPA_WAIT0();
        __nv_bfloat16* As = dyn + (it & 1) * 15360;
        #pragma unroll
        for (int v = 0; v < 2; v++) {
            int idx = v * 256 + t;
            int row = idx >> 3, cs = (idx & 7) * 4;
            float4 x = pref[v];
            float4 w = *(const float4*)(s_wd + it * 32 + cs);
            sdp[v] += x.x * w.x + x.y * w.y + x.z * w.z + x.w * w.w;
            __nv_bfloat16 h0, l0, h1, l1, h2, l2, h3, l3;
            bsplit(x.x, h0, l0); bsplit(x.y, h1, l1);
            bsplit(x.z, h2, l2); bsplit(x.w, h3, l3);
            *(__nv_bfloat162*)(As + row * 40 + cs)            = __nv_bfloat162(h0, h1);
            *(__nv_bfloat162*)(As + row * 40 + cs + 2)        = __nv_bfloat162(h2, h3);
            *(__nv_bfloat162*)(As + 2560 + row * 40 + cs)     = __nv_bfloat162(l0, l1);
            *(__nv_bfloat162*)(As + 2560 + row * 40 + cs + 2) = __nv_bfloat162(l2, l3);
        }
        __syncthreads();
        if (it + 1 < HH / 32) {
            int k0 = (it + 1) * 32;
            uint32_t sbB = sb + ((it + 1) & 1) * 30720 + 10240;
            CPA16(sbB +         srow  * 80 + kc * 2, Bh + (size_t)srow  * HH + k0 + kc);
            CPA16(sbB +         srow2 * 80 + kc * 2, Bh + (size_t)srow2 * HH + k0 + kc);
            CPA16(sbB + 10240 + srow  * 80 + kc * 2, Bl + (size_t)srow  * HH + k0 + kc);
            CPA16(sbB + 10240 + srow2 * 80 + kc * 2, Bl + (size_t)srow2 * HH + k0 + kc);
            CPA_COMMIT();
            #pragma unroll
            for (int v = 0; v < 2; v++) {
                int idx = v * 256 + t;
                pref[v] = *(const float4*)(A + (size_t)(idx >> 3) * HH + k0 + (idx & 7) * 4);
            }
        }
        const __nv_bfloat16* cA = dyn + (it & 1) * 15360;
        const __nv_bfloat16* cB = cA + 5120;
        #pragma unroll
        for (int kb = 0; kb < 32; kb += 16) {
            LOAD_AFR(cA, cA + 2560, 40, 2, wm * 32)
            uint32_t bh[4][2], bl[4][2];
            LOAD_BFR_K(cB, cB + 5120, 40, 4, wn * 32, bh, bl)
            MMA3P(acc, 2, 4, bh, bl)
        }
    }

    // s_d reduce (8 threads per row)
    #pragma unroll
    for (int v = 0; v < 2; v++) {
        float s = sdp[v];
        s += __shfl_xor_sync(0xffffffffu, s, 1);
        s += __shfl_xor_sync(0xffffffffu, s, 2);
        s += __shfl_xor_sync(0xffffffffu, s, 4);
        if ((lane & 7) == 0) s_sdv[v * 32 + (t >> 3)] = s;
    }

    float bias = wcb[0];
    int dmv[2][2];
    #pragma unroll
    for (int i = 0; i < 2; i++)
        #pragma unroll
        for (int rr = 0; rr < 2; rr++)
            dmv[i][rr] = dmk[b * DD + m0 + wm * 32 + i * 16 + rr * 8 + gr];
    __syncthreads();
    float sdv[2][2];
    #pragma unroll
    for (int i = 0; i < 2; i++)
        #pragma unroll
        for (int rr = 0; rr < 2; rr++)
            sdv[i][rr] = s_sdv[wm * 32 + i * 16 + rr * 8 + gr] + bias;

    #pragma unroll
    for (int i = 0; i < 2; i++)
        #pragma unroll
        for (int j = 0; j < 4; j++) {
            int n = wn * 32 + j * 8 + 2 * qp;
            float sq0 = g_sq[b * QQ + n], sq1 = g_sq[b * QQ + n + 1];
            int q0 = s_qm[n] > 0, q1 = s_qm[n + 1] > 0;
            #pragma unroll
            for (int rr = 0; rr < 2; rr++) {
                int m = m0 + wm * 32 + i * 16 + rr * 8 + gr;
                float s0 = acc[i][j][2 * rr]     + sdv[i][rr] + sq0;
                float s1 = acc[i][j][2 * rr + 1] + sdv[i][rr] + sq1;
                *(float2*)(g_S + ((size_t)b * DD + m) * QQ + n) = make_float2(s0, s1);
                int dm = dmv[i][rr] > 0;
                acc[i][j][2 * rr]     = (dm && q0) ? s0 : -1e30f;
                acc[i][j][2 * rr + 1] = (dm && q1) ? s1 : -1e30f;
            }
        }

    // row softmax max
    float M[2][2];
    #pragma unroll
    for (int i = 0; i < 2; i++)
        #pragma unroll
        for (int rr = 0; rr < 2; rr++) {
            float mx = -1e30f;
            #pragma unroll
            for (int j = 0; j < 4; j++)
                mx = fmaxf(mx, fmaxf(acc[i][j][2 * rr], acc[i][j][2 * rr + 1]));
            mx = fmaxf(mx, __shfl_xor_sync(0xffffffffu, mx, 1));
            mx = fmaxf(mx, __shfl_xor_sync(0xffffffffu, mx, 2));
            if (qp == 0) redM[wm * 32 + i * 16 + rr * 8 + gr][wn] = mx;
        }
    __syncthreads();
    #pragma unroll
    for (int i = 0; i < 2; i++)
        #pragma unroll
        for (int rr = 0; rr < 2; rr++) {
            int r = wm * 32 + i * 16 + rr * 8 + gr;
            M[i][rr] = fmaxf(fmaxf(redM[r][0], redM[r][1]),
                             fmaxf(redM[r][2], redM[r][3]));
        }
    // row softmax sum
    float inv[2][2];
    #pragma unroll
    for (int i = 0; i < 2; i++)
        #pragma unroll
        for (int rr = 0; rr < 2; rr++) {
            float s = 0.f;
            #pragma unroll
            for (int j = 0; j < 4; j++) {
                s += __expf(acc[i][j][2 * rr]     - M[i][rr]);
                s += __expf(acc[i][j][2 * rr + 1] - M[i][rr]);
            }
            s += __shfl_xor_sync(0xffffffffu, s, 1);
            s += __shfl_xor_sync(0xffffffffu, s, 2);
            if (qp == 0) redS[wm * 32 + i * 16 + rr * 8 + gr][wn] = s;
        }
    __syncthreads();
    #pragma unroll
    for (int i = 0; i < 2; i++)
        #pragma unroll
        for (int rr = 0; rr < 2; rr++) {
            int r = wm * 32 + i * 16 + rr * 8 + gr;
            inv[i][rr] = 1.f / (redS[r][0] + redS[r][1] + redS[r][2] + redS[r][3]);
        }
    // P1 write
    #pragma unroll
    for (int i = 0; i < 2; i++)
        #pragma unroll
        for (int j = 0; j < 4; j++) {
            int n = wn * 32 + j * 8 + 2 * qp;
            int q0 = s_qm[n] > 0, q1 = s_qm[n + 1] > 0;
            #pragma unroll
            for (int rr = 0; rr < 2; rr++) {
                int m = m0 + wm * 32 + i * 16 + rr * 8 + gr;
                int dm = dmv[i][rr] > 0;
                float p0 = (dm && q0) ? __expf(acc[i][j][2 * rr]     - M[i][rr]) * inv[i][rr] : 0.f;
                float p1 = (dm && q1) ? __expf(acc[i][j][2 * rr + 1] - M[i][rr]) * inv[i][rr] : 0.f;
                __nv_bfloat16 h0, l0, h1, l1;
                bsplit(p0, h0, l0); bsplit(p1, h1, l1);
                size_t o = ((size_t)b * DD + m) * QQ + n;
                *(__nv_bfloat162*)(g_P1h + o) = __nv_bfloat162(h0, h1);
                *(__nv_bfloat162*)(g_P1l + o) = __nv_bfloat162(l0, l1);
            }
        }
    // column partials (64 rows of this block)
    #pragma unroll
    for (int j = 0; j < 4; j++)
        #pragma unroll
        for (int cc = 0; cc < 2; cc++) {
            float cm = -1e30f;
            #pragma unroll
            for (int i = 0; i < 2; i++)
                #pragma unroll
                for (int rr = 0; rr < 2; rr++)
                    cm = fmaxf(cm, acc[i][j][2 * rr + cc]);
            float cs = 0.f;
            #pragma unroll
            for (int i = 0; i < 2; i++)
                #pragma unroll
                for (int rr = 0; rr < 2; rr++)
                    cs += __expf(acc[i][j][2 * rr + cc] - cm);
            #pragma unroll
            for (int o = 4; o <= 16; o <<= 1) {
                float om = __shfl_xor_sync(0xffffffffu, cm, o);
                float os = __shfl_xor_sync(0xffffffffu, cs, o);
                float nm = fmaxf(cm, om);
                cs = cs * __expf(cm - nm) + os * __expf(om - nm);
                cm = nm;
            }
            if (gr == 0) colp[wm][wn * 32 + j * 8 + 2 * qp + cc] = make_float2(cm, cs);
        }
    __syncthreads();
    if (t < 128) {
        float2 a = colp[0][t], c = colp[1][t];
        float nm = fmaxf(a.x, c.x);
        float s = a.y * __expf(a.x - nm) + c.y * __expf(c.x - nm);
        int idx = (b * 16 + blockIdx.x) * 128 + t;
        g_cmax[idx] = nm; g_csum[idx] = s;
    }
}

// ---------------- single-pass q2d softmax -> P2t hi/lo -----------------------
__global__ void softmax_q2d_kernel(const int* __restrict__ qm,
                                   const int* __restrict__ dmk) {
    __shared__ float sM[32], sI[32];
    __shared__ float tile[32][33];
    int b = blockIdx.y;
    int tx = threadIdx.x, ty = threadIdx.y;
    int q = blockIdx.x * 32 + tx;
    int qmv = qm[b * QQ + q];
    int tid = ty * 32 + tx;
    if (tid < 32) {
        int qq = blockIdx.x * 32 + tid;
        float m = -1e30f, s = 0.f;
        #pragma unroll
        for (int k = 0; k < 16; k++) {
            float mk = g_cmax[(b * 16 + k) * 128 + qq];
            float sk = g_csum[(b * 16 + k) * 128 + qq];
            float nm = fmaxf(m, mk);
            s = s * __expf(m - nm) + sk * __expf(mk - nm);
            m = nm;
        }
        sM[tid] = m; sI[tid] = 1.f / s;
    }
    __syncthreads();
    float M = sM[tx], inv = sI[tx];
    const float* base = g_S + (size_t)b * DD * QQ + q;
    int qr = tid >> 3, seg = (tid & 7) * 4;
    size_t drow = (size_t)b * QQ * DD + (size_t)(blockIdx.x * 32 + qr) * DD;
    for (int d0 = 0; d0 < DD; d0 += 32) {
        #pragma unroll
        for (int dj = ty; dj < 32; dj += 8) {
            int d = d0 + dj;
            int mk = (qmv > 0) && (dmk[b * DD + d] > 0);
            float v = base[(size_t)d * QQ];
            tile[tx][dj] = mk ? __expf(v - M) * inv : 0.f;
        }
        __syncthreads();
        float p0 = tile[qr][seg], p1 = tile[qr][seg + 1];
        float p2 = tile[qr][seg + 2], p3 = tile[qr][seg + 3];
        __nv_bfloat16 h0, l0, h1, l1, h2, l2, h3, l3;
        bsplit(p0, h0, l0); bsplit(p1, h1, l1);
        bsplit(p2, h2, l2); bsplit(p3, h3, l3);
        size_t o = drow + d0 + seg;
        *(__nv_bfloat162*)(g_P2th + o)     = __nv_bfloat162(h0, h1);
        *(__nv_bfloat162*)(g_P2th + o + 2) = __nv_bfloat162(h2, h3);
        *(__nv_bfloat162*)(g_P2tl + o)     = __nv_bfloat162(l0, l1);
        *(__nv_bfloat162*)(g_P2tl + o + 2) = __nv_bfloat162(l2, l3);
        __syncthreads();
    }
}

// ---------------- GEMM3: n-tile 64, 256 CTAs, 2 CTA/SM -----------------------
// stage bytes: Ah@0 10240 | Al@10240 | Bh@20480 4608 | Bl@25088 4608 = 29696; x2
__global__ __launch_bounds__(256, 2) void gemm3_mma(const float* __restrict__ Ud) {
    extern __shared__ __nv_bfloat16 dyn[];
    GEMM_IDS
    int b = blockIdx.y, n0 = blockIdx.x * 64;
    const __nv_bfloat16* Ahg = g_P2th + (size_t)b * QQ * DD;
    const __nv_bfloat16* Alg = g_P2tl + (size_t)b * QQ * DD;
    const float* Bg = Ud + (size_t)b * DD * HH + n0;
    float acc[4][2][4];
    ACC_INITN(acc, 4, 2)
    uint32_t sb = smem_u32(dyn);

    CPA16(sb +         srow  * 80 + kc * 2, Ahg + (size_t)srow  * DD + kc);
    CPA16(sb +         srow2 * 80 + kc * 2, Ahg + (size_t)srow2 * DD + kc);
    CPA16(sb + 10240 + srow  * 80 + kc * 2, Alg + (size_t)srow  * DD + kc);
    CPA16(sb + 10240 + srow2 * 80 + kc * 2, Alg + (size_t)srow2 * DD + kc);
    CPA_COMMIT();
    float4 pref[2];
    #pragma unroll
    for (int v = 0; v < 2; v++) {
        int idx = v * 256 + t;
        pref[v] = *(const float4*)(Bg + (size_t)(idx >> 4) * HH + (idx & 15) * 4);
    }

    for (int it = 0; it < DD / 32; it++) {
        CPA_WAIT0();
        // stage B from regs: [d][h] stride 72 elems
        __nv_bfloat16* Bs = dyn + (it & 1) * 14848 + 10240;
        #pragma unroll
        for (int v = 0; v < 2; v++) {
            int idx = v * 256 + t;
            int dr = idx >> 4, hc = (idx & 15) * 4;
            float4 x = pref[v];
            __nv_bfloat16 h0, l0, h1, l1, h2, l2, h3, l3;
            bsplit(x.x, h0, l0); bsplit(x.y, h1, l1);
            bsplit(x.z, h2, l2); bsplit(x.w, h3, l3);
            *(__nv_bfloat162*)(Bs + dr * 72 + hc)            = __nv_bfloat162(h0, h1);
            *(__nv_bfloat162*)(Bs + dr * 72 + hc + 2)        = __nv_bfloat162(h2, h3);
            *(__nv_bfloat162*)(Bs + 2304 + dr * 72 + hc)     = __nv_bfloat162(l0, l1);
            *(__nv_bfloat162*)(Bs + 2304 + dr * 72 + hc + 2) = __nv_bfloat162(l2, l3);
        }
        __syncthreads();
        if (it + 1 < DD / 32) {
            int k0 = (it + 1) * 32;
            uint32_t sbA = sb + ((it + 1) & 1) * 29696;
            CPA16(sbA +         srow  * 80 + kc * 2, Ahg + (size_t)srow  * DD + k0 + kc);
            CPA16(sbA +         srow2 * 80 + kc * 2, Ahg + (size_t)srow2 * DD + k0 + kc);
            CPA16(sbA + 10240 + srow  * 80 + kc * 2, Alg + (size_t)srow  * DD + k0 + kc);
            CPA16(sbA + 10240 + srow2 * 80 + kc * 2, Alg + (size_t)srow2 * DD + k0 + kc);
            CPA_COMMIT();
            #pragma unroll
            for (int v = 0; v < 2; v++) {
                int idx = v * 256 + t;
                pref[v] = *(const float4*)(Bg + (size_t)(k0 + (idx >> 4)) * HH + (idx & 15) * 4);
            }
        }
        const __nv_bfloat16* cA = dyn + (it & 1) * 14848;
        uint32_t bBh = sb + (it & 1) * 29696 + 20480;
        uint32_t bBl = bBh + 4608;
        #pragma unroll
        for (int kb = 0; kb < 32; kb += 16) {
            LOAD_AFR(cA, cA + 5120, 40, 4, wm * 64)
            uint32_t bh[4][2], bl[4][2];
            LOAD_BFR_T(bBh, bBl, 72, 1, wn * 16, bh, bl)
            MMA3P(acc, 4, 2, bh, bl)
        }
    }

    // epilogue: T[q][h] hi/lo
    #pragma unroll
    for (int i = 0; i < 4; i++) {
        int m = wm * 64 + i * 16 + gr;
        #pragma unroll
        for (int j = 0; j < 2; j++) {
            int n = n0 + wn * 16 + j * 8 + 2 * qp;
            #pragma unroll
            for (int rr = 0; rr < 2; rr++) {
                float a0 = acc[i][j][2 * rr], a1 = acc[i][j][2 * rr + 1];
                __nv_bfloat16 h0, l0, h1, l1;
                bsplit(a0, h0, l0); bsplit(a1, h1, l1);
                size_t o = ((size_t)b * QQ + m + rr * 8) * HH + n;
                *(__nv_bfloat162*)(g_Th + o) = __nv_bfloat162(h0, h1);
                *(__nv_bfloat162*)(g_Tl + o) = __nv_bfloat162(l0, l1);
            }
        }
    }
}

// ---------------- fused GEMM2+4: single-shot K=128 ---------------------------
#define ST24 136
#define TSZ  (128 * ST24)
__global__ __launch_bounds__(256) void gemm24f_mma(
    const float* __restrict__ Ud, float* __restrict__ out) {
    extern __shared__ __nv_bfloat16 dyn[];
    GEMM_IDS
    (void)srow; (void)srow2; (void)kc;
    int b = blockIdx.z, n0 = blockIdx.x * 128, m0 = blockIdx.y * 128;
    const __nv_bfloat16* srcs[6];
    int strides[6];
    srcs[0] = g_P1h  + (size_t)b * DD * QQ + (size_t)m0 * QQ; strides[0] = QQ;
    srcs[1] = g_P1l  + (size_t)b * DD * QQ + (size_t)m0 * QQ; strides[1] = QQ;
    srcs[2] = g_Uqph + (size_t)b * QQ * HH + n0;              strides[2] = HH;
    srcs[3] = g_Uqpl + (size_t)b * QQ * HH + n0;              strides[3] = HH;
    srcs[4] = g_Th   + (size_t)b * QQ * HH + n0;              strides[4] = HH;
    srcs[5] = g_Tl   + (size_t)b * QQ * HH + n0;              strides[5] = HH;

    uint32_t sb = smem_u32(dyn);
    #pragma unroll
    for (int v = 0; v < 8; v++) {
        int c = v * 256 + t;
        int row = c >> 4, kb8 = (c & 15) * 8;
        #pragma unroll
        for (int s = 0; s < 6; s++)
            CPA16(sb + s * (TSZ * 2) + row * (ST24 * 2) + kb8 * 2,
                  srcs[s] + (size_t)row * strides[s] + kb8);
    }
    CPA_COMMIT();
    CPA_WAIT0();
    __syncthreads();

    float acc2[4][4][4], acc4[4][4][4];
    ACC_INITN(acc2, 4, 4)
    ACC_INITN(acc4, 4, 4)
    const __nv_bfloat16* pA = dyn;
    uint32_t b2h = sb + 2 * (TSZ * 2), b2l = sb + 3 * (TSZ * 2);
    uint32_t b4h = sb + 4 * (TSZ * 2), b4l = sb + 5 * (TSZ * 2);
    #pragma unroll
    for (int s = 0; s < 8; s++) {
        int kb = s * 16;
        LOAD_AFR(pA, pA + TSZ, ST24, 4, wm * 64)
        {
            uint32_t bh[4][2], bl[4][2];
            LOAD_BFR_T(b2h, b2l, ST24, 2, wn * 32, bh, bl)
            MMA3P(acc2, 4, 4, bh, bl)
        }
        {
            uint32_t bh[4][2], bl[4][2];
            LOAD_BFR_T(b4h, b4l, ST24, 2, wn * 32, bh, bl)
            MMA3P(acc4, 4, 4, bh, bl)
        }
    }

    #pragma unroll
    for (int i = 0; i < 4; i++) {
        int m = m0 + wm * 64 + i * 16 + gr;
        #pragma unroll
        for (int j = 0; j < 4; j++) {
            int n = n0 + wn * 32 + j * 8 + 2 * qp;
            #pragma unroll
            for (int rr = 0; rr < 2; rr++) {
                int mm = m + rr * 8;
                float a2x = acc2[i][j][2 * rr], a2y = acc2[i][j][2 * rr + 1];
                float a4x = acc4[i][j][2 * rr], a4y = acc4[i][j][2 * rr + 1];
                float2 u = *(const float2*)(Ud + ((size_t)b * DD + mm) * HH + n);
                float* ob = out + ((size_t)b * DD + mm) * (size_t)(4 * HH) + n;
                *(float2*)(ob)          = u;
                *(float2*)(ob + HH)     = make_float2(a2x, a2y);
                *(float2*)(ob + 2 * HH) = make_float2(u.x * a2x, u.y * a2y);
                *(float2*)(ob + 3 * HH) = make_float2(u.x * a4x, u.y * a4y);
            }
        }
    }
}

// ---------------------------------------------------------------------------
extern "C" void kernel_launch(void* const* d_in, const int* in_sizes, int n_in,
                              void* d_out, int out_size) {
    const float* Ud  = (const float*)d_in[0];
    const float* Uq  = (const float*)d_in[1];
    const float* wcw = (const float*)d_in[2];
    const float* wcb = (const float*)d_in[3];
    const int*   qm  = (const int*)d_in[4];
    const int*   dmk = (const int*)d_in[5];
    float* out = (float*)d_out;

    cudaFuncSetAttribute(gemm1_mma,   cudaFuncAttributeMaxDynamicSharedMemorySize, 61440);
    cudaFuncSetAttribute(gemm3_mma,   cudaFuncAttributeMaxDynamicSharedMemorySize, 59392);
    cudaFuncSetAttribute(gemm24f_mma, cudaFuncAttributeMaxDynamicSharedMemorySize, 208896);

    // Uq splits (+ s_q)
    conv_uq_kernel<<<BB * QQ, 256>>>(Uq, wcw);

    // logits + row softmax + column partials + s_d  (256 CTAs, 2/SM)
    gemm1_mma<<<dim3(DD / 64, BB), 256, 61440>>>(Ud, wcw, wcb, qm, dmk);

    // single-pass column softmax -> P2t
    softmax_q2d_kernel<<<dim3(QQ / 32, BB), dim3(32, 8)>>>(qm, dmk);

    // T = P2^T @ Ud  (256 CTAs, 2/SM)
    gemm3_mma<<<dim3(HH / 64, BB), 256, 59392>>>(Ud);

    // fused A_d2q + A_q2d, all 4 output slices
    gemm24f_mma<<<dim3(HH / 128, DD / 128, BB), 256, 208896>>>(Ud, out);
}

// round 11
// speedup vs baseline: 1.0407x; 1.0407x over previous
#include <cuda_runtime.h>
#include <cuda_bf16.h>
#include <cstdint>

#define BB 16
#define DD 1024
#define QQ 128
#define HH 1024

// ---------------- scratch (device globals) ----------------------------------
__device__ float g_S [BB * DD * QQ];
__device__ float g_sq[BB * QQ];
__device__ float g_cmax[BB * 8 * 128];
__device__ float g_csum[BB * 8 * 128];
__device__ __nv_bfloat16 g_Uqwh[BB * QQ * HH], g_Uqwl[BB * QQ * HH];  // Uq*wdot [b,q,h]
__device__ __nv_bfloat16 g_Uqph[BB * QQ * HH], g_Uqpl[BB * QQ * HH];  // Uq plain [b,q,h]
__device__ __nv_bfloat16 g_P1h [BB * DD * QQ], g_P1l [BB * DD * QQ];  // S_d2q [b,d,q]
__device__ __nv_bfloat16 g_P2th[BB * QQ * DD], g_P2tl[BB * QQ * DD];  // S_q2d^T [b,q,d]
__device__ __nv_bfloat16 g_Th  [BB * QQ * HH], g_Tl  [BB * QQ * HH];  // T [b,q,h]

// ---------------- helpers ----------------------------------------------------
__device__ __forceinline__ uint32_t smem_u32(const void* p) {
    uint32_t a;
    asm("{ .reg .u64 t; cvta.to.shared.u64 t, %1; cvt.u32.u64 %0, t; }" : "=r"(a) : "l"(p));
    return a;
}
__device__ __forceinline__ uint32_t L32(const __nv_bfloat16* p) {
    return *(const uint32_t*)p;
}
__device__ __forceinline__ void mma_bf16(float* c, const uint32_t* a, const uint32_t* b) {
    asm volatile(
        "mma.sync.aligned.m16n8k16.row.col.f32.bf16.bf16.f32 "
        "{%0,%1,%2,%3}, {%4,%5,%6,%7}, {%8,%9}, {%0,%1,%2,%3};"
        : "+f"(c[0]), "+f"(c[1]), "+f"(c[2]), "+f"(c[3])
        : "r"(a[0]), "r"(a[1]), "r"(a[2]), "r"(a[3]), "r"(b[0]), "r"(b[1]));
}
__device__ __forceinline__ void ldmx4t(uint32_t& r0, uint32_t& r1,
                                       uint32_t& r2, uint32_t& r3, uint32_t a) {
    asm volatile("ldmatrix.sync.aligned.m8n8.x4.trans.shared.b16 {%0,%1,%2,%3}, [%4];"
        : "=r"(r0), "=r"(r1), "=r"(r2), "=r"(r3) : "r"(a));
}
__device__ __forceinline__ void bsplit(float x, __nv_bfloat16& h, __nv_bfloat16& l) {
    h = __float2bfloat16(x);
    l = __float2bfloat16(x - __bfloat162float(h));
}
#define CPA16(sa, g) \
    asm volatile("cp.async.cg.shared.global [%0], [%1], 16;" :: "r"(sa), "l"(g))
#define CPA_COMMIT() asm volatile("cp.async.commit_group;" ::: "memory")
#define CPA_WAIT0()  asm volatile("cp.async.wait_group 0;" ::: "memory")

// A fragments: MI m16-tiles from warp m-base MB, K-contig layout stride ST
#define LOAD_AFR(sAh, sAl, ST, MI, MB)                                        \
    uint32_t ah[MI][4], al[MI][4];                                            \
    _Pragma("unroll")                                                         \
    for (int i = 0; i < (MI); i++) {                                          \
        int r = (MB) + i * 16 + gr;                                           \
        const __nv_bfloat16* p = (sAh) + r * (ST) + kb + 2 * qp;              \
        const __nv_bfloat16* q = (sAl) + r * (ST) + kb + 2 * qp;              \
        ah[i][0] = L32(p);            ah[i][1] = L32(p + 8 * (ST));           \
        ah[i][2] = L32(p + 8);        ah[i][3] = L32(p + 8 * (ST) + 8);       \
        al[i][0] = L32(q);            al[i][1] = L32(q + 8 * (ST));           \
        al[i][2] = L32(q + 8);        al[i][3] = L32(q + 8 * (ST) + 8);       \
    }

#define MMA3P(ACC, MI, NJ, BH, BL)                                            \
    _Pragma("unroll")                                                         \
    for (int i = 0; i < (MI); i++)                                            \
        _Pragma("unroll")                                                     \
        for (int j = 0; j < (NJ); j++) mma_bf16((ACC)[i][j], ah[i], (BH)[j]); \
    _Pragma("unroll")                                                         \
    for (int i = 0; i < (MI); i++)                                            \
        _Pragma("unroll")                                                     \
        for (int j = 0; j < (NJ); j++) mma_bf16((ACC)[i][j], ah[i], (BL)[j]); \
    _Pragma("unroll")                                                         \
    for (int i = 0; i < (MI); i++)                                            \
        _Pragma("unroll")                                                     \
        for (int j = 0; j < (NJ); j++) mma_bf16((ACC)[i][j], al[i], (BH)[j]);

#define LOAD_BFR_K(sBh, sBl, ST, NJ, NB, BH, BL)                              \
    _Pragma("unroll")                                                         \
    for (int j = 0; j < (NJ); j++) {                                          \
        int c = (NB) + j * 8 + gr;                                            \
        const __nv_bfloat16* p = (sBh) + c * (ST) + kb + 2 * qp;              \
        const __nv_bfloat16* q = (sBl) + c * (ST) + kb + 2 * qp;              \
        BH[j][0] = L32(p); BH[j][1] = L32(p + 8);                             \
        BL[j][0] = L32(q); BL[j][1] = L32(q + 8);                             \
    }

#define LOAD_BFR_T(bBh, bBl, STB, NJ2, NB, BH, BL)                            \
    _Pragma("unroll")                                                         \
    for (int jj = 0; jj < (NJ2); jj++) {                                      \
        int c0 = (NB) + jj * 16;                                              \
        uint32_t off = (uint32_t)(((kb + (lane & 15)) * (STB) + c0 +          \
                                   ((lane >> 4) * 8)) * 2);                   \
        ldmx4t(BH[2*jj][0], BH[2*jj][1], BH[2*jj+1][0], BH[2*jj+1][1], (bBh) + off); \
        ldmx4t(BL[2*jj][0], BL[2*jj][1], BL[2*jj+1][0], BL[2*jj+1][1], (bBl) + off); \
    }

// 512-thread ids: 16 warps in 4x4 grid, warp tile 32x32
#define GEMM_IDS5                                                             \
    int t = threadIdx.x;                                                      \
    int wid = t >> 5, lane = t & 31;                                          \
    int wm = wid >> 2, wn = wid & 3;                                          \
    int gr = lane >> 2, qp = lane & 3;                                        \
    int srow = t >> 2, kc = (t & 3) * 8;

#define ACC_INITN(A, MI, NJ)                                                  \
    _Pragma("unroll")                                                         \
    for (int i = 0; i < (MI); i++)                                            \
        _Pragma("unroll")                                                     \
        for (int j = 0; j < (NJ); j++)                                        \
            _Pragma("unroll")                                                 \
            for (int e = 0; e < 4; e++) (A)[i][j][e] = 0.f;

// ---------------- conv_uq ----------------------------------------------------
__global__ void conv_uq_kernel(const float* __restrict__ Uq,
                               const float* __restrict__ wcw) {
    __shared__ float red[8];
    int row = blockIdx.x;
    int t = threadIdx.x;
    const float* src = Uq + (size_t)row * HH;
    float4 v = *(const float4*)(src + t * 4);
    float4 wd = *(const float4*)(wcw + 2 * HH + t * 4);
    float4 wq = *(const float4*)(wcw + HH + t * 4);
    __nv_bfloat16 h0, l0, h1, l1, h2, l2, h3, l3;
    bsplit(v.x, h0, l0); bsplit(v.y, h1, l1);
    bsplit(v.z, h2, l2); bsplit(v.w, h3, l3);
    size_t o = (size_t)row * HH + t * 4;
    *(__nv_bfloat162*)(g_Uqph + o)     = __nv_bfloat162(h0, h1);
    *(__nv_bfloat162*)(g_Uqph + o + 2) = __nv_bfloat162(h2, h3);
    *(__nv_bfloat162*)(g_Uqpl + o)     = __nv_bfloat162(l0, l1);
    *(__nv_bfloat162*)(g_Uqpl + o + 2) = __nv_bfloat162(l2, l3);
    float4 s = make_float4(v.x * wd.x, v.y * wd.y, v.z * wd.z, v.w * wd.w);
    bsplit(s.x, h0, l0); bsplit(s.y, h1, l1);
    bsplit(s.z, h2, l2); bsplit(s.w, h3, l3);
    *(__nv_bfloat162*)(g_Uqwh + o)     = __nv_bfloat162(h0, h1);
    *(__nv_bfloat162*)(g_Uqwh + o + 2) = __nv_bfloat162(h2, h3);
    *(__nv_bfloat162*)(g_Uqwl + o)     = __nv_bfloat162(l0, l1);
    *(__nv_bfloat162*)(g_Uqwl + o + 2) = __nv_bfloat162(l2, l3);
    float p = v.x * wq.x + v.y * wq.y + v.z * wq.z + v.w * wq.w;
    #pragma unroll
    for (int off = 16; off; off >>= 1) p += __shfl_xor_sync(0xffffffffu, p, off);
    if ((t & 31) == 0) red[t >> 5] = p;
    __syncthreads();
    if (t == 0) {
        float sum = 0.f;
        #pragma unroll
        for (int j = 0; j < 8; j++) sum += red[j];
        g_sq[row] = sum;
    }
}

// ---------------- GEMM1 fused (512 thr, 128x128 tile) ------------------------
// dyn layout (elements): A stages at (it&1)*10240 [hi 0|lo 5120];
// B at 20480 + (it&1)*10240 [hi 0|lo 5120]. total 40960 elems = 81920 B.
__global__ __launch_bounds__(512) void gemm1_mma(
    const float* __restrict__ Ud, const float* __restrict__ wcw,
    const float* __restrict__ wcb,
    const int* __restrict__ qm, const int* __restrict__ dmk) {
    extern __shared__ __nv_bfloat16 dyn[];
    __shared__ float redM[128][4], redS[128][4];
    __shared__ float2 colp[4][128];
    __shared__ int s_qm[128];
    __shared__ float s_sdv[128];
    __shared__ float s_wd[HH];
    GEMM_IDS5
    int b = blockIdx.y, m0 = blockIdx.x * 128;
    const float* A = Ud + (size_t)b * DD * HH + (size_t)m0 * HH;
    const __nv_bfloat16* Bh = g_Uqwh + (size_t)b * QQ * HH;
    const __nv_bfloat16* Bl = g_Uqwl + (size_t)b * QQ * HH;
    float acc[2][4][4];
    ACC_INITN(acc, 2, 4)
    float sdp[2] = {0.f, 0.f};
    if (t < 128) s_qm[t] = qm[b * QQ + t];
    #pragma unroll
    for (int i = t; i < HH; i += 512) s_wd[i] = wcw[i];
    uint32_t sbB0 = smem_u32(dyn) + 40960;

    float4 pref[2];
    #pragma unroll
    for (int v = 0; v < 2; v++) {
        int idx = v * 512 + t;
        pref[v] = *(const float4*)(A + (size_t)(idx >> 3) * HH + (idx & 7) * 4);
    }
    CPA16(sbB0 +         srow * 80 + kc * 2, Bh + (size_t)srow * HH + kc);
    CPA16(sbB0 + 10240 + srow * 80 + kc * 2, Bl + (size_t)srow * HH + kc);
    CPA_COMMIT();
    __syncthreads();   // s_wd ready

    for (int it = 0; it < HH / 32; it++) {
        CPA_WAIT0();
        __nv_bfloat16* As = dyn + (it & 1) * 10240;
        #pragma unroll
        for (int v = 0; v < 2; v++) {
            int idx = v * 512 + t;
            int row = idx >> 3, cs = (idx & 7) * 4;
            float4 x = pref[v];
            float4 w = *(const float4*)(s_wd + it * 32 + cs);
            sdp[v] += x.x * w.x + x.y * w.y + x.z * w.z + x.w * w.w;
            __nv_bfloat16 h0, l0, h1, l1, h2, l2, h3, l3;
            bsplit(x.x, h0, l0); bsplit(x.y, h1, l1);
            bsplit(x.z, h2, l2); bsplit(x.w, h3, l3);
            *(__nv_bfloat162*)(As + row * 40 + cs)            = __nv_bfloat162(h0, h1);
            *(__nv_bfloat162*)(As + row * 40 + cs + 2)        = __nv_bfloat162(h2, h3);
            *(__nv_bfloat162*)(As + 5120 + row * 40 + cs)     = __nv_bfloat162(l0, l1);
            *(__nv_bfloat162*)(As + 5120 + row * 40 + cs + 2) = __nv_bfloat162(l2, l3);
        }
        __syncthreads();
        if (it + 1 < HH / 32) {
            int k0 = (it + 1) * 32;
            uint32_t sbB = sbB0 + ((it + 1) & 1) * 20480;
            CPA16(sbB +         srow * 80 + kc * 2, Bh + (size_t)srow * HH + k0 + kc);
            CPA16(sbB + 10240 + srow * 80 + kc * 2, Bl + (size_t)srow * HH + k0 + kc);
            CPA_COMMIT();
            #pragma unroll
            for (int v = 0; v < 2; v++) {
                int idx = v * 512 + t;
                pref[v] = *(const float4*)(A + (size_t)(idx >> 3) * HH + k0 + (idx & 7) * 4);
            }
        }
        const __nv_bfloat16* cA = dyn + (it & 1) * 10240;
        const __nv_bfloat16* cB = dyn + 20480 + (it & 1) * 10240;
        #pragma unroll
        for (int kb = 0; kb < 32; kb += 16) {
            LOAD_AFR(cA, cA + 5120, 40, 2, wm * 32)
            uint32_t bh[4][2], bl[4][2];
            LOAD_BFR_K(cB, cB + 5120, 40, 4, wn * 32, bh, bl)
            MMA3P(acc, 2, 4, bh, bl)
        }
    }

    // s_d reduce: thread covers rows v*64 + (t>>3); 8 threads/row
    #pragma unroll
    for (int v = 0; v < 2; v++) {
        float s = sdp[v];
        s += __shfl_xor_sync(0xffffffffu, s, 1);
        s += __shfl_xor_sync(0xffffffffu, s, 2);
        s += __shfl_xor_sync(0xffffffffu, s, 4);
        if ((t & 7) == 0) s_sdv[v * 64 + (t >> 3)] = s;
    }

    float bias = wcb[0];
    int dmv[2][2];
    #pragma unroll
    for (int i = 0; i < 2; i++)
        #pragma unroll
        for (int rr = 0; rr < 2; rr++)
            dmv[i][rr] = dmk[b * DD + m0 + wm * 32 + i * 16 + rr * 8 + gr];
    __syncthreads();
    float sdv[2][2];
    #pragma unroll
    for (int i = 0; i < 2; i++)
        #pragma unroll
        for (int rr = 0; rr < 2; rr++)
            sdv[i][rr] = s_sdv[wm * 32 + i * 16 + rr * 8 + gr] + bias;

    #pragma unroll
    for (int i = 0; i < 2; i++)
        #pragma unroll
        for (int j = 0; j < 4; j++) {
            int n = wn * 32 + j * 8 + 2 * qp;
            float sq0 = g_sq[b * QQ + n], sq1 = g_sq[b * QQ + n + 1];
            int q0 = s_qm[n] > 0, q1 = s_qm[n + 1] > 0;
            #pragma unroll
            for (int rr = 0; rr < 2; rr++) {
                int m = m0 + wm * 32 + i * 16 + rr * 8 + gr;
                float s0 = acc[i][j][2 * rr]     + sdv[i][rr] + sq0;
                float s1 = acc[i][j][2 * rr + 1] + sdv[i][rr] + sq1;
                *(float2*)(g_S + ((size_t)b * DD + m) * QQ + n) = make_float2(s0, s1);
                int dm = dmv[i][rr] > 0;
                acc[i][j][2 * rr]     = (dm && q0) ? s0 : -1e30f;
                acc[i][j][2 * rr + 1] = (dm && q1) ? s1 : -1e30f;
            }
        }

    // row softmax max
    float M[2][2];
    #pragma unroll
    for (int i = 0; i < 2; i++)
        #pragma unroll
        for (int rr = 0; rr < 2; rr++) {
            float mx = -1e30f;
            #pragma unroll
            for (int j = 0; j < 4; j++)
                mx = fmaxf(mx, fmaxf(acc[i][j][2 * rr], acc[i][j][2 * rr + 1]));
            mx = fmaxf(mx, __shfl_xor_sync(0xffffffffu, mx, 1));
            mx = fmaxf(mx, __shfl_xor_sync(0xffffffffu, mx, 2));
            if (qp == 0) redM[wm * 32 + i * 16 + rr * 8 + gr][wn] = mx;
        }
    __syncthreads();
    #pragma unroll
    for (int i = 0; i < 2; i++)
        #pragma unroll
        for (int rr = 0; rr < 2; rr++) {
            int r = wm * 32 + i * 16 + rr * 8 + gr;
            M[i][rr] = fmaxf(fmaxf(redM[r][0], redM[r][1]),
                             fmaxf(redM[r][2], redM[r][3]));
        }
    // row softmax sum
    float inv[2][2];
    #pragma unroll
    for (int i = 0; i < 2; i++)
        #pragma unroll
        for (int rr = 0; rr < 2; rr++) {
            float s = 0.f;
            #pragma unroll
            for (int j = 0; j < 4; j++) {
                s += __expf(acc[i][j][2 * rr]     - M[i][rr]);
                s += __expf(acc[i][j][2 * rr + 1] - M[i][rr]);
            }
            s += __shfl_xor_sync(0xffffffffu, s, 1);
            s += __shfl_xor_sync(0xffffffffu, s, 2);
            if (qp == 0) redS[wm * 32 + i * 16 + rr * 8 + gr][wn] = s;
        }
    __syncthreads();
    #pragma unroll
    for (int i = 0; i < 2; i++)
        #pragma unroll
        for (int rr = 0; rr < 2; rr++) {
            int r = wm * 32 + i * 16 + rr * 8 + gr;
            inv[i][rr] = 1.f / (redS[r][0] + redS[r][1] + redS[r][2] + redS[r][3]);
        }
    // P1 write
    #pragma unroll
    for (int i = 0; i < 2; i++)
        #pragma unroll
        for (int j = 0; j < 4; j++) {
            int n = wn * 32 + j * 8 + 2 * qp;
            int q0 = s_qm[n] > 0, q1 = s_qm[n + 1] > 0;
            #pragma unroll
            for (int rr = 0; rr < 2; rr++) {
                int m = m0 + wm * 32 + i * 16 + rr * 8 + gr;
                int dm = dmv[i][rr] > 0;
                float p0 = (dm && q0) ? __expf(acc[i][j][2 * rr]     - M[i][rr]) * inv[i][rr] : 0.f;
                float p1 = (dm && q1) ? __expf(acc[i][j][2 * rr + 1] - M[i][rr]) * inv[i][rr] : 0.f;
                __nv_bfloat16 h0, l0, h1, l1;
                bsplit(p0, h0, l0); bsplit(p1, h1, l1);
                size_t o = ((size_t)b * DD + m) * QQ + n;
                *(__nv_bfloat162*)(g_P1h + o) = __nv_bfloat162(h0, h1);
                *(__nv_bfloat162*)(g_P1l + o) = __nv_bfloat162(l0, l1);
            }
        }
    // column partials
    #pragma unroll
    for (int j = 0; j < 4; j++)
        #pragma unroll
        for (int cc = 0; cc < 2; cc++) {
            float cm = -1e30f;
            #pragma unroll
            for (int i = 0; i < 2; i++)
                #pragma unroll
                for (int rr = 0; rr < 2; rr++)
                    cm = fmaxf(cm, acc[i][j][2 * rr + cc]);
            float cs = 0.f;
            #pragma unroll
            for (int i = 0; i < 2; i++)
                #pragma unroll
                for (int rr = 0; rr < 2; rr++)
                    cs += __expf(acc[i][j][2 * rr + cc] - cm);
            #pragma unroll
            for (int o = 4; o <= 16; o <<= 1) {
                float om = __shfl_xor_sync(0xffffffffu, cm, o);
                float os = __shfl_xor_sync(0xffffffffu, cs, o);
                float nm = fmaxf(cm, om);
                cs = cs * __expf(cm - nm) + os * __expf(om - nm);
                cm = nm;
            }
            if (gr == 0) colp[wm][wn * 32 + j * 8 + 2 * qp + cc] = make_float2(cm, cs);
        }
    __syncthreads();
    if (t < 128) {
        float m = -1e30f, s = 0.f;
        #pragma unroll
        for (int k = 0; k < 4; k++) {
            float2 a = colp[k][t];
            float nm = fmaxf(m, a.x);
            s = s * __expf(m - nm) + a.y * __expf(a.x - nm);
            m = nm;
        }
        int idx = (b * 8 + blockIdx.x) * 128 + t;
        g_cmax[idx] = m; g_csum[idx] = s;
    }
}

// ---------------- single-pass q2d softmax -> P2t hi/lo -----------------------
__global__ void softmax_q2d_kernel(const int* __restrict__ qm,
                                   const int* __restrict__ dmk) {
    __shared__ float sM[32], sI[32];
    __shared__ float tile[32][33];
    int b = blockIdx.y;
    int tx = threadIdx.x, ty = threadIdx.y;
    int q = blockIdx.x * 32 + tx;
    int qmv = qm[b * QQ + q];
    int tid = ty * 32 + tx;
    if (tid < 32) {
        int qq = blockIdx.x * 32 + tid;
        float m = -1e30f, s = 0.f;
        #pragma unroll
        for (int k = 0; k < 8; k++) {
            float mk = g_cmax[(b * 8 + k) * 128 + qq];
            float sk = g_csum[(b * 8 + k) * 128 + qq];
            float nm = fmaxf(m, mk);
            s = s * __expf(m - nm) + sk * __expf(mk - nm);
            m = nm;
        }
        sM[tid] = m; sI[tid] = 1.f / s;
    }
    __syncthreads();
    float M = sM[tx], inv = sI[tx];
    const float* base = g_S + (size_t)b * DD * QQ + q;
    int qr = tid >> 3, seg = (tid & 7) * 4;
    size_t drow = (size_t)b * QQ * DD + (size_t)(blockIdx.x * 32 + qr) * DD;
    for (int d0 = 0; d0 < DD; d0 += 32) {
        #pragma unroll
        for (int dj = ty; dj < 32; dj += 8) {
            int d = d0 + dj;
            int mk = (qmv > 0) && (dmk[b * DD + d] > 0);
            float v = base[(size_t)d * QQ];
            tile[tx][dj] = mk ? __expf(v - M) * inv : 0.f;
        }
        __syncthreads();
        float p0 = tile[qr][seg], p1 = tile[qr][seg + 1];
        float p2 = tile[qr][seg + 2], p3 = tile[qr][seg + 3];
        __nv_bfloat16 h0, l0, h1, l1, h2, l2, h3, l3;
        bsplit(p0, h0, l0); bsplit(p1, h1, l1);
        bsplit(p2, h2, l2); bsplit(p3, h3, l3);
        size_t o = drow + d0 + seg;
        *(__nv_bfloat162*)(g_P2th + o)     = __nv_bfloat162(h0, h1);
        *(__nv_bfloat162*)(g_P2th + o + 2) = __nv_bfloat162(h2, h3);
        *(__nv_bfloat162*)(g_P2tl + o)     = __nv_bfloat162(l0, l1);
        *(__nv_bfloat162*)(g_P2tl + o + 2) = __nv_bfloat162(l2, l3);
        __syncthreads();
    }
}

// ---------------- GEMM3 (512 thr, 128x128 tile): T = P2^T @ Ud ---------------
// stage (elems): A hi 0 | A lo 5120 | Bh 10240 (stride 136) | Bl 10240+2176*2
// stage elems = 18944, x2. bytes per stage 37888.
__global__ __launch_bounds__(512) void gemm3_mma(const float* __restrict__ Ud) {
    extern __shared__ __nv_bfloat16 dyn[];
    GEMM_IDS5
    int b = blockIdx.y, n0 = blockIdx.x * 128;
    const __nv_bfloat16* Ahg = g_P2th + (size_t)b * QQ * DD;
    const __nv_bfloat16* Alg = g_P2tl + (size_t)b * QQ * DD;
    const float* Bg = Ud + (size_t)b * DD * HH + n0;
    float acc[2][4][4];
    ACC_INITN(acc, 2, 4)
    uint32_t sb = smem_u32(dyn);

    CPA16(sb +         srow * 80 + kc * 2, Ahg + (size_t)srow * DD + kc);
    CPA16(sb + 10240 + srow * 80 + kc * 2, Alg + (size_t)srow * DD + kc);
    CPA_COMMIT();
    float4 pref[2];
    #pragma unroll
    for (int v = 0; v < 2; v++) {
        int idx = v * 512 + t;
        pref[v] = *(const float4*)(Bg + (size_t)(idx >> 5) * HH + (idx & 31) * 4);
    }

    for (int it = 0; it < DD / 32; it++) {
        CPA_WAIT0();
        __nv_bfloat16* Bs = dyn + (it & 1) * 18944 + 10240;
        #pragma unroll
        for (int v = 0; v < 2; v++) {
            int idx = v * 512 + t;
            int dr = idx >> 5, hc = (idx & 31) * 4;
            float4 x = pref[v];
            __nv_bfloat16 h0, l0, h1, l1, h2, l2, h3, l3;
            bsplit(x.x, h0, l0); bsplit(x.y, h1, l1);
            bsplit(x.z, h2, l2); bsplit(x.w, h3, l3);
            *(__nv_bfloat162*)(Bs + dr * 136 + hc)            = __nv_bfloat162(h0, h1);
            *(__nv_bfloat162*)(Bs + dr * 136 + hc + 2)        = __nv_bfloat162(h2, h3);
            *(__nv_bfloat162*)(Bs + 4352 + dr * 136 + hc)     = __nv_bfloat162(l0, l1);
            *(__nv_bfloat162*)(Bs + 4352 + dr * 136 + hc + 2) = __nv_bfloat162(l2, l3);
        }
        __syncthreads();
        if (it + 1 < DD / 32) {
            int k0 = (it + 1) * 32;
            uint32_t sbA = sb + ((it + 1) & 1) * 37888;
            CPA16(sbA +         srow * 80 + kc * 2, Ahg + (size_t)srow * DD + k0 + kc);
            CPA16(sbA + 10240 + srow * 80 + kc * 2, Alg + (size_t)srow * DD + k0 + kc);
            CPA_COMMIT();
            #pragma unroll
            for (int v = 0; v < 2; v++) {
                int idx = v * 512 + t;
                pref[v] = *(const float4*)(Bg + (size_t)(k0 + (idx >> 5)) * HH + (idx & 31) * 4);
            }
        }
        const __nv_bfloat16* cA = dyn + (it & 1) * 18944;
        uint32_t bBh = sb + (it & 1) * 37888 + 20480;
        uint32_t bBl = bBh + 8704;
        #pragma unroll
        for (int kb = 0; kb < 32; kb += 16) {
            LOAD_AFR(cA, cA + 5120, 40, 2, wm * 32)
            uint32_t bh[4][2], bl[4][2];
            LOAD_BFR_T(bBh, bBl, 136, 2, wn * 32, bh, bl)
            MMA3P(acc, 2, 4, bh, bl)
        }
    }

    #pragma unroll
    for (int i = 0; i < 2; i++) {
        int m = wm * 32 + i * 16 + gr;
        #pragma unroll
        for (int j = 0; j < 4; j++) {
            int n = n0 + wn * 32 + j * 8 + 2 * qp;
            #pragma unroll
            for (int rr = 0; rr < 2; rr++) {
                float a0 = acc[i][j][2 * rr], a1 = acc[i][j][2 * rr + 1];
                __nv_bfloat16 h0, l0, h1, l1;
                bsplit(a0, h0, l0); bsplit(a1, h1, l1);
                size_t o = ((size_t)b * QQ + m + rr * 8) * HH + n;
                *(__nv_bfloat162*)(g_Th + o) = __nv_bfloat162(h0, h1);
                *(__nv_bfloat162*)(g_Tl + o) = __nv_bfloat162(l0, l1);
            }
        }
    }
}

// ---------------- fused GEMM2+4 (512 thr, single-shot K=128) -----------------
#define ST24 136
#define TSZ  (128 * ST24)
__global__ __launch_bounds__(512) void gemm24f_mma(
    const float* __restrict__ Ud, float* __restrict__ out) {
    extern __shared__ __nv_bfloat16 dyn[];
    GEMM_IDS5
    (void)srow; (void)kc;
    int b = blockIdx.z, n0 = blockIdx.x * 128, m0 = blockIdx.y * 128;
    const __nv_bfloat16* srcs[6];
    int strides[6];
    srcs[0] = g_P1h  + (size_t)b * DD * QQ + (size_t)m0 * QQ; strides[0] = QQ;
    srcs[1] = g_P1l  + (size_t)b * DD * QQ + (size_t)m0 * QQ; strides[1] = QQ;
    srcs[2] = g_Uqph + (size_t)b * QQ * HH + n0;              strides[2] = HH;
    srcs[3] = g_Uqpl + (size_t)b * QQ * HH + n0;              strides[3] = HH;
    srcs[4] = g_Th   + (size_t)b * QQ * HH + n0;              strides[4] = HH;
    srcs[5] = g_Tl   + (size_t)b * QQ * HH + n0;              strides[5] = HH;

    uint32_t sb = smem_u32(dyn);
    #pragma unroll
    for (int v = 0; v < 4; v++) {
        int c = v * 512 + t;
        int row = c >> 4, kb8 = (c & 15) * 8;
        #pragma unroll
        for (int s = 0; s < 6; s++)
            CPA16(sb + s * (TSZ * 2) + row * (ST24 * 2) + kb8 * 2,
                  srcs[s] + (size_t)row * strides[s] + kb8);
    }
    CPA_COMMIT();
    CPA_WAIT0();
    __syncthreads();

    float acc2[2][4][4], acc4[2][4][4];
    ACC_INITN(acc2, 2, 4)
    ACC_INITN(acc4, 2, 4)
    const __nv_bfloat16* pA = dyn;
    uint32_t b2h = sb + 2 * (TSZ * 2), b2l = sb + 3 * (TSZ * 2);
    uint32_t b4h = sb + 4 * (TSZ * 2), b4l = sb + 5 * (TSZ * 2);
    #pragma unroll
    for (int s = 0; s < 8; s++) {
        int kb = s * 16;
        LOAD_AFR(pA, pA + TSZ, ST24, 2, wm * 32)
        {
            uint32_t bh[4][2], bl[4][2];
            LOAD_BFR_T(b2h, b2l, ST24, 2, wn * 32, bh, bl)
            MMA3P(acc2, 2, 4, bh, bl)
        }
        {
            uint32_t bh[4][2], bl[4][2];
            LOAD_BFR_T(b4h, b4l, ST24, 2, wn * 32, bh, bl)
            MMA3P(acc4, 2, 4, bh, bl)
        }
    }

    #pragma unroll
    for (int i = 0; i < 2; i++) {
        int m = m0 + wm * 32 + i * 16 + gr;
        #pragma unroll
        for (int j = 0; j < 4; j++) {
            int n = n0 + wn * 32 + j * 8 + 2 * qp;
            #pragma unroll
            for (int rr = 0; rr < 2; rr++) {
                int mm = m + rr * 8;
                float a2x = acc2[i][j][2 * rr], a2y = acc2[i][j][2 * rr + 1];
                float a4x = acc4[i][j][2 * rr], a4y = acc4[i][j][2 * rr + 1];
                float2 u = *(const float2*)(Ud + ((size_t)b * DD + mm) * HH + n);
                float* ob = out + ((size_t)b * DD + mm) * (size_t)(4 * HH) + n;
                *(float2*)(ob)          = u;
                *(float2*)(ob + HH)     = make_float2(a2x, a2y);
                *(float2*)(ob + 2 * HH) = make_float2(u.x * a2x, u.y * a2y);
                *(float2*)(ob + 3 * HH) = make_float2(u.x * a4x, u.y * a4y);
            }
        }
    }
}

// ---------------------------------------------------------------------------
extern "C" void kernel_launch(void* const* d_in, const int* in_sizes, int n_in,
                              void* d_out, int out_size) {
    const float* Ud  = (const float*)d_in[0];
    const float* Uq  = (const float*)d_in[1];
    const float* wcw = (const float*)d_in[2];
    const float* wcb = (const float*)d_in[3];
    const int*   qm  = (const int*)d_in[4];
    const int*   dmk = (const int*)d_in[5];
    float* out = (float*)d_out;

    cudaFuncSetAttribute(gemm1_mma,   cudaFuncAttributeMaxDynamicSharedMemorySize, 81920);
    cudaFuncSetAttribute(gemm3_mma,   cudaFuncAttributeMaxDynamicSharedMemorySize, 75776);
    cudaFuncSetAttribute(gemm24f_mma, cudaFuncAttributeMaxDynamicSharedMemorySize, 208896);

    conv_uq_kernel<<<BB * QQ, 256>>>(Uq, wcw);

    gemm1_mma<<<dim3(DD / 128, BB), 512, 81920>>>(Ud, wcw, wcb, qm, dmk);

    softmax_q2d_kernel<<<dim3(QQ / 32, BB), dim3(32, 8)>>>(qm, dmk);

    gemm3_mma<<<dim3(HH / 128, BB), 512, 75776>>>(Ud);

    gemm24f_mma<<<dim3(HH / 128, DD / 128, BB), 512, 208896>>>(Ud, out);
}

// round 13
// speedup vs baseline: 1.0442x; 1.0034x over previous
#include <cuda_runtime.h>
#include <cuda_bf16.h>
#include <cstdint>

#define BB 16
#define DD 1024
#define QQ 128
#define HH 1024

// ---------------- scratch (device globals) ----------------------------------
__device__ float g_S [BB * DD * QQ];
__device__ float g_sq[BB * QQ];
__device__ float g_cmax[BB * 8 * 128];
__device__ float g_csum[BB * 8 * 128];
__device__ __nv_bfloat16 g_Udh [BB * DD * HH], g_Udl [BB * DD * HH];  // Ud split [b,d,h] (written by gemm1)
__device__ __nv_bfloat16 g_Uqwh[BB * QQ * HH], g_Uqwl[BB * QQ * HH];  // Uq*wdot [b,q,h]
__device__ __nv_bfloat16 g_Uqph[BB * QQ * HH], g_Uqpl[BB * QQ * HH];  // Uq plain [b,q,h]
__device__ __nv_bfloat16 g_P1h [BB * DD * QQ], g_P1l [BB * DD * QQ];  // S_d2q [b,d,q]
__device__ __nv_bfloat16 g_P2th[BB * QQ * DD], g_P2tl[BB * QQ * DD];  // S_q2d^T [b,q,d]
__device__ __nv_bfloat16 g_Th  [BB * QQ * HH], g_Tl  [BB * QQ * HH];  // T [b,q,h]

// ---------------- helpers ----------------------------------------------------
__device__ __forceinline__ uint32_t smem_u32(const void* p) {
    uint32_t a;
    asm("{ .reg .u64 t; cvta.to.shared.u64 t, %1; cvt.u32.u64 %0, t; }" : "=r"(a) : "l"(p));
    return a;
}
__device__ __forceinline__ uint32_t L32(const __nv_bfloat16* p) {
    return *(const uint32_t*)p;
}
__device__ __forceinline__ void mma_bf16(float* c, const uint32_t* a, const uint32_t* b) {
    asm volatile(
        "mma.sync.aligned.m16n8k16.row.col.f32.bf16.bf16.f32 "
        "{%0,%1,%2,%3}, {%4,%5,%6,%7}, {%8,%9}, {%0,%1,%2,%3};"
        : "+f"(c[0]), "+f"(c[1]), "+f"(c[2]), "+f"(c[3])
        : "r"(a[0]), "r"(a[1]), "r"(a[2]), "r"(a[3]), "r"(b[0]), "r"(b[1]));
}
__device__ __forceinline__ void ldmx4t(uint32_t& r0, uint32_t& r1,
                                       uint32_t& r2, uint32_t& r3, uint32_t a) {
    asm volatile("ldmatrix.sync.aligned.m8n8.x4.trans.shared.b16 {%0,%1,%2,%3}, [%4];"
        : "=r"(r0), "=r"(r1), "=r"(r2), "=r"(r3) : "r"(a));
}
__device__ __forceinline__ void ldmx4(uint32_t& r0, uint32_t& r1,
                                      uint32_t& r2, uint32_t& r3, uint32_t a) {
    asm volatile("ldmatrix.sync.aligned.m8n8.x4.shared.b16 {%0,%1,%2,%3}, [%4];"
        : "=r"(r0), "=r"(r1), "=r"(r2), "=r"(r3) : "r"(a));
}
__device__ __forceinline__ void bsplit(float x, __nv_bfloat16& h, __nv_bfloat16& l) {
    h = __float2bfloat16(x);
    l = __float2bfloat16(x - __bfloat162float(h));
}
#define CPA16(sa, g) \
    asm volatile("cp.async.cg.shared.global [%0], [%1], 16;" :: "r"(sa), "l"(g))
#define CPA_COMMIT() asm volatile("cp.async.commit_group;" ::: "memory")
#define CPA_WAIT0()  asm volatile("cp.async.wait_group 0;" ::: "memory")
#define CPA_WAIT1()  asm volatile("cp.async.wait_group 1;" ::: "memory")

// A fragments via ldmatrix.x4: 4 m16 tiles from warp m-base MB; STb = row bytes
#define LOAD_AFRAGS(bAh, bAl, STb, MB)                                        \
    uint32_t ah[4][4], al[4][4];                                              \
    {                                                                         \
        uint32_t ao = (uint32_t)(((MB) + (lane & 15)) * (STb))                \
                    + (uint32_t)((kb + ((lane >> 4) << 3)) * 2);              \
        _Pragma("unroll")                                                     \
        for (int i = 0; i < 4; i++) {                                         \
            ldmx4(ah[i][0], ah[i][1], ah[i][2], ah[i][3],                     \
                  (bAh) + ao + (uint32_t)(i * 16 * (STb)));                   \
            ldmx4(al[i][0], al[i][1], al[i][2], al[i][3],                     \
                  (bAl) + ao + (uint32_t)(i * 16 * (STb)));                   \
        }                                                                     \
    }

#define MMA3PASS(ACC, BH, BL)                                                 \
    _Pragma("unroll")                                                         \
    for (int i = 0; i < 4; i++)                                               \
        _Pragma("unroll")                                                     \
        for (int j = 0; j < 4; j++) mma_bf16((ACC)[i][j], ah[i], (BH)[j]);    \
    _Pragma("unroll")                                                         \
    for (int i = 0; i < 4; i++)                                               \
        _Pragma("unroll")                                                     \
        for (int j = 0; j < 4; j++) mma_bf16((ACC)[i][j], ah[i], (BL)[j]);    \
    _Pragma("unroll")                                                         \
    for (int i = 0; i < 4; i++)                                               \
        _Pragma("unroll")                                                     \
        for (int j = 0; j < 4; j++) mma_bf16((ACC)[i][j], al[i], (BH)[j]);

#define LOAD_BFRAGS_K(sBh, sBl, ST, BH, BL)                                   \
    _Pragma("unroll")                                                         \
    for (int j = 0; j < 4; j++) {                                             \
        int c = wn * 32 + j * 8 + gr;                                         \
        const __nv_bfloat16* p = (sBh) + c * (ST) + kb + 2 * qp;              \
        const __nv_bfloat16* q = (sBl) + c * (ST) + kb + 2 * qp;              \
        BH[j][0] = L32(p); BH[j][1] = L32(p + 8);                             \
        BL[j][0] = L32(q); BL[j][1] = L32(q + 8);                             \
    }

#define LOAD_BFRAGS_T(bBh, bBl, STB, BH, BL)                                  \
    _Pragma("unroll")                                                         \
    for (int jj = 0; jj < 2; jj++) {                                          \
        int c0 = wn * 32 + jj * 16;                                           \
        uint32_t off = (uint32_t)(((kb + (lane & 15)) * (STB) + c0 +          \
                                   ((lane >> 4) * 8)) * 2);                   \
        ldmx4t(BH[2*jj][0], BH[2*jj][1], BH[2*jj+1][0], BH[2*jj+1][1], (bBh) + off); \
        ldmx4t(BL[2*jj][0], BL[2*jj][1], BL[2*jj+1][0], BL[2*jj+1][1], (bBl) + off); \
    }

#define GEMM_IDS                                                              \
    int t = threadIdx.x;                                                      \
    int wid = t >> 5, lane = t & 31;                                          \
    int wm = wid >> 2, wn = wid & 3;                                          \
    int gr = lane >> 2, qp = lane & 3;                                        \
    int srow = t >> 2, srow2 = (t >> 2) + 64, kc = (t & 3) * 8;

#define ACC_INIT(A)                                                           \
    _Pragma("unroll")                                                         \
    for (int i = 0; i < 4; i++)                                               \
        _Pragma("unroll")                                                     \
        for (int j = 0; j < 4; j++)                                           \
            _Pragma("unroll")                                                 \
            for (int e = 0; e < 4; e++) (A)[i][j][e] = 0.f;

// ---------------- conv_uq ----------------------------------------------------
__global__ void conv_uq_kernel(const float* __restrict__ Uq,
                               const float* __restrict__ wcw) {
    __shared__ float red[8];
    int row = blockIdx.x;
    int t = threadIdx.x;
    const float* src = Uq + (size_t)row * HH;
    float4 v = *(const float4*)(src + t * 4);
    float4 wd = *(const float4*)(wcw + 2 * HH + t * 4);
    float4 wq = *(const float4*)(wcw + HH + t * 4);
    __nv_bfloat16 h0, l0, h1, l1, h2, l2, h3, l3;
    bsplit(v.x, h0, l0); bsplit(v.y, h1, l1);
    bsplit(v.z, h2, l2); bsplit(v.w, h3, l3);
    size_t o = (size_t)row * HH + t * 4;
    *(__nv_bfloat162*)(g_Uqph + o)     = __nv_bfloat162(h0, h1);
    *(__nv_bfloat162*)(g_Uqph + o + 2) = __nv_bfloat162(h2, h3);
    *(__nv_bfloat162*)(g_Uqpl + o)     = __nv_bfloat162(l0, l1);
    *(__nv_bfloat162*)(g_Uqpl + o + 2) = __nv_bfloat162(l2, l3);
    float4 s = make_float4(v.x * wd.x, v.y * wd.y, v.z * wd.z, v.w * wd.w);
    bsplit(s.x, h0, l0); bsplit(s.y, h1, l1);
    bsplit(s.z, h2, l2); bsplit(s.w, h3, l3);
    *(__nv_bfloat162*)(g_Uqwh + o)     = __nv_bfloat162(h0, h1);
    *(__nv_bfloat162*)(g_Uqwh + o + 2) = __nv_bfloat162(h2, h3);
    *(__nv_bfloat162*)(g_Uqwl + o)     = __nv_bfloat162(l0, l1);
    *(__nv_bfloat162*)(g_Uqwl + o + 2) = __nv_bfloat162(l2, l3);
    float p = v.x * wq.x + v.y * wq.y + v.z * wq.z + v.w * wq.w;
    #pragma unroll
    for (int off = 16; off; off >>= 1) p += __shfl_xor_sync(0xffffffffu, p, off);
    if ((t & 31) == 0) red[t >> 5] = p;
    __syncthreads();
    if (t == 0) {
        float sum = 0.f;
        #pragma unroll
        for (int j = 0; j < 8; j++) sum += red[j];
        g_sq[row] = sum;
    }
}

// ---------------- GEMM1 fused + Ud split emission ----------------------------
// bytes: A stage s: s*20480 (hi 10240 | lo 10240); B stage s: 40960 + s*20480.
__global__ __launch_bounds__(256) void gemm1_mma(
    const float* __restrict__ Ud, const float* __restrict__ wcw,
    const float* __restrict__ wcb,
    const int* __restrict__ qm, const int* __restrict__ dmk) {
    extern __shared__ __nv_bfloat16 dyn[];
    __shared__ float redM[128][4], redS[128][4];
    __shared__ float2 colp[2][128];
    __shared__ int s_qm[128];
    __shared__ float s_sdv[128];
    __shared__ float s_wd[HH];
    GEMM_IDS
    int b = blockIdx.y, m0 = blockIdx.x * 128;
    const float* A = Ud + (size_t)b * DD * HH + (size_t)m0 * HH;
    const __nv_bfloat16* Bh = g_Uqwh + (size_t)b * QQ * HH;
    const __nv_bfloat16* Bl = g_Uqwl + (size_t)b * QQ * HH;
    float acc[4][4][4];
    ACC_INIT(acc)
    float sdp[4] = {0.f, 0.f, 0.f, 0.f};
    if (t < 128) s_qm[t] = qm[b * QQ + t];
    #pragma unroll
    for (int i = t; i < HH; i += 256) s_wd[i] = wcw[i];
    uint32_t sb = smem_u32(dyn);
    uint32_t sbB0 = sb + 40960;

    float4 pref[4];
    #pragma unroll
    for (int v = 0; v < 4; v++) {
        int idx = v * 256 + t;
        pref[v] = *(const float4*)(A + (size_t)(idx >> 3) * HH + (idx & 7) * 4);
    }
    CPA16(sbB0 +         srow  * 80 + kc * 2, Bh + (size_t)srow  * HH + kc);
    CPA16(sbB0 +         srow2 * 80 + kc * 2, Bh + (size_t)srow2 * HH + kc);
    CPA16(sbB0 + 10240 + srow  * 80 + kc * 2, Bl + (size_t)srow  * HH + kc);
    CPA16(sbB0 + 10240 + srow2 * 80 + kc * 2, Bl + (size_t)srow2 * HH + kc);
    CPA_COMMIT();
    __syncthreads();   // s_wd ready

    for (int it = 0; it < HH / 32; it++) {
        CPA_WAIT0();
        __nv_bfloat16* As = dyn + (it & 1) * 10240;
        #pragma unroll
        for (int v = 0; v < 4; v++) {
            int idx = v * 256 + t;
            int row = idx >> 3, cs = (idx & 7) * 4;
            float4 x = pref[v];
            float4 w = *(const float4*)(s_wd + it * 32 + cs);
            sdp[v] += x.x * w.x + x.y * w.y + x.z * w.z + x.w * w.w;
            __nv_bfloat16 h0, l0, h1, l1, h2, l2, h3, l3;
            bsplit(x.x, h0, l0); bsplit(x.y, h1, l1);
            bsplit(x.z, h2, l2); bsplit(x.w, h3, l3);
            __nv_bfloat162 hp0(h0, h1), hp1(h2, h3), lp0(l0, l1), lp1(l2, l3);
            *(__nv_bfloat162*)(As + row * 40 + cs)            = hp0;
            *(__nv_bfloat162*)(As + row * 40 + cs + 2)        = hp1;
            *(__nv_bfloat162*)(As + 5120 + row * 40 + cs)     = lp0;
            *(__nv_bfloat162*)(As + 5120 + row * 40 + cs + 2) = lp1;
            size_t go = ((size_t)b * DD + m0 + row) * HH + it * 32 + cs;
            *(__nv_bfloat162*)(g_Udh + go)     = hp0;
            *(__nv_bfloat162*)(g_Udh + go + 2) = hp1;
            *(__nv_bfloat162*)(g_Udl + go)     = lp0;
            *(__nv_bfloat162*)(g_Udl + go + 2) = lp1;
        }
        __syncthreads();
        if (it + 1 < HH / 32) {
            int k0 = (it + 1) * 32;
            uint32_t sbB = sbB0 + ((it + 1) & 1) * 20480;
            CPA16(sbB +         srow  * 80 + kc * 2, Bh + (size_t)srow  * HH + k0 + kc);
            CPA16(sbB +         srow2 * 80 + kc * 2, Bh + (size_t)srow2 * HH + k0 + kc);
            CPA16(sbB + 10240 + srow  * 80 + kc * 2, Bl + (size_t)srow  * HH + k0 + kc);
            CPA16(sbB + 10240 + srow2 * 80 + kc * 2, Bl + (size_t)srow2 * HH + k0 + kc);
            CPA_COMMIT();
            #pragma unroll
            for (int v = 0; v < 4; v++) {
                int idx = v * 256 + t;
                pref[v] = *(const float4*)(A + (size_t)(idx >> 3) * HH + k0 + (idx & 7) * 4);
            }
        }
        uint32_t aBh = sb + (it & 1) * 20480;
        uint32_t aBl = aBh + 10240;
        const __nv_bfloat16* cBh = dyn + 20480 + (it & 1) * 10240;
        const __nv_bfloat16* cBl = cBh + 5120;
        #pragma unroll
        for (int kb = 0; kb < 32; kb += 16) {
            LOAD_AFRAGS(aBh, aBl, 80, wm * 64)
            uint32_t bh[4][2], bl[4][2];
            LOAD_BFRAGS_K(cBh, cBl, 40, bh, bl)
            MMA3PASS(acc, bh, bl)
        }
    }

    // s_d reduce (8 lanes share a row)
    #pragma unroll
    for (int v = 0; v < 4; v++) {
        float s = sdp[v];
        s += __shfl_xor_sync(0xffffffffu, s, 1);
        s += __shfl_xor_sync(0xffffffffu, s, 2);
        s += __shfl_xor_sync(0xffffffffu, s, 4);
        if ((lane & 7) == 0) s_sdv[v * 32 + (t >> 3)] = s;
    }

    float bias = wcb[0];
    int dmv[4][2];
    #pragma unroll
    for (int i = 0; i < 4; i++)
        #pragma unroll
        for (int rr = 0; rr < 2; rr++)
            dmv[i][rr] = dmk[b * DD + m0 + wm * 64 + i * 16 + rr * 8 + gr];
    __syncthreads();
    float sdv[4][2];
    #pragma unroll
    for (int i = 0; i < 4; i++)
        #pragma unroll
        for (int rr = 0; rr < 2; rr++)
            sdv[i][rr] = s_sdv[wm * 64 + i * 16 + rr * 8 + gr] + bias;

    #pragma unroll
    for (int i = 0; i < 4; i++)
        #pragma unroll
        for (int j = 0; j < 4; j++) {
            int n = wn * 32 + j * 8 + 2 * qp;
            float sq0 = g_sq[b * QQ + n], sq1 = g_sq[b * QQ + n + 1];
            int q0 = s_qm[n] > 0, q1 = s_qm[n + 1] > 0;
            #pragma unroll
            for (int rr = 0; rr < 2; rr++) {
                int m = m0 + wm * 64 + i * 16 + rr * 8 + gr;
                float s0 = acc[i][j][2 * rr]     + sdv[i][rr] + sq0;
                float s1 = acc[i][j][2 * rr + 1] + sdv[i][rr] + sq1;
                *(float2*)(g_S + ((size_t)b * DD + m) * QQ + n) = make_float2(s0, s1);
                int dm = dmv[i][rr] > 0;
                acc[i][j][2 * rr]     = (dm && q0) ? s0 : -1e30f;
                acc[i][j][2 * rr + 1] = (dm && q1) ? s1 : -1e30f;
            }
        }

    float M[4][2];
    #pragma unroll
    for (int i = 0; i < 4; i++)
        #pragma unroll
        for (int rr = 0; rr < 2; rr++) {
            float mx = -1e30f;
            #pragma unroll
            for (int j = 0; j < 4; j++)
                mx = fmaxf(mx, fmaxf(acc[i][j][2 * rr], acc[i][j][2 * rr + 1]));
            mx = fmaxf(mx, __shfl_xor_sync(0xffffffffu, mx, 1));
            mx = fmaxf(mx, __shfl_xor_sync(0xffffffffu, mx, 2));
            if (qp == 0) redM[wm * 64 + i * 16 + rr * 8 + gr][wn] = mx;
        }
    __syncthreads();
    #pragma unroll
    for (int i = 0; i < 4; i++)
        #pragma unroll
        for (int rr = 0; rr < 2; rr++) {
            int r = wm * 64 + i * 16 + rr * 8 + gr;
            M[i][rr] = fmaxf(fmaxf(redM[r][0], redM[r][1]),
                             fmaxf(redM[r][2], redM[r][3]));
        }
    float inv[4][2];
    #pragma unroll
    for (int i = 0; i < 4; i++)
        #pragma unroll
        for (int rr = 0; rr < 2; rr++) {
            float s = 0.f;
            #pragma unroll
            for (int j = 0; j < 4; j++) {
                s += __expf(acc[i][j][2 * rr]     - M[i][rr]);
                s += __expf(acc[i][j][2 * rr + 1] - M[i][rr]);
            }
            s += __shfl_xor_sync(0xffffffffu, s, 1);
            s += __shfl_xor_sync(0xffffffffu, s, 2);
            if (qp == 0) redS[wm * 64 + i * 16 + rr * 8 + gr][wn] = s;
        }
    __syncthreads();
    #pragma unroll
    for (int i = 0; i < 4; i++)
        #pragma unroll
        for (int rr = 0; rr < 2; rr++) {
            int r = wm * 64 + i * 16 + rr * 8 + gr;
            inv[i][rr] = 1.f / (redS[r][0] + redS[r][1] + redS[r][2] + redS[r][3]);
        }
    #pragma unroll
    for (int i = 0; i < 4; i++)
        #pragma unroll
        for (int j = 0; j < 4; j++) {
            int n = wn * 32 + j * 8 + 2 * qp;
            int q0 = s_qm[n] > 0, q1 = s_qm[n + 1] > 0;
            #pragma unroll
            for (int rr = 0; rr < 2; rr++) {
                int m = m0 + wm * 64 + i * 16 + rr * 8 + gr;
                int dm = dmv[i][rr] > 0;
                float p0 = (dm && q0) ? __expf(acc[i][j][2 * rr]     - M[i][rr]) * inv[i][rr] : 0.f;
                float p1 = (dm && q1) ? __expf(acc[i][j][2 * rr + 1] - M[i][rr]) * inv[i][rr] : 0.f;
                __nv_bfloat16 h0, l0, h1, l1;
                bsplit(p0, h0, l0); bsplit(p1, h1, l1);
                size_t o = ((size_t)b * DD + m) * QQ + n;
                *(__nv_bfloat162*)(g_P1h + o) = __nv_bfloat162(h0, h1);
                *(__nv_bfloat162*)(g_P1l + o) = __nv_bfloat162(l0, l1);
            }
        }
    #pragma unroll
    for (int j = 0; j < 4; j++)
        #pragma unroll
        for (int cc = 0; cc < 2; cc++) {
            float cm = -1e30f;
            #pragma unroll
            for (int i = 0; i < 4; i++)
                #pragma unroll
                for (int rr = 0; rr < 2; rr++)
                    cm = fmaxf(cm, acc[i][j][2 * rr + cc]);
            float cs = 0.f;
            #pragma unroll
            for (int i = 0; i < 4; i++)
                #pragma unroll
                for (int rr = 0; rr < 2; rr++)
                    cs += __expf(acc[i][j][2 * rr + cc] - cm);
            #pragma unroll
            for (int o = 4; o <= 16; o <<= 1) {
                float om = __shfl_xor_sync(0xffffffffu, cm, o);
                float os = __shfl_xor_sync(0xffffffffu, cs, o);
                float nm = fmaxf(cm, om);
                cs = cs * __expf(cm - nm) + os * __expf(om - nm);
                cm = nm;
            }
            if (gr == 0) colp[wm][wn * 32 + j * 8 + 2 * qp + cc] = make_float2(cm, cs);
        }
    __syncthreads();
    if (t < 128) {
        float2 a = colp[0][t], c = colp[1][t];
        float nm = fmaxf(a.x, c.x);
        float s = a.y * __expf(a.x - nm) + c.y * __expf(c.x - nm);
        int idx = (b * 8 + blockIdx.x) * 128 + t;
        g_cmax[idx] = nm; g_csum[idx] = s;
    }
}

// ---------------- single-pass q2d softmax -> P2t hi/lo -----------------------
__global__ void softmax_q2d_kernel(const int* __restrict__ qm,
                                   const int* __restrict__ dmk) {
    __shared__ float sM[32], sI[32];
    __shared__ float tile[32][33];
    int b = blockIdx.y;
    int tx = threadIdx.x, ty = threadIdx.y;
    int q = blockIdx.x * 32 + tx;
    int qmv = qm[b * QQ + q];
    int tid = ty * 32 + tx;
    if (tid < 32) {
        int qq = blockIdx.x * 32 + tid;
        float m = -1e30f, s = 0.f;
        #pragma unroll
        for (int k = 0; k < 8; k++) {
            float mk = g_cmax[(b * 8 + k) * 128 + qq];
            float sk = g_csum[(b * 8 + k) * 128 + qq];
            float nm = fmaxf(m, mk);
            s = s * __expf(m - nm) + sk * __expf(mk - nm);
            m = nm;
        }
        sM[tid] = m; sI[tid] = 1.f / s;
    }
    __syncthreads();
    float M = sM[tx], inv = sI[tx];
    const float* base = g_S + (size_t)b * DD * QQ + q;
    int qr = tid >> 3, seg = (tid & 7) * 4;
    size_t drow = (size_t)b * QQ * DD + (size_t)(blockIdx.x * 32 + qr) * DD;
    for (int d0 = 0; d0 < DD; d0 += 32) {
        #pragma unroll
        for (int dj = ty; dj < 32; dj += 8) {
            int d = d0 + dj;
            int mk = (qmv > 0) && (dmk[b * DD + d] > 0);
            float v = base[(size_t)d * QQ];
            tile[tx][dj] = mk ? __expf(v - M) * inv : 0.f;
        }
        __syncthreads();
        float p0 = tile[qr][seg], p1 = tile[qr][seg + 1];
        float p2 = tile[qr][seg + 2], p3 = tile[qr][seg + 3];
        __nv_bfloat16 h0, l0, h1, l1, h2, l2, h3, l3;
        bsplit(p0, h0, l0); bsplit(p1, h1, l1);
        bsplit(p2, h2, l2); bsplit(p3, h3, l3);
        size_t o = drow + d0 + seg;
        *(__nv_bfloat162*)(g_P2th + o)     = __nv_bfloat162(h0, h1);
        *(__nv_bfloat162*)(g_P2th + o + 2) = __nv_bfloat162(h2, h3);
        *(__nv_bfloat162*)(g_P2tl + o)     = __nv_bfloat162(l0, l1);
        *(__nv_bfloat162*)(g_P2tl + o + 2) = __nv_bfloat162(l2, l3);
        __syncthreads();
    }
}

// ---------------- GEMM3: pure dual cp.async, 3-stage -------------------------
// stage bytes: Ah@0 10240 | Al@10240 | Bh@20480 8704 (stride 272B) | Bl@29184.
// stage total 37888; x3 = 113664 B dyn smem.
__global__ __launch_bounds__(256) void gemm3_mma() {
    extern __shared__ __nv_bfloat16 dyn[];
    GEMM_IDS
    int b = blockIdx.y, n0 = blockIdx.x * 128;
    const __nv_bfloat16* Ahg = g_P2th + (size_t)b * QQ * DD;
    const __nv_bfloat16* Alg = g_P2tl + (size_t)b * QQ * DD;
    const __nv_bfloat16* Bhg = g_Udh + (size_t)b * DD * HH;
    const __nv_bfloat16* Blg = g_Udl + (size_t)b * DD * HH;
    int dr = t >> 4, dr2 = dr + 16, cc = (t & 15) * 8;
    float acc[4][4][4];
    ACC_INIT(acc)
    uint32_t sb = smem_u32(dyn);

#define G3_ISSUE(st, k0)                                                      \
    {                                                                         \
        uint32_t ba = sb + (uint32_t)(((st) % 3) * 37888);                    \
        CPA16(ba +         srow  * 80 + kc * 2, Ahg + (size_t)srow  * DD + (k0) + kc); \
        CPA16(ba +         srow2 * 80 + kc * 2, Ahg + (size_t)srow2 * DD + (k0) + kc); \
        CPA16(ba + 10240 + srow  * 80 + kc * 2, Alg + (size_t)srow  * DD + (k0) + kc); \
        CPA16(ba + 10240 + srow2 * 80 + kc * 2, Alg + (size_t)srow2 * DD + (k0) + kc); \
        CPA16(ba + 20480 + dr  * 272 + cc * 2, Bhg + (size_t)((k0) + dr ) * HH + n0 + cc); \
        CPA16(ba + 20480 + dr2 * 272 + cc * 2, Bhg + (size_t)((k0) + dr2) * HH + n0 + cc); \
        CPA16(ba + 29184 + dr  * 272 + cc * 2, Blg + (size_t)((k0) + dr ) * HH + n0 + cc); \
        CPA16(ba + 29184 + dr2 * 272 + cc * 2, Blg + (size_t)((k0) + dr2) * HH + n0 + cc); \
        CPA_COMMIT();                                                         \
    }

    G3_ISSUE(0, 0)
    G3_ISSUE(1, 32)

    const int NIT = DD / 32;
    for (int it = 0; it < NIT; it++) {
        if (it + 1 < NIT) { CPA_WAIT1(); } else { CPA_WAIT0(); }
        __syncthreads();
        if (it + 2 < NIT) G3_ISSUE(it + 2, (it + 2) * 32)
        uint32_t ba = sb + (uint32_t)((it % 3) * 37888);
        uint32_t aBh = ba, aBl = ba + 10240;
        uint32_t bBh = ba + 20480, bBl = ba + 29184;
        #pragma unroll
        for (int kb = 0; kb < 32; kb += 16) {
            LOAD_AFRAGS(aBh, aBl, 80, wm * 64)
            uint32_t bh[4][2], bl[4][2];
            LOAD_BFRAGS_T(bBh, bBl, 136, bh, bl)
            MMA3PASS(acc, bh, bl)
        }
    }
#undef G3_ISSUE

    #pragma unroll
    for (int i = 0; i < 4; i++) {
        int m = wm * 64 + i * 16 + gr;   // q
        #pragma unroll
        for (int j = 0; j < 4; j++) {
            int n = n0 + wn * 32 + j * 8 + 2 * qp;
            #pragma unroll
            for (int rr = 0; rr < 2; rr++) {
                float a0 = acc[i][j][2 * rr], a1 = acc[i][j][2 * rr + 1];
                __nv_bfloat16 h0, l0, h1, l1;
                bsplit(a0, h0, l0); bsplit(a1, h1, l1);
                size_t o = ((size_t)b * QQ + m + rr * 8) * HH + n;
                *(__nv_bfloat162*)(g_Th + o) = __nv_bfloat162(h0, h1);
                *(__nv_bfloat162*)(g_Tl + o) = __nv_bfloat162(l0, l1);
            }
        }
    }
}

// ---------------- fused GEMM2+4: 2-group load overlap ------------------------
#define ST24 136
#define TSZ  (128 * ST24)
__global__ __launch_bounds__(256) void gemm24f_mma(
    const float* __restrict__ Ud, float* __restrict__ out) {
    extern __shared__ __nv_bfloat16 dyn[];
    GEMM_IDS
    (void)srow; (void)srow2; (void)kc;
    int b = blockIdx.z, n0 = blockIdx.x * 128, m0 = blockIdx.y * 128;
    const __nv_bfloat16* srcs[6];
    int strides[6];
    srcs[0] = g_P1h  + (size_t)b * DD * QQ + (size_t)m0 * QQ; strides[0] = QQ;
    srcs[1] = g_P1l  + (size_t)b * DD * QQ + (size_t)m0 * QQ; strides[1] = QQ;
    srcs[2] = g_Uqph + (size_t)b * QQ * HH + n0;              strides[2] = HH;
    srcs[3] = g_Uqpl + (size_t)b * QQ * HH + n0;              strides[3] = HH;
    srcs[4] = g_Th   + (size_t)b * QQ * HH + n0;              strides[4] = HH;
    srcs[5] = g_Tl   + (size_t)b * QQ * HH + n0;              strides[5] = HH;

    uint32_t sb = smem_u32(dyn);
    // group 1: A tiles (0,1) full + B tiles (2..5) rows 0..63
    #pragma unroll
    for (int v = 0; v < 8; v++) {
        int c = v * 256 + t;
        int row = c >> 4, kb8 = (c & 15) * 8;
        #pragma unroll
        for (int s = 0; s < 2; s++)
            CPA16(sb + s * (TSZ * 2) + row * (ST24 * 2) + kb8 * 2,
                  srcs[s] + (size_t)row * strides[s] + kb8);
    }
    #pragma unroll
    for (int v = 0; v < 4; v++) {
        int c = v * 256 + t;
        int row = c >> 4, kb8 = (c & 15) * 8;
        #pragma unroll
        for (int s = 2; s < 6; s++)
            CPA16(sb + s * (TSZ * 2) + row * (ST24 * 2) + kb8 * 2,
                  srcs[s] + (size_t)row * strides[s] + kb8);
    }
    CPA_COMMIT();
    // group 2: B tiles rows 64..127
    #pragma unroll
    for (int v = 0; v < 4; v++) {
        int c = v * 256 + t;
        int row = 64 + (c >> 4), kb8 = (c & 15) * 8;
        #pragma unroll
        for (int s = 2; s < 6; s++)
            CPA16(sb + s * (TSZ * 2) + row * (ST24 * 2) + kb8 * 2,
                  srcs[s] + (size_t)row * strides[s] + kb8);
    }
    CPA_COMMIT();

    float acc2[4][4][4], acc4[4][4][4];
    ACC_INIT(acc2)
    ACC_INIT(acc4)
    uint32_t aBh = sb, aBl = sb + TSZ * 2;
    uint32_t b2h = sb + 2 * (TSZ * 2), b2l = sb + 3 * (TSZ * 2);
    uint32_t b4h = sb + 4 * (TSZ * 2), b4l = sb + 5 * (TSZ * 2);

    CPA_WAIT1();
    __syncthreads();
    #pragma unroll
    for (int s = 0; s < 4; s++) {
        int kb = s * 16;
        LOAD_AFRAGS(aBh, aBl, ST24 * 2, wm * 64)
        {
            uint32_t bh[4][2], bl[4][2];
            LOAD_BFRAGS_T(b2h, b2l, ST24, bh, bl)
            MMA3PASS(acc2, bh, bl)
        }
        {
            uint32_t bh[4][2], bl[4][2];
            LOAD_BFRAGS_T(b4h, b4l, ST24, bh, bl)
            MMA3PASS(acc4, bh, bl)
        }
    }
    CPA_WAIT0();
    __syncthreads();
    #pragma unroll
    for (int s = 4; s < 8; s++) {
        int kb = s * 16;
        LOAD_AFRAGS(aBh, aBl, ST24 * 2, wm * 64)
        {
            uint32_t bh[4][2], bl[4][2];
            LOAD_BFRAGS_T(b2h, b2l, ST24, bh, bl)
            MMA3PASS(acc2, bh, bl)
        }
        {
            uint32_t bh[4][2], bl[4][2];
            LOAD_BFRAGS_T(b4h, b4l, ST24, bh, bl)
            MMA3PASS(acc4, bh, bl)
        }
    }

    #pragma unroll
    for (int i = 0; i < 4; i++) {
        int m = m0 + wm * 64 + i * 16 + gr;
        #pragma unroll
        for (int j = 0; j < 4; j++) {
            int n = n0 + wn * 32 + j * 8 + 2 * qp;
            #pragma unroll
            for (int rr = 0; rr < 2; rr++) {
                int mm = m + rr * 8;
                float a2x = acc2[i][j][2 * rr], a2y = acc2[i][j][2 * rr + 1];
                float a4x = acc4[i][j][2 * rr], a4y = acc4[i][j][2 * rr + 1];
                float2 u = *(const float2*)(Ud + ((size_t)b * DD + mm) * HH + n);
                float* ob = out + ((size_t)b * DD + mm) * (size_t)(4 * HH) + n;
                *(float2*)(ob)          = u;
                *(float2*)(ob + HH)     = make_float2(a2x, a2y);
                *(float2*)(ob + 2 * HH) = make_float2(u.x * a2x, u.y * a2y);
                *(float2*)(ob + 3 * HH) = make_float2(u.x * a4x, u.y * a4y);
            }
        }
    }
}

// ---------------------------------------------------------------------------
extern "C" void kernel_launch(void* const* d_in, const int* in_sizes, int n_in,
                              void* d_out, int out_size) {
    const float* Ud  = (const float*)d_in[0];
    const float* Uq  = (const float*)d_in[1];
    const float* wcw = (const float*)d_in[2];
    const float* wcb = (const float*)d_in[3];
    const int*   qm  = (const int*)d_in[4];
    const int*   dmk = (const int*)d_in[5];
    float* out = (float*)d_out;

    cudaFuncSetAttribute(gemm1_mma,   cudaFuncAttributeMaxDynamicSharedMemorySize, 81920);
    cudaFuncSetAttribute(gemm3_mma,   cudaFuncAttributeMaxDynamicSharedMemorySize, 113664);
    cudaFuncSetAttribute(gemm24f_mma, cudaFuncAttributeMaxDynamicSharedMemorySize, 208896);

    conv_uq_kernel<<<BB * QQ, 256>>>(Uq, wcw);

    // logits + row softmax + col partials + s_d + Ud split emission
    gemm1_mma<<<dim3(DD / 128, BB), 256, 81920>>>(Ud, wcw, wcb, qm, dmk);

    softmax_q2d_kernel<<<dim3(QQ / 32, BB), dim3(32, 8)>>>(qm, dmk);

    // T = P2^T @ Ud  (pure dual cp.async, 3-stage)
    gemm3_mma<<<dim3(HH / 128, BB), 256, 113664>>>();

    gemm24f_mma<<<dim3(HH / 128, DD / 128, BB), 256, 208896>>>(Ud, out);
}

// round 14
// speedup vs baseline: 1.2121x; 1.1608x over previous
#include <cuda_runtime.h>
#include <cuda_bf16.h>
#include <cstdint>

#define BB 16
#define DD 1024
#define QQ 128
#define HH 1024

// ---------------- scratch (device globals) ----------------------------------
__device__ float g_S [BB * DD * QQ];
__device__ float g_sq[BB * QQ];
__device__ float g_cmax[BB * 8 * 128];
__device__ float g_csum[BB * 8 * 128];
__device__ float g_F   [BB * DD];     // rowSum * exp(rowMax) per (b,d)
__device__ __nv_bfloat16 g_Uqwh[BB * QQ * HH], g_Uqwl[BB * QQ * HH];  // Uq*wdot [b,q,h]
__device__ __nv_bfloat16 g_Uqph[BB * QQ * HH], g_Uqpl[BB * QQ * HH];  // Uq plain [b,q,h]
__device__ __nv_bfloat16 g_P1h [BB * DD * QQ], g_P1l [BB * DD * QQ];  // S_d2q [b,d,q]
__device__ __nv_bfloat16 g_P2th[BB * QQ * DD];                        // S_q2d^T hi [b,q,d]
__device__ __nv_bfloat16 g_Th  [BB * QQ * HH], g_Tl  [BB * QQ * HH];  // T [b,q,h]

// ---------------- helpers ----------------------------------------------------
__device__ __forceinline__ uint32_t smem_u32(const void* p) {
    uint32_t a;
    asm("{ .reg .u64 t; cvta.to.shared.u64 t, %1; cvt.u32.u64 %0, t; }" : "=r"(a) : "l"(p));
    return a;
}
__device__ __forceinline__ uint32_t L32(const __nv_bfloat16* p) {
    return *(const uint32_t*)p;
}
__device__ __forceinline__ void mma_bf16(float* c, const uint32_t* a, const uint32_t* b) {
    asm volatile(
        "mma.sync.aligned.m16n8k16.row.col.f32.bf16.bf16.f32 "
        "{%0,%1,%2,%3}, {%4,%5,%6,%7}, {%8,%9}, {%0,%1,%2,%3};"
        : "+f"(c[0]), "+f"(c[1]), "+f"(c[2]), "+f"(c[3])
        : "r"(a[0]), "r"(a[1]), "r"(a[2]), "r"(a[3]), "r"(b[0]), "r"(b[1]));
}
__device__ __forceinline__ void ldmx4t(uint32_t& r0, uint32_t& r1,
                                       uint32_t& r2, uint32_t& r3, uint32_t a) {
    asm volatile("ldmatrix.sync.aligned.m8n8.x4.trans.shared.b16 {%0,%1,%2,%3}, [%4];"
        : "=r"(r0), "=r"(r1), "=r"(r2), "=r"(r3) : "r"(a));
}
__device__ __forceinline__ void bsplit(float x, __nv_bfloat16& h, __nv_bfloat16& l) {
    h = __float2bfloat16(x);
    l = __float2bfloat16(x - __bfloat162float(h));
}
#define CPA16(sa, g) \
    asm volatile("cp.async.cg.shared.global [%0], [%1], 16;" :: "r"(sa), "l"(g))
#define CPA_COMMIT() asm volatile("cp.async.commit_group;" ::: "memory")
#define CPA_WAIT0()  asm volatile("cp.async.wait_group 0;" ::: "memory")

// A fragments (hi+lo), K-contiguous layout, stride ST elems
#define LOAD_AFRAGS(sAh, sAl, ST)                                             \
    uint32_t ah[4][4], al[4][4];                                              \
    _Pragma("unroll")                                                         \
    for (int i = 0; i < 4; i++) {                                             \
        int r = wm * 64 + i * 16 + gr;                                        \
        const __nv_bfloat16* p = (sAh) + r * (ST) + kb + 2 * qp;              \
        const __nv_bfloat16* q = (sAl) + r * (ST) + kb + 2 * qp;              \
        ah[i][0] = L32(p);            ah[i][1] = L32(p + 8 * (ST));           \
        ah[i][2] = L32(p + 8);        ah[i][3] = L32(p + 8 * (ST) + 8);       \
        al[i][0] = L32(q);            al[i][1] = L32(q + 8 * (ST));           \
        al[i][2] = L32(q + 8);        al[i][3] = L32(q + 8 * (ST) + 8);       \
    }

// A fragments (hi only)
#define LOAD_AFRAGS_H(sAh, ST)                                                \
    uint32_t ah[4][4];                                                        \
    _Pragma("unroll")                                                         \
    for (int i = 0; i < 4; i++) {                                             \
        int r = wm * 64 + i * 16 + gr;                                        \
        const __nv_bfloat16* p = (sAh) + r * (ST) + kb + 2 * qp;              \
        ah[i][0] = L32(p);            ah[i][1] = L32(p + 8 * (ST));           \
        ah[i][2] = L32(p + 8);        ah[i][3] = L32(p + 8 * (ST) + 8);       \
    }

#define MMA3PASS(ACC, BH, BL)                                                 \
    _Pragma("unroll")                                                         \
    for (int i = 0; i < 4; i++)                                               \
        _Pragma("unroll")                                                     \
        for (int j = 0; j < 4; j++) mma_bf16((ACC)[i][j], ah[i], (BH)[j]);    \
    _Pragma("unroll")                                                         \
    for (int i = 0; i < 4; i++)                                               \
        _Pragma("unroll")                                                     \
        for (int j = 0; j < 4; j++) mma_bf16((ACC)[i][j], ah[i], (BL)[j]);    \
    _Pragma("unroll")                                                         \
    for (int i = 0; i < 4; i++)                                               \
        _Pragma("unroll")                                                     \
        for (int j = 0; j < 4; j++) mma_bf16((ACC)[i][j], al[i], (BH)[j]);

// 2-pass variant: bf16(A) x full-precision B
#define MMA2PASS(ACC, BH, BL)                                                 \
    _Pragma("unroll")                                                         \
    for (int i = 0; i < 4; i++)                                               \
        _Pragma("unroll")                                                     \
        for (int j = 0; j < 4; j++) mma_bf16((ACC)[i][j], ah[i], (BH)[j]);    \
    _Pragma("unroll")                                                         \
    for (int i = 0; i < 4; i++)                                               \
        _Pragma("unroll")                                                     \
        for (int j = 0; j < 4; j++) mma_bf16((ACC)[i][j], ah[i], (BL)[j]);

#define LOAD_BFRAGS_K(sBh, sBl, ST, BH, BL)                                   \
    _Pragma("unroll")                                                         \
    for (int j = 0; j < 4; j++) {                                             \
        int c = wn * 32 + j * 8 + gr;                                         \
        const __nv_bfloat16* p = (sBh) + c * (ST) + kb + 2 * qp;              \
        const __nv_bfloat16* q = (sBl) + c * (ST) + kb + 2 * qp;              \
        BH[j][0] = L32(p); BH[j][1] = L32(p + 8);                             \
        BL[j][0] = L32(q); BL[j][1] = L32(q + 8);                             \
    }

#define LOAD_BFRAGS_T(bBh, bBl, STB, BH, BL)                                  \
    _Pragma("unroll")                                                         \
    for (int jj = 0; jj < 2; jj++) {                                          \
        int c0 = wn * 32 + jj * 16;                                           \
        uint32_t off = (uint32_t)(((kb + (lane & 15)) * (STB) + c0 +          \
                                   ((lane >> 4) * 8)) * 2);                   \
        ldmx4t(BH[2*jj][0], BH[2*jj][1], BH[2*jj+1][0], BH[2*jj+1][1], (bBh) + off); \
        ldmx4t(BL[2*jj][0], BL[2*jj][1], BL[2*jj+1][0], BL[2*jj+1][1], (bBl) + off); \
    }

#define GEMM_IDS                                                              \
    int t = threadIdx.x;                                                      \
    int wid = t >> 5, lane = t & 31;                                          \
    int wm = wid >> 2, wn = wid & 3;                                          \
    int gr = lane >> 2, qp = lane & 3;                                        \
    int srow = t >> 2, srow2 = (t >> 2) + 64, kc = (t & 3) * 8;

#define ACC_INIT(A)                                                           \
    _Pragma("unroll")                                                         \
    for (int i = 0; i < 4; i++)                                               \
        _Pragma("unroll")                                                     \
        for (int j = 0; j < 4; j++)                                           \
            _Pragma("unroll")                                                 \
            for (int e = 0; e < 4; e++) (A)[i][j][e] = 0.f;

// ---------------- conv_uq ----------------------------------------------------
__global__ void conv_uq_kernel(const float* __restrict__ Uq,
                               const float* __restrict__ wcw) {
    __shared__ float red[8];
    int row = blockIdx.x;
    int t = threadIdx.x;
    const float* src = Uq + (size_t)row * HH;
    float4 v = *(const float4*)(src + t * 4);
    float4 wd = *(const float4*)(wcw + 2 * HH + t * 4);
    float4 wq = *(const float4*)(wcw + HH + t * 4);
    __nv_bfloat16 h0, l0, h1, l1, h2, l2, h3, l3;
    bsplit(v.x, h0, l0); bsplit(v.y, h1, l1);
    bsplit(v.z, h2, l2); bsplit(v.w, h3, l3);
    size_t o = (size_t)row * HH + t * 4;
    *(__nv_bfloat162*)(g_Uqph + o)     = __nv_bfloat162(h0, h1);
    *(__nv_bfloat162*)(g_Uqph + o + 2) = __nv_bfloat162(h2, h3);
    *(__nv_bfloat162*)(g_Uqpl + o)     = __nv_bfloat162(l0, l1);
    *(__nv_bfloat162*)(g_Uqpl + o + 2) = __nv_bfloat162(l2, l3);
    float4 s = make_float4(v.x * wd.x, v.y * wd.y, v.z * wd.z, v.w * wd.w);
    bsplit(s.x, h0, l0); bsplit(s.y, h1, l1);
    bsplit(s.z, h2, l2); bsplit(s.w, h3, l3);
    *(__nv_bfloat162*)(g_Uqwh + o)     = __nv_bfloat162(h0, h1);
    *(__nv_bfloat162*)(g_Uqwh + o + 2) = __nv_bfloat162(h2, h3);
    *(__nv_bfloat162*)(g_Uqwl + o)     = __nv_bfloat162(l0, l1);
    *(__nv_bfloat162*)(g_Uqwl + o + 2) = __nv_bfloat162(l2, l3);
    float p = v.x * wq.x + v.y * wq.y + v.z * wq.z + v.w * wq.w;
    #pragma unroll
    for (int off = 16; off; off >>= 1) p += __shfl_xor_sync(0xffffffffu, p, off);
    if ((t & 31) == 0) red[t >> 5] = p;
    __syncthreads();
    if (t == 0) {
        float sum = 0.f;
        #pragma unroll
        for (int j = 0; j < 8; j++) sum += red[j];
        g_sq[row] = sum;
    }
}

// ---------------- GEMM1 fused: S, P1, col partials, s_d, F -------------------
__global__ __launch_bounds__(256) void gemm1_mma(
    const float* __restrict__ Ud, const float* __restrict__ wcw,
    const float* __restrict__ wcb,
    const int* __restrict__ qm, const int* __restrict__ dmk) {
    extern __shared__ __nv_bfloat16 dyn[];
    __shared__ float redM[128][4], redS[128][4];
    __shared__ float2 colp[2][128];
    __shared__ int s_qm[128];
    __shared__ float s_sdv[128];
    __shared__ float s_wd[HH];
    GEMM_IDS
    int b = blockIdx.y, m0 = blockIdx.x * 128;
    const float* A = Ud + (size_t)b * DD * HH + (size_t)m0 * HH;
    const __nv_bfloat16* Bh = g_Uqwh + (size_t)b * QQ * HH;
    const __nv_bfloat16* Bl = g_Uqwl + (size_t)b * QQ * HH;
    float acc[4][4][4];
    ACC_INIT(acc)
    float sdp[4] = {0.f, 0.f, 0.f, 0.f};
    if (t < 128) s_qm[t] = qm[b * QQ + t];
    #pragma unroll
    for (int i = t; i < HH; i += 256) s_wd[i] = wcw[i];
    uint32_t sbB0 = smem_u32(dyn) + 40960;

    float4 pref[4];
    #pragma unroll
    for (int v = 0; v < 4; v++) {
        int idx = v * 256 + t;
        pref[v] = *(const float4*)(A + (size_t)(idx >> 3) * HH + (idx & 7) * 4);
    }
    CPA16(sbB0 +         srow  * 80 + kc * 2, Bh + (size_t)srow  * HH + kc);
    CPA16(sbB0 +         srow2 * 80 + kc * 2, Bh + (size_t)srow2 * HH + kc);
    CPA16(sbB0 + 10240 + srow  * 80 + kc * 2, Bl + (size_t)srow  * HH + kc);
    CPA16(sbB0 + 10240 + srow2 * 80 + kc * 2, Bl + (size_t)srow2 * HH + kc);
    CPA_COMMIT();
    __syncthreads();   // s_wd ready

    for (int it = 0; it < HH / 32; it++) {
        CPA_WAIT0();
        __nv_bfloat16* As = dyn + (it & 1) * 10240;
        #pragma unroll
        for (int v = 0; v < 4; v++) {
            int idx = v * 256 + t;
            int row = idx >> 3, cs = (idx & 7) * 4;
            float4 x = pref[v];
            float4 w = *(const float4*)(s_wd + it * 32 + cs);
            sdp[v] += x.x * w.x + x.y * w.y + x.z * w.z + x.w * w.w;
            __nv_bfloat16 h0, l0, h1, l1, h2, l2, h3, l3;
            bsplit(x.x, h0, l0); bsplit(x.y, h1, l1);
            bsplit(x.z, h2, l2); bsplit(x.w, h3, l3);
            *(__nv_bfloat162*)(As + row * 40 + cs)            = __nv_bfloat162(h0, h1);
            *(__nv_bfloat162*)(As + row * 40 + cs + 2)        = __nv_bfloat162(h2, h3);
            *(__nv_bfloat162*)(As + 5120 + row * 40 + cs)     = __nv_bfloat162(l0, l1);
            *(__nv_bfloat162*)(As + 5120 + row * 40 + cs + 2) = __nv_bfloat162(l2, l3);
        }
        __syncthreads();
        if (it + 1 < HH / 32) {
            int k0 = (it + 1) * 32;
            uint32_t sbB = sbB0 + ((it + 1) & 1) * 20480;
            CPA16(sbB +         srow  * 80 + kc * 2, Bh + (size_t)srow  * HH + k0 + kc);
            CPA16(sbB +         srow2 * 80 + kc * 2, Bh + (size_t)srow2 * HH + k0 + kc);
            CPA16(sbB + 10240 + srow  * 80 + kc * 2, Bl + (size_t)srow  * HH + k0 + kc);
            CPA16(sbB + 10240 + srow2 * 80 + kc * 2, Bl + (size_t)srow2 * HH + k0 + kc);
            CPA_COMMIT();
            #pragma unroll
            for (int v = 0; v < 4; v++) {
                int idx = v * 256 + t;
                pref[v] = *(const float4*)(A + (size_t)(idx >> 3) * HH + k0 + (idx & 7) * 4);
            }
        }
        const __nv_bfloat16* cA = dyn + (it & 1) * 10240;
        const __nv_bfloat16* cB = dyn + 20480 + (it & 1) * 10240;
        #pragma unroll
        for (int kb = 0; kb < 32; kb += 16) {
            LOAD_AFRAGS(cA, cA + 5120, 40)
            uint32_t bh[4][2], bl[4][2];
            LOAD_BFRAGS_K(cB, cB + 5120, 40, bh, bl)
            MMA3PASS(acc, bh, bl)
        }
    }

    // s_d reduce (8 lanes share a row)
    #pragma unroll
    for (int v = 0; v < 4; v++) {
        float s = sdp[v];
        s += __shfl_xor_sync(0xffffffffu, s, 1);
        s += __shfl_xor_sync(0xffffffffu, s, 2);
        s += __shfl_xor_sync(0xffffffffu, s, 4);
        if ((lane & 7) == 0) s_sdv[v * 32 + (t >> 3)] = s;
    }

    float bias = wcb[0];
    int dmv[4][2];
    #pragma unroll
    for (int i = 0; i < 4; i++)
        #pragma unroll
        for (int rr = 0; rr < 2; rr++)
            dmv[i][rr] = dmk[b * DD + m0 + wm * 64 + i * 16 + rr * 8 + gr];
    __syncthreads();
    float sdv[4][2];
    #pragma unroll
    for (int i = 0; i < 4; i++)
        #pragma unroll
        for (int rr = 0; rr < 2; rr++)
            sdv[i][rr] = s_sdv[wm * 64 + i * 16 + rr * 8 + gr] + bias;

    #pragma unroll
    for (int i = 0; i < 4; i++)
        #pragma unroll
        for (int j = 0; j < 4; j++) {
            int n = wn * 32 + j * 8 + 2 * qp;
            float sq0 = g_sq[b * QQ + n], sq1 = g_sq[b * QQ + n + 1];
            int q0 = s_qm[n] > 0, q1 = s_qm[n + 1] > 0;
            #pragma unroll
            for (int rr = 0; rr < 2; rr++) {
                int m = m0 + wm * 64 + i * 16 + rr * 8 + gr;
                float s0 = acc[i][j][2 * rr]     + sdv[i][rr] + sq0;
                float s1 = acc[i][j][2 * rr + 1] + sdv[i][rr] + sq1;
                *(float2*)(g_S + ((size_t)b * DD + m) * QQ + n) = make_float2(s0, s1);
                int dm = dmv[i][rr] > 0;
                acc[i][j][2 * rr]     = (dm && q0) ? s0 : -1e30f;
                acc[i][j][2 * rr + 1] = (dm && q1) ? s1 : -1e30f;
            }
        }

    // row softmax max
    float M[4][2];
    #pragma unroll
    for (int i = 0; i < 4; i++)
        #pragma unroll
        for (int rr = 0; rr < 2; rr++) {
            float mx = -1e30f;
            #pragma unroll
            for (int j = 0; j < 4; j++)
                mx = fmaxf(mx, fmaxf(acc[i][j][2 * rr], acc[i][j][2 * rr + 1]));
            mx = fmaxf(mx, __shfl_xor_sync(0xffffffffu, mx, 1));
            mx = fmaxf(mx, __shfl_xor_sync(0xffffffffu, mx, 2));
            if (qp == 0) redM[wm * 64 + i * 16 + rr * 8 + gr][wn] = mx;
        }
    __syncthreads();
    #pragma unroll
    for (int i = 0; i < 4; i++)
        #pragma unroll
        for (int rr = 0; rr < 2; rr++) {
            int r = wm * 64 + i * 16 + rr * 8 + gr;
            M[i][rr] = fmaxf(fmaxf(redM[r][0], redM[r][1]),
                             fmaxf(redM[r][2], redM[r][3]));
        }
    // row softmax sum
    float inv[4][2];
    #pragma unroll
    for (int i = 0; i < 4; i++)
        #pragma unroll
        for (int rr = 0; rr < 2; rr++) {
            float s = 0.f;
            #pragma unroll
            for (int j = 0; j < 4; j++) {
                s += __expf(acc[i][j][2 * rr]     - M[i][rr]);
                s += __expf(acc[i][j][2 * rr + 1] - M[i][rr]);
            }
            s += __shfl_xor_sync(0xffffffffu, s, 1);
            s += __shfl_xor_sync(0xffffffffu, s, 2);
            if (qp == 0) redS[wm * 64 + i * 16 + rr * 8 + gr][wn] = s;
        }
    __syncthreads();
    #pragma unroll
    for (int i = 0; i < 4; i++)
        #pragma unroll
        for (int rr = 0; rr < 2; rr++) {
            int r = wm * 64 + i * 16 + rr * 8 + gr;
            float tot = redS[r][0] + redS[r][1] + redS[r][2] + redS[r][3];
            inv[i][rr] = 1.f / tot;
            // F = rowSum * exp(rowMax)  (one writer per row)
            if (qp == 0 && wn == 0)
                g_F[b * DD + m0 + r] = tot * __expf(M[i][rr]);
        }
    // P1 write
    #pragma unroll
    for (int i = 0; i < 4; i++)
        #pragma unroll
        for (int j = 0; j < 4; j++) {
            int n = wn * 32 + j * 8 + 2 * qp;
            int q0 = s_qm[n] > 0, q1 = s_qm[n + 1] > 0;
            #pragma unroll
            for (int rr = 0; rr < 2; rr++) {
                int m = m0 + wm * 64 + i * 16 + rr * 8 + gr;
                int dm = dmv[i][rr] > 0;
                float p0 = (dm && q0) ? __expf(acc[i][j][2 * rr]     - M[i][rr]) * inv[i][rr] : 0.f;
                float p1 = (dm && q1) ? __expf(acc[i][j][2 * rr + 1] - M[i][rr]) * inv[i][rr] : 0.f;
                __nv_bfloat16 h0, l0, h1, l1;
                bsplit(p0, h0, l0); bsplit(p1, h1, l1);
                size_t o = ((size_t)b * DD + m) * QQ + n;
                *(__nv_bfloat162*)(g_P1h + o) = __nv_bfloat162(h0, h1);
                *(__nv_bfloat162*)(g_P1l + o) = __nv_bfloat162(l0, l1);
            }
        }
    // column partials
    #pragma unroll
    for (int j = 0; j < 4; j++)
        #pragma unroll
        for (int cc = 0; cc < 2; cc++) {
            float cm = -1e30f;
            #pragma unroll
            for (int i = 0; i < 4; i++)
                #pragma unroll
                for (int rr = 0; rr < 2; rr++)
                    cm = fmaxf(cm, acc[i][j][2 * rr + cc]);
            float cs = 0.f;
            #pragma unroll
            for (int i = 0; i < 4; i++)
                #pragma unroll
                for (int rr = 0; rr < 2; rr++)
                    cs += __expf(acc[i][j][2 * rr + cc] - cm);
            #pragma unroll
            for (int o = 4; o <= 16; o <<= 1) {
                float om = __shfl_xor_sync(0xffffffffu, cm, o);
                float os = __shfl_xor_sync(0xffffffffu, cs, o);
                float nm = fmaxf(cm, om);
                cs = cs * __expf(cm - nm) + os * __expf(om - nm);
                cm = nm;
            }
            if (gr == 0) colp[wm][wn * 32 + j * 8 + 2 * qp + cc] = make_float2(cm, cs);
        }
    __syncthreads();
    if (t < 128) {
        float2 a = colp[0][t], c = colp[1][t];
        float nm = fmaxf(a.x, c.x);
        float s = a.y * __expf(a.x - nm) + c.y * __expf(c.x - nm);
        int idx = (b * 8 + blockIdx.x) * 128 + t;
        g_cmax[idx] = nm; g_csum[idx] = s;
    }
}

// ---------------- exp-free q2d: P2t[q,d] = P1[d,q] * F[d] * G[q] -------------
__global__ void softmax_q2d_kernel(const int* __restrict__ qm) {
    __shared__ float sG[32], sF[32];
    __shared__ float tile[32][33];
    int b = blockIdx.y;
    int tx = threadIdx.x, ty = threadIdx.y;
    int tid = ty * 32 + tx;
    if (tid < 32) {
        int qq = blockIdx.x * 32 + tid;
        float m = -1e30f, s = 0.f;
        #pragma unroll
        for (int k = 0; k < 8; k++) {
            float mk = g_cmax[(b * 8 + k) * 128 + qq];
            float sk = g_csum[(b * 8 + k) * 128 + qq];
            float nm = fmaxf(m, mk);
            s = s * __expf(m - nm) + sk * __expf(mk - nm);
            m = nm;
        }
        float G = 0.f;
        if (qm[b * QQ + qq] > 0 && m > -1e29f && s > 0.f)
            G = __expf(-m) / s;
        sG[tid] = G;
    }
    __syncthreads();
    int qr = tid >> 3, seg = (tid & 7) * 4;
    float Gq = sG[qr];
    size_t drow = (size_t)b * QQ * DD + (size_t)(blockIdx.x * 32 + qr) * DD;
    for (int d0 = 0; d0 < DD; d0 += 32) {
        if (tid < 32) sF[tid] = g_F[b * DD + d0 + tid];
        __syncthreads();
        #pragma unroll
        for (int dj = ty; dj < 32; dj += 8) {
            int d = d0 + dj;
            size_t o = ((size_t)b * DD + d) * QQ + blockIdx.x * 32 + tx;
            float v = (__bfloat162float(g_P1h[o]) + __bfloat162float(g_P1l[o])) * sF[dj];
            tile[tx][dj] = v;
        }
        __syncthreads();
        float p0 = tile[qr][seg]     * Gq, p1 = tile[qr][seg + 1] * Gq;
        float p2 = tile[qr][seg + 2] * Gq, p3 = tile[qr][seg + 3] * Gq;
        __nv_bfloat16 h0 = __float2bfloat16(p0), h1 = __float2bfloat16(p1);
        __nv_bfloat16 h2 = __float2bfloat16(p2), h3 = __float2bfloat16(p3);
        size_t o = drow + d0 + seg;
        *(__nv_bfloat162*)(g_P2th + o)     = __nv_bfloat162(h0, h1);
        *(__nv_bfloat162*)(g_P2th + o + 2) = __nv_bfloat162(h2, h3);
        __syncthreads();
    }
}

// ---------------- GEMM3 (2-pass): T[q,h] = sum_d P2h[q,d] * Ud[d,h] ----------
// stage (elems): Ah [0,5120) | Bh [5120,9472) stride 136 | Bl [9472,13824).
// stage bytes 27648; x2 = 55296 dyn smem.
__global__ __launch_bounds__(256) void gemm3_mma(const float* __restrict__ Ud) {
    extern __shared__ __nv_bfloat16 dyn[];
    GEMM_IDS
    int b = blockIdx.y, n0 = blockIdx.x * 128;
    const __nv_bfloat16* Ahg = g_P2th + (size_t)b * QQ * DD;
    const float* Bg = Ud + (size_t)b * DD * HH + n0;
    float acc[4][4][4];
    ACC_INIT(acc)
    uint32_t sb = smem_u32(dyn);

    CPA16(sb + srow  * 80 + kc * 2, Ahg + (size_t)srow  * DD + kc);
    CPA16(sb + srow2 * 80 + kc * 2, Ahg + (size_t)srow2 * DD + kc);
    CPA_COMMIT();
    float4 pref[4];
    #pragma unroll
    for (int v = 0; v < 4; v++) {
        int idx = v * 256 + t;
        pref[v] = *(const float4*)(Bg + (size_t)(idx >> 5) * HH + (idx & 31) * 4);
    }

    for (int it = 0; it < DD / 32; it++) {
        CPA_WAIT0();
        // stage B from regs (split), layout [d][h] stride 136
        __nv_bfloat16* Bs = dyn + (it & 1) * 13824 + 5120;
        #pragma unroll
        for (int v = 0; v < 4; v++) {
            int idx = v * 256 + t;
            int dr = idx >> 5, hc = (idx & 31) * 4;
            float4 x = pref[v];
            __nv_bfloat16 h0, l0, h1, l1, h2, l2, h3, l3;
            bsplit(x.x, h0, l0); bsplit(x.y, h1, l1);
            bsplit(x.z, h2, l2); bsplit(x.w, h3, l3);
            *(__nv_bfloat162*)(Bs + dr * 136 + hc)            = __nv_bfloat162(h0, h1);
            *(__nv_bfloat162*)(Bs + dr * 136 + hc + 2)        = __nv_bfloat162(h2, h3);
            *(__nv_bfloat162*)(Bs + 4352 + dr * 136 + hc)     = __nv_bfloat162(l0, l1);
            *(__nv_bfloat162*)(Bs + 4352 + dr * 136 + hc + 2) = __nv_bfloat162(l2, l3);
        }
        __syncthreads();
        if (it + 1 < DD / 32) {
            int k0 = (it + 1) * 32;
            uint32_t sbA = sb + ((it + 1) & 1) * 27648;
            CPA16(sbA + srow  * 80 + kc * 2, Ahg + (size_t)srow  * DD + k0 + kc);
            CPA16(sbA + srow2 * 80 + kc * 2, Ahg + (size_t)srow2 * DD + k0 + kc);
            CPA_COMMIT();
            #pragma unroll
            for (int v = 0; v < 4; v++) {
                int idx = v * 256 + t;
                pref[v] = *(const float4*)(Bg + (size_t)(k0 + (idx >> 5)) * HH + (idx & 31) * 4);
            }
        }
        const __nv_bfloat16* cA = dyn + (it & 1) * 13824;
        uint32_t bBh = sb + (it & 1) * 27648 + 10240;
        uint32_t bBl = bBh + 8704;
        #pragma unroll
        for (int kb = 0; kb < 32; kb += 16) {
            LOAD_AFRAGS_H(cA, 40)
            uint32_t bh[4][2], bl[4][2];
            LOAD_BFRAGS_T(bBh, bBl, 136, bh, bl)
            MMA2PASS(acc, bh, bl)
        }
    }

    // epilogue: T[q][h] hi/lo
    #pragma unroll
    for (int i = 0; i < 4; i++) {
        int m = wm * 64 + i * 16 + gr;   // q
        #pragma unroll
        for (int j = 0; j < 4; j++) {
            int n = n0 + wn * 32 + j * 8 + 2 * qp;   // h
            #pragma unroll
            for (int rr = 0; rr < 2; rr++) {
                float a0 = acc[i][j][2 * rr], a1 = acc[i][j][2 * rr + 1];
                __nv_bfloat16 h0, l0, h1, l1;
                bsplit(a0, h0, l0); bsplit(a1, h1, l1);
                size_t o = ((size_t)b * QQ + m + rr * 8) * HH + n;
                *(__nv_bfloat162*)(g_Th + o) = __nv_bfloat162(h0, h1);
                *(__nv_bfloat162*)(g_Tl + o) = __nv_bfloat162(l0, l1);
            }
        }
    }
}

// ---------------- fused GEMM2+4: single-shot K=128 ---------------------------
// acc2 (slices 1,2): 3-pass.  acc4 (slice 3): 2-pass (A hi only).
#define ST24 136
#define TSZ  (128 * ST24)
__global__ __launch_bounds__(256) void gemm24f_mma(
    const float* __restrict__ Ud, float* __restrict__ out) {
    extern __shared__ __nv_bfloat16 dyn[];
    GEMM_IDS
    (void)srow; (void)srow2; (void)kc;
    int b = blockIdx.z, n0 = blockIdx.x * 128, m0 = blockIdx.y * 128;
    const __nv_bfloat16* srcs[6];
    int strides[6];
    srcs[0] = g_P1h  + (size_t)b * DD * QQ + (size_t)m0 * QQ; strides[0] = QQ;
    srcs[1] = g_P1l  + (size_t)b * DD * QQ + (size_t)m0 * QQ; strides[1] = QQ;
    srcs[2] = g_Uqph + (size_t)b * QQ * HH + n0;              strides[2] = HH;
    srcs[3] = g_Uqpl + (size_t)b * QQ * HH + n0;              strides[3] = HH;
    srcs[4] = g_Th   + (size_t)b * QQ * HH + n0;              strides[4] = HH;
    srcs[5] = g_Tl   + (size_t)b * QQ * HH + n0;              strides[5] = HH;

    uint32_t sb = smem_u32(dyn);
    #pragma unroll
    for (int v = 0; v < 8; v++) {
        int c = v * 256 + t;
        int row = c >> 4, kb8 = (c & 15) * 8;
        #pragma unroll
        for (int s = 0; s < 6; s++)
            CPA16(sb + s * (TSZ * 2) + row * (ST24 * 2) + kb8 * 2,
                  srcs[s] + (size_t)row * strides[s] + kb8);
    }
    CPA_COMMIT();
    CPA_WAIT0();
    __syncthreads();

    float acc2[4][4][4], acc4[4][4][4];
    ACC_INIT(acc2)
    ACC_INIT(acc4)
    const __nv_bfloat16* pA = dyn;
    uint32_t b2h = sb + 2 * (TSZ * 2), b2l = sb + 3 * (TSZ * 2);
    uint32_t b4h = sb + 4 * (TSZ * 2), b4l = sb + 5 * (TSZ * 2);
    #pragma unroll
    for (int s = 0; s < 8; s++) {
        int kb = s * 16;
        LOAD_AFRAGS(pA, pA + TSZ, ST24)
        {
            uint32_t bh[4][2], bl[4][2];
            LOAD_BFRAGS_T(b2h, b2l, ST24, bh, bl)
            MMA3PASS(acc2, bh, bl)
        }
        {
            uint32_t bh[4][2], bl[4][2];
            LOAD_BFRAGS_T(b4h, b4l, ST24, bh, bl)
            MMA2PASS(acc4, bh, bl)
        }
    }

    #pragma unroll
    for (int i = 0; i < 4; i++) {
        int m = m0 + wm * 64 + i * 16 + gr;
        #pragma unroll
        for (int j = 0; j < 4; j++) {
            int n = n0 + wn * 32 + j * 8 + 2 * qp;
            #pragma unroll
            for (int rr = 0; rr < 2; rr++) {
                int mm = m + rr * 8;
                float a2x = acc2[i][j][2 * rr], a2y = acc2[i][j][2 * rr + 1];
                float a4x = acc4[i][j][2 * rr], a4y = acc4[i][j][2 * rr + 1];
                float2 u = *(const float2*)(Ud + ((size_t)b * DD + mm) * HH + n);
                float* ob = out + ((size_t)b * DD + mm) * (size_t)(4 * HH) + n;
                *(float2*)(ob)          = u;
                *(float2*)(ob + HH)     = make_float2(a2x, a2y);
                *(float2*)(ob + 2 * HH) = make_float2(u.x * a2x, u.y * a2y);
                *(float2*)(ob + 3 * HH) = make_float2(u.x * a4x, u.y * a4y);
            }
        }
    }
}

// ---------------------------------------------------------------------------
extern "C" void kernel_launch(void* const* d_in, const int* in_sizes, int n_in,
                              void* d_out, int out_size) {
    const float* Ud  = (const float*)d_in[0];
    const float* Uq  = (const float*)d_in[1];
    const float* wcw = (const float*)d_in[2];
    const float* wcb = (const float*)d_in[3];
    const int*   qm  = (const int*)d_in[4];
    const int*   dmk = (const int*)d_in[5];
    float* out = (float*)d_out;

    cudaFuncSetAttribute(gemm1_mma,   cudaFuncAttributeMaxDynamicSharedMemorySize, 81920);
    cudaFuncSetAttribute(gemm3_mma,   cudaFuncAttributeMaxDynamicSharedMemorySize, 55296);
    cudaFuncSetAttribute(gemm24f_mma, cudaFuncAttributeMaxDynamicSharedMemorySize, 208896);

    conv_uq_kernel<<<BB * QQ, 256>>>(Uq, wcw);

    // logits + row softmax + col partials + s_d + F
    gemm1_mma<<<dim3(DD / 128, BB), 256, 81920>>>(Ud, wcw, wcb, qm, dmk);

    // exp-free column softmax -> P2t (hi only)
    softmax_q2d_kernel<<<dim3(QQ / 32, BB), dim3(32, 8)>>>(qm);

    // T = P2^T @ Ud  (2-pass)
    gemm3_mma<<<dim3(HH / 128, BB), 256, 55296>>>(Ud);

    // fused A_d2q (3-pass) + A_q2d (2-pass), all 4 output slices
    gemm24f_mma<<<dim3(HH / 128, DD / 128, BB), 256, 208896>>>(Ud, out);
}

// round 15
// speedup vs baseline: 1.3135x; 1.0837x over previous
#include <cuda_runtime.h>
#include <cuda_bf16.h>
#include <cstdint>

#define BB 16
#define DD 1024
#define QQ 128
#define HH 1024

// ---------------- scratch (device globals) ----------------------------------
__device__ float g_sq[BB * QQ];
__device__ float g_cmax[BB * 8 * 128];
__device__ float g_csum[BB * 8 * 128];
__device__ float g_F   [BB * DD];     // rowSum * exp(rowMax) per (b,d)
__device__ __nv_bfloat16 g_Uqwh[BB * QQ * HH], g_Uqwl[BB * QQ * HH];  // Uq*wdot [b,q,h]
__device__ __nv_bfloat16 g_Uqph[BB * QQ * HH], g_Uqpl[BB * QQ * HH];  // Uq plain [b,q,h]
__device__ __nv_bfloat16 g_P1h [BB * DD * QQ], g_P1l [BB * DD * QQ];  // S_d2q [b,d,q]
__device__ __nv_bfloat16 g_P2th[BB * QQ * DD];                        // S_q2d^T hi [b,q,d]
__device__ __nv_bfloat16 g_Th  [BB * QQ * HH], g_Tl  [BB * QQ * HH];  // T [b,q,h]

// ---------------- helpers ----------------------------------------------------
__device__ __forceinline__ uint32_t smem_u32(const void* p) {
    uint32_t a;
    asm("{ .reg .u64 t; cvta.to.shared.u64 t, %1; cvt.u32.u64 %0, t; }" : "=r"(a) : "l"(p));
    return a;
}
__device__ __forceinline__ uint32_t L32(const __nv_bfloat16* p) {
    return *(const uint32_t*)p;
}
__device__ __forceinline__ void mma_bf16(float* c, const uint32_t* a, const uint32_t* b) {
    asm volatile(
        "mma.sync.aligned.m16n8k16.row.col.f32.bf16.bf16.f32 "
        "{%0,%1,%2,%3}, {%4,%5,%6,%7}, {%8,%9}, {%0,%1,%2,%3};"
        : "+f"(c[0]), "+f"(c[1]), "+f"(c[2]), "+f"(c[3])
        : "r"(a[0]), "r"(a[1]), "r"(a[2]), "r"(a[3]), "r"(b[0]), "r"(b[1]));
}
__device__ __forceinline__ void ldmx4t(uint32_t& r0, uint32_t& r1,
                                       uint32_t& r2, uint32_t& r3, uint32_t a) {
    asm volatile("ldmatrix.sync.aligned.m8n8.x4.trans.shared.b16 {%0,%1,%2,%3}, [%4];"
        : "=r"(r0), "=r"(r1), "=r"(r2), "=r"(r3) : "r"(a));
}
__device__ __forceinline__ void bsplit(float x, __nv_bfloat16& h, __nv_bfloat16& l) {
    h = __float2bfloat16(x);
    l = __float2bfloat16(x - __bfloat162float(h));
}
#define CPA16(sa, g) \
    asm volatile("cp.async.cg.shared.global [%0], [%1], 16;" :: "r"(sa), "l"(g))
#define CPA_COMMIT() asm volatile("cp.async.commit_group;" ::: "memory")
#define CPA_WAIT0()  asm volatile("cp.async.wait_group 0;" ::: "memory")

// A fragments (hi+lo), K-contiguous layout, stride ST elems
#define LOAD_AFRAGS(sAh, sAl, ST)                                             \
    uint32_t ah[4][4], al[4][4];                                              \
    _Pragma("unroll")                                                         \
    for (int i = 0; i < 4; i++) {                                             \
        int r = wm * 64 + i * 16 + gr;                                        \
        const __nv_bfloat16* p = (sAh) + r * (ST) + kb + 2 * qp;              \
        const __nv_bfloat16* q = (sAl) + r * (ST) + kb + 2 * qp;              \
        ah[i][0] = L32(p);            ah[i][1] = L32(p + 8 * (ST));           \
        ah[i][2] = L32(p + 8);        ah[i][3] = L32(p + 8 * (ST) + 8);       \
        al[i][0] = L32(q);            al[i][1] = L32(q + 8 * (ST));           \
        al[i][2] = L32(q + 8);        al[i][3] = L32(q + 8 * (ST) + 8);       \
    }

// A fragments (hi only)
#define LOAD_AFRAGS_H(sAh, ST)                                                \
    uint32_t ah[4][4];                                                        \
    _Pragma("unroll")                                                         \
    for (int i = 0; i < 4; i++) {                                             \
        int r = wm * 64 + i * 16 + gr;                                        \
        const __nv_bfloat16* p = (sAh) + r * (ST) + kb + 2 * qp;              \
        ah[i][0] = L32(p);            ah[i][1] = L32(p + 8 * (ST));           \
        ah[i][2] = L32(p + 8);        ah[i][3] = L32(p + 8 * (ST) + 8);       \
    }

#define MMA3PASS(ACC, BH, BL)                                                 \
    _Pragma("unroll")                                                         \
    for (int i = 0; i < 4; i++)                                               \
        _Pragma("unroll")                                                     \
        for (int j = 0; j < 4; j++) mma_bf16((ACC)[i][j], ah[i], (BH)[j]);    \
    _Pragma("unroll")                                                         \
    for (int i = 0; i < 4; i++)                                               \
        _Pragma("unroll")                                                     \
        for (int j = 0; j < 4; j++) mma_bf16((ACC)[i][j], ah[i], (BL)[j]);    \
    _Pragma("unroll")                                                         \
    for (int i = 0; i < 4; i++)                                               \
        _Pragma("unroll")                                                     \
        for (int j = 0; j < 4; j++) mma_bf16((ACC)[i][j], al[i], (BH)[j]);

// 2-pass variant: bf16(A hi) x full-precision B
#define MMA2PASS(ACC, BH, BL)                                                 \
    _Pragma("unroll")                                                         \
    for (int i = 0; i < 4; i++)                                               \
        _Pragma("unroll")                                                     \
        for (int j = 0; j < 4; j++) mma_bf16((ACC)[i][j], ah[i], (BH)[j]);    \
    _Pragma("unroll")                                                         \
    for (int i = 0; i < 4; i++)                                               \
        _Pragma("unroll")                                                     \
        for (int j = 0; j < 4; j++) mma_bf16((ACC)[i][j], ah[i], (BL)[j]);

#define LOAD_BFRAGS_K(sBh, sBl, ST, BH, BL)                                   \
    _Pragma("unroll")                                                         \
    for (int j = 0; j < 4; j++) {                                             \
        int c = wn * 32 + j * 8 + gr;                                         \
        const __nv_bfloat16* p = (sBh) + c * (ST) + kb + 2 * qp;              \
        const __nv_bfloat16* q = (sBl) + c * (ST) + kb + 2 * qp;              \
        BH[j][0] = L32(p); BH[j][1] = L32(p + 8);                             \
        BL[j][0] = L32(q); BL[j][1] = L32(q + 8);                             \
    }

#define LOAD_BFRAGS_T(bBh, bBl, STB, BH, BL)                                  \
    _Pragma("unroll")                                                         \
    for (int jj = 0; jj < 2; jj++) {                                          \
        int c0 = wn * 32 + jj * 16;                                           \
        uint32_t off = (uint32_t)(((kb + (lane & 15)) * (STB) + c0 +          \
                                   ((lane >> 4) * 8)) * 2);                   \
        ldmx4t(BH[2*jj][0], BH[2*jj][1], BH[2*jj+1][0], BH[2*jj+1][1], (bBh) + off); \
        ldmx4t(BL[2*jj][0], BL[2*jj][1], BL[2*jj+1][0], BL[2*jj+1][1], (bBl) + off); \
    }

#define GEMM_IDS                                                              \
    int t = threadIdx.x;                                                      \
    int wid = t >> 5, lane = t & 31;                                          \
    int wm = wid >> 2, wn = wid & 3;                                          \
    int gr = lane >> 2, qp = lane & 3;                                        \
    int srow = t >> 2, srow2 = (t >> 2) + 64, kc = (t & 3) * 8;

#define ACC_INIT(A)                                                           \
    _Pragma("unroll")                                                         \
    for (int i = 0; i < 4; i++)                                               \
        _Pragma("unroll")                                                     \
        for (int j = 0; j < 4; j++)                                           \
            _Pragma("unroll")                                                 \
            for (int e = 0; e < 4; e++) (A)[i][j][e] = 0.f;

// ---------------- conv_uq ----------------------------------------------------
__global__ void conv_uq_kernel(const float* __restrict__ Uq,
                               const float* __restrict__ wcw) {
    __shared__ float red[8];
    int row = blockIdx.x;
    int t = threadIdx.x;
    const float* src = Uq + (size_t)row * HH;
    float4 v = *(const float4*)(src + t * 4);
    float4 wd = *(const float4*)(wcw + 2 * HH + t * 4);
    float4 wq = *(const float4*)(wcw + HH + t * 4);
    __nv_bfloat16 h0, l0, h1, l1, h2, l2, h3, l3;
    bsplit(v.x, h0, l0); bsplit(v.y, h1, l1);
    bsplit(v.z, h2, l2); bsplit(v.w, h3, l3);
    size_t o = (size_t)row * HH + t * 4;
    *(__nv_bfloat162*)(g_Uqph + o)     = __nv_bfloat162(h0, h1);
    *(__nv_bfloat162*)(g_Uqph + o + 2) = __nv_bfloat162(h2, h3);
    *(__nv_bfloat162*)(g_Uqpl + o)     = __nv_bfloat162(l0, l1);
    *(__nv_bfloat162*)(g_Uqpl + o + 2) = __nv_bfloat162(l2, l3);
    float4 s = make_float4(v.x * wd.x, v.y * wd.y, v.z * wd.z, v.w * wd.w);
    bsplit(s.x, h0, l0); bsplit(s.y, h1, l1);
    bsplit(s.z, h2, l2); bsplit(s.w, h3, l3);
    *(__nv_bfloat162*)(g_Uqwh + o)     = __nv_bfloat162(h0, h1);
    *(__nv_bfloat162*)(g_Uqwh + o + 2) = __nv_bfloat162(h2, h3);
    *(__nv_bfloat162*)(g_Uqwl + o)     = __nv_bfloat162(l0, l1);
    *(__nv_bfloat162*)(g_Uqwl + o + 2) = __nv_bfloat162(l2, l3);
    float p = v.x * wq.x + v.y * wq.y + v.z * wq.z + v.w * wq.w;
    #pragma unroll
    for (int off = 16; off; off >>= 1) p += __shfl_xor_sync(0xffffffffu, p, off);
    if ((t & 31) == 0) red[t >> 5] = p;
    __syncthreads();
    if (t == 0) {
        float sum = 0.f;
        #pragma unroll
        for (int j = 0; j < 8; j++) sum += red[j];
        g_sq[row] = sum;
    }
}

// ---------------- GEMM1 fused: P1, col partials, s_d, F (no S store) ---------
__global__ __launch_bounds__(256) void gemm1_mma(
    const float* __restrict__ Ud, const float* __restrict__ wcw,
    const float* __restrict__ wcb,
    const int* __restrict__ qm, const int* __restrict__ dmk) {
    extern __shared__ __nv_bfloat16 dyn[];
    __shared__ float redM[128][4], redS[128][4];
    __shared__ float2 colp[2][128];
    __shared__ int s_qm[128];
    __shared__ float s_sdv[128];
    __shared__ float s_wd[HH];
    GEMM_IDS
    int b = blockIdx.y, m0 = blockIdx.x * 128;
    const float* A = Ud + (size_t)b * DD * HH + (size_t)m0 * HH;
    const __nv_bfloat16* Bh = g_Uqwh + (size_t)b * QQ * HH;
    const __nv_bfloat16* Bl = g_Uqwl + (size_t)b * QQ * HH;
    float acc[4][4][4];
    ACC_INIT(acc)
    float sdp[4] = {0.f, 0.f, 0.f, 0.f};
    if (t < 128) s_qm[t] = qm[b * QQ + t];
    #pragma unroll
    for (int i = t; i < HH; i += 256) s_wd[i] = wcw[i];
    uint32_t sbB0 = smem_u32(dyn) + 40960;

    float4 pref[4];
    #pragma unroll
    for (int v = 0; v < 4; v++) {
        int idx = v * 256 + t;
        pref[v] = *(const float4*)(A + (size_t)(idx >> 3) * HH + (idx & 7) * 4);
    }
    CPA16(sbB0 +         srow  * 80 + kc * 2, Bh + (size_t)srow  * HH + kc);
    CPA16(sbB0 +         srow2 * 80 + kc * 2, Bh + (size_t)srow2 * HH + kc);
    CPA16(sbB0 + 10240 + srow  * 80 + kc * 2, Bl + (size_t)srow  * HH + kc);
    CPA16(sbB0 + 10240 + srow2 * 80 + kc * 2, Bl + (size_t)srow2 * HH + kc);
    CPA_COMMIT();
    __syncthreads();   // s_wd ready

    for (int it = 0; it < HH / 32; it++) {
        CPA_WAIT0();
        __nv_bfloat16* As = dyn + (it & 1) * 10240;
        #pragma unroll
        for (int v = 0; v < 4; v++) {
            int idx = v * 256 + t;
            int row = idx >> 3, cs = (idx & 7) * 4;
            float4 x = pref[v];
            float4 w = *(const float4*)(s_wd + it * 32 + cs);
            sdp[v] += x.x * w.x + x.y * w.y + x.z * w.z + x.w * w.w;
            __nv_bfloat16 h0, l0, h1, l1, h2, l2, h3, l3;
            bsplit(x.x, h0, l0); bsplit(x.y, h1, l1);
            bsplit(x.z, h2, l2); bsplit(x.w, h3, l3);
            *(__nv_bfloat162*)(As + row * 40 + cs)            = __nv_bfloat162(h0, h1);
            *(__nv_bfloat162*)(As + row * 40 + cs + 2)        = __nv_bfloat162(h2, h3);
            *(__nv_bfloat162*)(As + 5120 + row * 40 + cs)     = __nv_bfloat162(l0, l1);
            *(__nv_bfloat162*)(As + 5120 + row * 40 + cs + 2) = __nv_bfloat162(l2, l3);
        }
        __syncthreads();
        if (it + 1 < HH / 32) {
            int k0 = (it + 1) * 32;
            uint32_t sbB = sbB0 + ((it + 1) & 1) * 20480;
            CPA16(sbB +         srow  * 80 + kc * 2, Bh + (size_t)srow  * HH + k0 + kc);
            CPA16(sbB +         srow2 * 80 + kc * 2, Bh + (size_t)srow2 * HH + k0 + kc);
            CPA16(sbB + 10240 + srow  * 80 + kc * 2, Bl + (size_t)srow  * HH + k0 + kc);
            CPA16(sbB + 10240 + srow2 * 80 + kc * 2, Bl + (size_t)srow2 * HH + k0 + kc);
            CPA_COMMIT();
            #pragma unroll
            for (int v = 0; v < 4; v++) {
                int idx = v * 256 + t;
                pref[v] = *(const float4*)(A + (size_t)(idx >> 3) * HH + k0 + (idx & 7) * 4);
            }
        }
        const __nv_bfloat16* cA = dyn + (it & 1) * 10240;
        const __nv_bfloat16* cB = dyn + 20480 + (it & 1) * 10240;
        #pragma unroll
        for (int kb = 0; kb < 32; kb += 16) {
            LOAD_AFRAGS(cA, cA + 5120, 40)
            uint32_t bh[4][2], bl[4][2];
            LOAD_BFRAGS_K(cB, cB + 5120, 40, bh, bl)
            MMA3PASS(acc, bh, bl)
        }
    }

    // s_d reduce (8 lanes share a row)
    #pragma unroll
    for (int v = 0; v < 4; v++) {
        float s = sdp[v];
        s += __shfl_xor_sync(0xffffffffu, s, 1);
        s += __shfl_xor_sync(0xffffffffu, s, 2);
        s += __shfl_xor_sync(0xffffffffu, s, 4);
        if ((lane & 7) == 0) s_sdv[v * 32 + (t >> 3)] = s;
    }

    float bias = wcb[0];
    int dmv[4][2];
    #pragma unroll
    for (int i = 0; i < 4; i++)
        #pragma unroll
        for (int rr = 0; rr < 2; rr++)
            dmv[i][rr] = dmk[b * DD + m0 + wm * 64 + i * 16 + rr * 8 + gr];
    __syncthreads();
    float sdv[4][2];
    #pragma unroll
    for (int i = 0; i < 4; i++)
        #pragma unroll
        for (int rr = 0; rr < 2; rr++)
            sdv[i][rr] = s_sdv[wm * 64 + i * 16 + rr * 8 + gr] + bias;

    #pragma unroll
    for (int i = 0; i < 4; i++)
        #pragma unroll
        for (int j = 0; j < 4; j++) {
            int n = wn * 32 + j * 8 + 2 * qp;
            float sq0 = g_sq[b * QQ + n], sq1 = g_sq[b * QQ + n + 1];
            int q0 = s_qm[n] > 0, q1 = s_qm[n + 1] > 0;
            #pragma unroll
            for (int rr = 0; rr < 2; rr++) {
                float s0 = acc[i][j][2 * rr]     + sdv[i][rr] + sq0;
                float s1 = acc[i][j][2 * rr + 1] + sdv[i][rr] + sq1;
                int dm = dmv[i][rr] > 0;
                acc[i][j][2 * rr]     = (dm && q0) ? s0 : -1e30f;
                acc[i][j][2 * rr + 1] = (dm && q1) ? s1 : -1e30f;
            }
        }

    // row softmax max
    float M[4][2];
    #pragma unroll
    for (int i = 0; i < 4; i++)
        #pragma unroll
        for (int rr = 0; rr < 2; rr++) {
            float mx = -1e30f;
            #pragma unroll
            for (int j = 0; j < 4; j++)
                mx = fmaxf(mx, fmaxf(acc[i][j][2 * rr], acc[i][j][2 * rr + 1]));
            mx = fmaxf(mx, __shfl_xor_sync(0xffffffffu, mx, 1));
            mx = fmaxf(mx, __shfl_xor_sync(0xffffffffu, mx, 2));
            if (qp == 0) redM[wm * 64 + i * 16 + rr * 8 + gr][wn] = mx;
        }
    __syncthreads();
    #pragma unroll
    for (int i = 0; i < 4; i++)
        #pragma unroll
        for (int rr = 0; rr < 2; rr++) {
            int r = wm * 64 + i * 16 + rr * 8 + gr;
            M[i][rr] = fmaxf(fmaxf(redM[r][0], redM[r][1]),
                             fmaxf(redM[r][2], redM[r][3]));
        }
    // row softmax sum
    float inv[4][2];
    #pragma unroll
    for (int i = 0; i < 4; i++)
        #pragma unroll
        for (int rr = 0; rr < 2; rr++) {
            float s = 0.f;
            #pragma unroll
            for (int j = 0; j < 4; j++) {
                s += __expf(acc[i][j][2 * rr]     - M[i][rr]);
                s += __expf(acc[i][j][2 * rr + 1] - M[i][rr]);
            }
            s += __shfl_xor_sync(0xffffffffu, s, 1);
            s += __shfl_xor_sync(0xffffffffu, s, 2);
            if (qp == 0) redS[wm * 64 + i * 16 + rr * 8 + gr][wn] = s;
        }
    __syncthreads();
    #pragma unroll
    for (int i = 0; i < 4; i++)
        #pragma unroll
        for (int rr = 0; rr < 2; rr++) {
            int r = wm * 64 + i * 16 + rr * 8 + gr;
            float tot = redS[r][0] + redS[r][1] + redS[r][2] + redS[r][3];
            inv[i][rr] = 1.f / tot;
            if (qp == 0 && wn == 0)
                g_F[b * DD + m0 + r] = tot * __expf(M[i][rr]);
        }
    // P1 write
    #pragma unroll
    for (int i = 0; i < 4; i++)
        #pragma unroll
        for (int j = 0; j < 4; j++) {
            int n = wn * 32 + j * 8 + 2 * qp;
            int q0 = s_qm[n] > 0, q1 = s_qm[n + 1] > 0;
            #pragma unroll
            for (int rr = 0; rr < 2; rr++) {
                int m = m0 + wm * 64 + i * 16 + rr * 8 + gr;
                int dm = dmv[i][rr] > 0;
                float p0 = (dm && q0) ? __expf(acc[i][j][2 * rr]     - M[i][rr]) * inv[i][rr] : 0.f;
                float p1 = (dm && q1) ? __expf(acc[i][j][2 * rr + 1] - M[i][rr]) * inv[i][rr] : 0.f;
                __nv_bfloat16 h0, l0, h1, l1;
                bsplit(p0, h0, l0); bsplit(p1, h1, l1);
                size_t o = ((size_t)b * DD + m) * QQ + n;
                *(__nv_bfloat162*)(g_P1h + o) = __nv_bfloat162(h0, h1);
                *(__nv_bfloat162*)(g_P1l + o) = __nv_bfloat162(l0, l1);
            }
        }
    // column partials
    #pragma unroll
    for (int j = 0; j < 4; j++)
        #pragma unroll
        for (int cc = 0; cc < 2; cc++) {
            float cm = -1e30f;
            #pragma unroll
            for (int i = 0; i < 4; i++)
                #pragma unroll
                for (int rr = 0; rr < 2; rr++)
                    cm = fmaxf(cm, acc[i][j][2 * rr + cc]);
            float cs = 0.f;
            #pragma unroll
            for (int i = 0; i < 4; i++)
                #pragma unroll
                for (int rr = 0; rr < 2; rr++)
                    cs += __expf(acc[i][j][2 * rr + cc] - cm);
            #pragma unroll
            for (int o = 4; o <= 16; o <<= 1) {
                float om = __shfl_xor_sync(0xffffffffu, cm, o);
                float os = __shfl_xor_sync(0xffffffffu, cs, o);
                float nm = fmaxf(cm, om);
                cs = cs * __expf(cm - nm) + os * __expf(om - nm);
                cm = nm;
            }
            if (gr == 0) colp[wm][wn * 32 + j * 8 + 2 * qp + cc] = make_float2(cm, cs);
        }
    __syncthreads();
    if (t < 128) {
        float2 a = colp[0][t], c = colp[1][t];
        float nm = fmaxf(a.x, c.x);
        float s = a.y * __expf(a.x - nm) + c.y * __expf(c.x - nm);
        int idx = (b * 8 + blockIdx.x) * 128 + t;
        g_cmax[idx] = nm; g_csum[idx] = s;
    }
}

// ---------------- exp-free q2d: P2t[q,d] = P1[d,q] * F[d] * G[q] -------------
__global__ void softmax_q2d_kernel(const int* __restrict__ qm) {
    __shared__ float sG[32], sF[32];
    __shared__ float tile[32][33];
    int b = blockIdx.y;
    int tx = threadIdx.x, ty = threadIdx.y;
    int tid = ty * 32 + tx;
    if (tid < 32) {
        int qq = blockIdx.x * 32 + tid;
        float m = -1e30f, s = 0.f;
        #pragma unroll
        for (int k = 0; k < 8; k++) {
            float mk = g_cmax[(b * 8 + k) * 128 + qq];
            float sk = g_csum[(b * 8 + k) * 128 + qq];
            float nm = fmaxf(m, mk);
            s = s * __expf(m - nm) + sk * __expf(mk - nm);
            m = nm;
        }
        float G = 0.f;
        if (qm[b * QQ + qq] > 0 && m > -1e29f && s > 0.f)
            G = __expf(-m) / s;
        sG[tid] = G;
    }
    __syncthreads();
    int qr = tid >> 3, seg = (tid & 7) * 4;
    float Gq = sG[qr];
    size_t drow = (size_t)b * QQ * DD + (size_t)(blockIdx.x * 32 + qr) * DD;
    for (int d0 = 0; d0 < DD; d0 += 32) {
        if (tid < 32) sF[tid] = g_F[b * DD + d0 + tid];
        __syncthreads();
        #pragma unroll
        for (int dj = ty; dj < 32; dj += 8) {
            int d = d0 + dj;
            size_t o = ((size_t)b * DD + d) * QQ + blockIdx.x * 32 + tx;
            float v = (__bfloat162float(g_P1h[o]) + __bfloat162float(g_P1l[o])) * sF[dj];
            tile[tx][dj] = v;
        }
        __syncthreads();
        float p0 = tile[qr][seg]     * Gq, p1 = tile[qr][seg + 1] * Gq;
        float p2 = tile[qr][seg + 2] * Gq, p3 = tile[qr][seg + 3] * Gq;
        __nv_bfloat16 h0 = __float2bfloat16(p0), h1 = __float2bfloat16(p1);
        __nv_bfloat16 h2 = __float2bfloat16(p2), h3 = __float2bfloat16(p3);
        size_t o = drow + d0 + seg;
        *(__nv_bfloat162*)(g_P2th + o)     = __nv_bfloat162(h0, h1);
        *(__nv_bfloat162*)(g_P2th + o + 2) = __nv_bfloat162(h2, h3);
        __syncthreads();
    }
}

// ---------------- GEMM3 (2-pass): T[q,h] = sum_d P2h[q,d] * Ud[d,h] ----------
__global__ __launch_bounds__(256) void gemm3_mma(const float* __restrict__ Ud) {
    extern __shared__ __nv_bfloat16 dyn[];
    GEMM_IDS
    int b = blockIdx.y, n0 = blockIdx.x * 128;
    const __nv_bfloat16* Ahg = g_P2th + (size_t)b * QQ * DD;
    const float* Bg = Ud + (size_t)b * DD * HH + n0;
    float acc[4][4][4];
    ACC_INIT(acc)
    uint32_t sb = smem_u32(dyn);

    CPA16(sb + srow  * 80 + kc * 2, Ahg + (size_t)srow  * DD + kc);
    CPA16(sb + srow2 * 80 + kc * 2, Ahg + (size_t)srow2 * DD + kc);
    CPA_COMMIT();
    float4 pref[4];
    #pragma unroll
    for (int v = 0; v < 4; v++) {
        int idx = v * 256 + t;
        pref[v] = *(const float4*)(Bg + (size_t)(idx >> 5) * HH + (idx & 31) * 4);
    }

    for (int it = 0; it < DD / 32; it++) {
        CPA_WAIT0();
        __nv_bfloat16* Bs = dyn + (it & 1) * 13824 + 5120;
        #pragma unroll
        for (int v = 0; v < 4; v++) {
            int idx = v * 256 + t;
            int dr = idx >> 5, hc = (idx & 31) * 4;
            float4 x = pref[v];
            __nv_bfloat16 h0, l0, h1, l1, h2, l2, h3, l3;
            bsplit(x.x, h0, l0); bsplit(x.y, h1, l1);
            bsplit(x.z, h2, l2); bsplit(x.w, h3, l3);
            *(__nv_bfloat162*)(Bs + dr * 136 + hc)            = __nv_bfloat162(h0, h1);
            *(__nv_bfloat162*)(Bs + dr * 136 + hc + 2)        = __nv_bfloat162(h2, h3);
            *(__nv_bfloat162*)(Bs + 4352 + dr * 136 + hc)     = __nv_bfloat162(l0, l1);
            *(__nv_bfloat162*)(Bs + 4352 + dr * 136 + hc + 2) = __nv_bfloat162(l2, l3);
        }
        __syncthreads();
        if (it + 1 < DD / 32) {
            int k0 = (it + 1) * 32;
            uint32_t sbA = sb + ((it + 1) & 1) * 27648;
            CPA16(sbA + srow  * 80 + kc * 2, Ahg + (size_t)srow  * DD + k0 + kc);
            CPA16(sbA + srow2 * 80 + kc * 2, Ahg + (size_t)srow2 * DD + k0 + kc);
            CPA_COMMIT();
            #pragma unroll
            for (int v = 0; v < 4; v++) {
                int idx = v * 256 + t;
                pref[v] = *(const float4*)(Bg + (size_t)(k0 + (idx >> 5)) * HH + (idx & 31) * 4);
            }
        }
        const __nv_bfloat16* cA = dyn + (it & 1) * 13824;
        uint32_t bBh = sb + (it & 1) * 27648 + 10240;
        uint32_t bBl = bBh + 8704;
        #pragma unroll
        for (int kb = 0; kb < 32; kb += 16) {
            LOAD_AFRAGS_H(cA, 40)
            uint32_t bh[4][2], bl[4][2];
            LOAD_BFRAGS_T(bBh, bBl, 136, bh, bl)
            MMA2PASS(acc, bh, bl)
        }
    }

    #pragma unroll
    for (int i = 0; i < 4; i++) {
        int m = wm * 64 + i * 16 + gr;
        #pragma unroll
        for (int j = 0; j < 4; j++) {
            int n = n0 + wn * 32 + j * 8 + 2 * qp;
            #pragma unroll
            for (int rr = 0; rr < 2; rr++) {
                float a0 = acc[i][j][2 * rr], a1 = acc[i][j][2 * rr + 1];
                __nv_bfloat16 h0, l0, h1, l1;
                bsplit(a0, h0, l0); bsplit(a1, h1, l1);
                size_t o = ((size_t)b * QQ + m + rr * 8) * HH + n;
                *(__nv_bfloat162*)(g_Th + o) = __nv_bfloat162(h0, h1);
                *(__nv_bfloat162*)(g_Tl + o) = __nv_bfloat162(l0, l1);
            }
        }
    }
}

// ---------------- fused GEMM2+4: all 2-pass, 5 smem tiles --------------------
#define ST24 136
#define TSZ  (128 * ST24)
__global__ __launch_bounds__(256) void gemm24f_mma(
    const float* __restrict__ Ud, float* __restrict__ out) {
    extern __shared__ __nv_bfloat16 dyn[];
    GEMM_IDS
    (void)srow; (void)srow2; (void)kc;
    int b = blockIdx.z, n0 = blockIdx.x * 128, m0 = blockIdx.y * 128;
    const __nv_bfloat16* srcs[5];
    int strides[5];
    srcs[0] = g_P1h  + (size_t)b * DD * QQ + (size_t)m0 * QQ; strides[0] = QQ;
    srcs[1] = g_Uqph + (size_t)b * QQ * HH + n0;              strides[1] = HH;
    srcs[2] = g_Uqpl + (size_t)b * QQ * HH + n0;              strides[2] = HH;
    srcs[3] = g_Th   + (size_t)b * QQ * HH + n0;              strides[3] = HH;
    srcs[4] = g_Tl   + (size_t)b * QQ * HH + n0;              strides[4] = HH;

    uint32_t sb = smem_u32(dyn);
    #pragma unroll
    for (int v = 0; v < 8; v++) {
        int c = v * 256 + t;
        int row = c >> 4, kb8 = (c & 15) * 8;
        #pragma unroll
        for (int s = 0; s < 5; s++)
            CPA16(sb + s * (TSZ * 2) + row * (ST24 * 2) + kb8 * 2,
                  srcs[s] + (size_t)row * strides[s] + kb8);
    }
    CPA_COMMIT();
    CPA_WAIT0();
    __syncthreads();

    float acc2[4][4][4], acc4[4][4][4];
    ACC_INIT(acc2)
    ACC_INIT(acc4)
    const __nv_bfloat16* pA = dyn;
    uint32_t b2h = sb + 1 * (TSZ * 2), b2l = sb + 2 * (TSZ * 2);
    uint32_t b4h = sb + 3 * (TSZ * 2), b4l = sb + 4 * (TSZ * 2);
    #pragma unroll
    for (int s = 0; s < 8; s++) {
        int kb = s * 16;
        LOAD_AFRAGS_H(pA, ST24)
        {
            uint32_t bh[4][2], bl[4][2];
            LOAD_BFRAGS_T(b2h, b2l, ST24, bh, bl)
            MMA2PASS(acc2, bh, bl)
        }
        {
            uint32_t bh[4][2], bl[4][2];
            LOAD_BFRAGS_T(b4h, b4l, ST24, bh, bl)
            MMA2PASS(acc4, bh, bl)
        }
    }

    #pragma unroll
    for (int i = 0; i < 4; i++) {
        int m = m0 + wm * 64 + i * 16 + gr;
        #pragma unroll
        for (int j = 0; j < 4; j++) {
            int n = n0 + wn * 32 + j * 8 + 2 * qp;
            #pragma unroll
            for (int rr = 0; rr < 2; rr++) {
                int mm = m + rr * 8;
                float a2x = acc2[i][j][2 * rr], a2y = acc2[i][j][2 * rr + 1];
                float a4x = acc4[i][j][2 * rr], a4y = acc4[i][j][2 * rr + 1];
                float2 u = *(const float2*)(Ud + ((size_t)b * DD + mm) * HH + n);
                float* ob = out + ((size_t)b * DD + mm) * (size_t)(4 * HH) + n;
                *(float2*)(ob)          = u;
                *(float2*)(ob + HH)     = make_float2(a2x, a2y);
                *(float2*)(ob + 2 * HH) = make_float2(u.x * a2x, u.y * a2y);
                *(float2*)(ob + 3 * HH) = make_float2(u.x * a4x, u.y * a4y);
            }
        }
    }
}

// ---------------------------------------------------------------------------
extern "C" void kernel_launch(void* const* d_in, const int* in_sizes, int n_in,
                              void* d_out, int out_size) {
    const float* Ud  = (const float*)d_in[0];
    const float* Uq  = (const float*)d_in[1];
    const float* wcw = (const float*)d_in[2];
    const float* wcb = (const float*)d_in[3];
    const int*   qm  = (const int*)d_in[4];
    const int*   dmk = (const int*)d_in[5];
    float* out = (float*)d_out;

    cudaFuncSetAttribute(gemm1_mma,   cudaFuncAttributeMaxDynamicSharedMemorySize, 81920);
    cudaFuncSetAttribute(gemm3_mma,   cudaFuncAttributeMaxDynamicSharedMemorySize, 55296);
    cudaFuncSetAttribute(gemm24f_mma, cudaFuncAttributeMaxDynamicSharedMemorySize, 174080);

    conv_uq_kernel<<<BB * QQ, 256>>>(Uq, wcw);

    // logits + row softmax + col partials + s_d + F (no S materialization)
    gemm1_mma<<<dim3(DD / 128, BB), 256, 81920>>>(Ud, wcw, wcb, qm, dmk);

    // exp-free column softmax -> P2t (hi only)
    softmax_q2d_kernel<<<dim3(QQ / 32, BB), dim3(32, 8)>>>(qm);

    // T = P2^T @ Ud  (2-pass)
    gemm3_mma<<<dim3(HH / 128, BB), 256, 55296>>>(Ud);

    // fused A_d2q + A_q2d (both 2-pass), all 4 output slices
    gemm24f_mma<<<dim3(HH / 128, DD / 128, BB), 256, 174080>>>(Ud, out);
}

// round 17
// speedup vs baseline: 1.6140x; 1.2287x over previous
#include <cuda_runtime.h>
#include <cuda_bf16.h>
#include <cstdint>

#define BB 16
#define DD 1024
#define QQ 128
#define HH 1024

// ---------------- scratch (device globals) ----------------------------------
__device__ float g_sq[BB * QQ];
__device__ float g_cmax[BB * 8 * 128];
__device__ float g_csum[BB * 8 * 128];
__device__ __nv_bfloat16 g_Uqwh[BB * QQ * HH], g_Uqwl[BB * QQ * HH];  // Uq*wdot [b,q,h]
__device__ __nv_bfloat16 g_Uqph[BB * QQ * HH], g_Uqpl[BB * QQ * HH];  // Uq plain [b,q,h]
__device__ __nv_bfloat16 g_P1h [BB * DD * QQ];                        // S_d2q [b,d,q]
__device__ __nv_bfloat16 g_P1Fh[BB * DD * QQ];                        // exp(S) = P1*F [b,d,q]
__device__ __nv_bfloat16 g_Th  [BB * QQ * HH], g_Tl  [BB * QQ * HH];  // T [b,q,h]

// ---------------- helpers ----------------------------------------------------
__device__ __forceinline__ uint32_t smem_u32(const void* p) {
    uint32_t a;
    asm("{ .reg .u64 t; cvta.to.shared.u64 t, %1; cvt.u32.u64 %0, t; }" : "=r"(a) : "l"(p));
    return a;
}
__device__ __forceinline__ uint32_t L32(const __nv_bfloat16* p) {
    return *(const uint32_t*)p;
}
__device__ __forceinline__ void mma_bf16(float* c, const uint32_t* a, const uint32_t* b) {
    asm volatile(
        "mma.sync.aligned.m16n8k16.row.col.f32.bf16.bf16.f32 "
        "{%0,%1,%2,%3}, {%4,%5,%6,%7}, {%8,%9}, {%0,%1,%2,%3};"
        : "+f"(c[0]), "+f"(c[1]), "+f"(c[2]), "+f"(c[3])
        : "r"(a[0]), "r"(a[1]), "r"(a[2]), "r"(a[3]), "r"(b[0]), "r"(b[1]));
}
__device__ __forceinline__ void ldmx4t(uint32_t& r0, uint32_t& r1,
                                       uint32_t& r2, uint32_t& r3, uint32_t a) {
    asm volatile("ldmatrix.sync.aligned.m8n8.x4.trans.shared.b16 {%0,%1,%2,%3}, [%4];"
        : "=r"(r0), "=r"(r1), "=r"(r2), "=r"(r3) : "r"(a));
}
__device__ __forceinline__ void bsplit(float x, __nv_bfloat16& h, __nv_bfloat16& l) {
    h = __float2bfloat16(x);
    l = __float2bfloat16(x - __bfloat162float(h));
}
#define CPA16(sa, g) \
    asm volatile("cp.async.cg.shared.global [%0], [%1], 16;" :: "r"(sa), "l"(g))
#define CPA_COMMIT() asm volatile("cp.async.commit_group;" ::: "memory")
#define CPA_WAIT0()  asm volatile("cp.async.wait_group 0;" ::: "memory")

// A fragments (hi+lo), K-contiguous layout (A row-major [m][k]), stride ST
#define LOAD_AFRAGS(sAh, sAl, ST)                                             \
    uint32_t ah[4][4], al[4][4];                                              \
    _Pragma("unroll")                                                         \
    for (int i = 0; i < 4; i++) {                                             \
        int r = wm * 64 + i * 16 + gr;                                        \
        const __nv_bfloat16* p = (sAh) + r * (ST) + kb + 2 * qp;              \
        const __nv_bfloat16* q = (sAl) + r * (ST) + kb + 2 * qp;              \
        ah[i][0] = L32(p);            ah[i][1] = L32(p + 8 * (ST));           \
        ah[i][2] = L32(p + 8);        ah[i][3] = L32(p + 8 * (ST) + 8);       \
        al[i][0] = L32(q);            al[i][1] = L32(q + 8 * (ST));           \
        al[i][2] = L32(q + 8);        al[i][3] = L32(q + 8 * (ST) + 8);       \
    }

// A fragments (hi only), row-major [m][k]
#define LOAD_AFRAGS_H(sAh, ST)                                                \
    uint32_t ah[4][4];                                                        \
    _Pragma("unroll")                                                         \
    for (int i = 0; i < 4; i++) {                                             \
        int r = wm * 64 + i * 16 + gr;                                        \
        const __nv_bfloat16* p = (sAh) + r * (ST) + kb + 2 * qp;              \
        ah[i][0] = L32(p);            ah[i][1] = L32(p + 8 * (ST));           \
        ah[i][2] = L32(p + 8);        ah[i][3] = L32(p + 8 * (ST) + 8);       \
    }

// A fragments (hi only) from [k][m] layout via ldmatrix.trans; STB elems
// tiles: t0 (m, k) t1 (m+8, k) t2 (m, k+8) t3 (m+8, k+8)
#define LOAD_AFRAGS_T(bA, STB)                                                \
    uint32_t ah[4][4];                                                        \
    _Pragma("unroll")                                                         \
    for (int i = 0; i < 4; i++) {                                             \
        int mcol = wm * 64 + i * 16 + (((lane >> 3) & 1) << 3);               \
        int kk = kb + (lane & 7) + ((lane >> 4) << 3);                        \
        uint32_t off = (uint32_t)((kk * (STB) + mcol) * 2);                   \
        ldmx4t(ah[i][0], ah[i][1], ah[i][2], ah[i][3], (bA) + off);           \
    }

#define MMA3PASS(ACC, BH, BL)                                                 \
    _Pragma("unroll")                                                         \
    for (int i = 0; i < 4; i++)                                               \
        _Pragma("unroll")                                                     \
        for (int j = 0; j < 4; j++) mma_bf16((ACC)[i][j], ah[i], (BH)[j]);    \
    _Pragma("unroll")                                                         \
    for (int i = 0; i < 4; i++)                                               \
        _Pragma("unroll")                                                     \
        for (int j = 0; j < 4; j++) mma_bf16((ACC)[i][j], ah[i], (BL)[j]);    \
    _Pragma("unroll")                                                         \
    for (int i = 0; i < 4; i++)                                               \
        _Pragma("unroll")                                                     \
        for (int j = 0; j < 4; j++) mma_bf16((ACC)[i][j], al[i], (BH)[j]);

#define MMA2PASS(ACC, BH, BL)                                                 \
    _Pragma("unroll")                                                         \
    for (int i = 0; i < 4; i++)                                               \
        _Pragma("unroll")                                                     \
        for (int j = 0; j < 4; j++) mma_bf16((ACC)[i][j], ah[i], (BH)[j]);    \
    _Pragma("unroll")                                                         \
    for (int i = 0; i < 4; i++)                                               \
        _Pragma("unroll")                                                     \
        for (int j = 0; j < 4; j++) mma_bf16((ACC)[i][j], ah[i], (BL)[j]);

#define LOAD_BFRAGS_K(sBh, sBl, ST, BH, BL)                                   \
    _Pragma("unroll")                                                         \
    for (int j = 0; j < 4; j++) {                                             \
        int c = wn * 32 + j * 8 + gr;                                         \
        const __nv_bfloat16* p = (sBh) + c * (ST) + kb + 2 * qp;              \
        const __nv_bfloat16* q = (sBl) + c * (ST) + kb + 2 * qp;              \
        BH[j][0] = L32(p); BH[j][1] = L32(p + 8);                             \
        BL[j][0] = L32(q); BL[j][1] = L32(q + 8);                             \
    }

#define LOAD_BFRAGS_T(bBh, bBl, STB, BH, BL)                                  \
    _Pragma("unroll")                                                         \
    for (int jj = 0; jj < 2; jj++) {                                          \
        int c0 = wn * 32 + jj * 16;                                           \
        uint32_t off = (uint32_t)(((kb + (lane & 15)) * (STB) + c0 +          \
                                   ((lane >> 4) * 8)) * 2);                   \
        ldmx4t(BH[2*jj][0], BH[2*jj][1], BH[2*jj+1][0], BH[2*jj+1][1], (bBh) + off); \
        ldmx4t(BL[2*jj][0], BL[2*jj][1], BL[2*jj+1][0], BL[2*jj+1][1], (bBl) + off); \
    }

#define GEMM_IDS                                                              \
    int t = threadIdx.x;                                                      \
    int wid = t >> 5, lane = t & 31;                                          \
    int wm = wid >> 2, wn = wid & 3;                                          \
    int gr = lane >> 2, qp = lane & 3;                                        \
    int srow = t >> 2, srow2 = (t >> 2) + 64, kc = (t & 3) * 8;

#define ACC_INIT(A)                                                           \
    _Pragma("unroll")                                                         \
    for (int i = 0; i < 4; i++)                                               \
        _Pragma("unroll")                                                     \
        for (int j = 0; j < 4; j++)                                           \
            _Pragma("unroll")                                                 \
            for (int e = 0; e < 4; e++) (A)[i][j][e] = 0.f;

// ---------------- conv_uq ----------------------------------------------------
__global__ void conv_uq_kernel(const float* __restrict__ Uq,
                               const float* __restrict__ wcw) {
    __shared__ float red[8];
    int row = blockIdx.x;
    int t = threadIdx.x;
    const float* src = Uq + (size_t)row * HH;
    float4 v = *(const float4*)(src + t * 4);
    float4 wd = *(const float4*)(wcw + 2 * HH + t * 4);
    float4 wq = *(const float4*)(wcw + HH + t * 4);
    __nv_bfloat16 h0, l0, h1, l1, h2, l2, h3, l3;
    bsplit(v.x, h0, l0); bsplit(v.y, h1, l1);
    bsplit(v.z, h2, l2); bsplit(v.w, h3, l3);
    size_t o = (size_t)row * HH + t * 4;
    *(__nv_bfloat162*)(g_Uqph + o)     = __nv_bfloat162(h0, h1);
    *(__nv_bfloat162*)(g_Uqph + o + 2) = __nv_bfloat162(h2, h3);
    *(__nv_bfloat162*)(g_Uqpl + o)     = __nv_bfloat162(l0, l1);
    *(__nv_bfloat162*)(g_Uqpl + o + 2) = __nv_bfloat162(l2, l3);
    float4 s = make_float4(v.x * wd.x, v.y * wd.y, v.z * wd.z, v.w * wd.w);
    bsplit(s.x, h0, l0); bsplit(s.y, h1, l1);
    bsplit(s.z, h2, l2); bsplit(s.w, h3, l3);
    *(__nv_bfloat162*)(g_Uqwh + o)     = __nv_bfloat162(h0, h1);
    *(__nv_bfloat162*)(g_Uqwh + o + 2) = __nv_bfloat162(h2, h3);
    *(__nv_bfloat162*)(g_Uqwl + o)     = __nv_bfloat162(l0, l1);
    *(__nv_bfloat162*)(g_Uqwl + o + 2) = __nv_bfloat162(l2, l3);
    float p = v.x * wq.x + v.y * wq.y + v.z * wq.z + v.w * wq.w;
    #pragma unroll
    for (int off = 16; off; off >>= 1) p += __shfl_xor_sync(0xffffffffu, p, off);
    if ((t & 31) == 0) red[t >> 5] = p;
    __syncthreads();
    if (t == 0) {
        float sum = 0.f;
        #pragma unroll
        for (int j = 0; j < 8; j++) sum += red[j];
        g_sq[row] = sum;
    }
}

// ---------------- GEMM1 fused: P1, P1F=exp(S), col partials, s_d -------------
__global__ __launch_bounds__(256) void gemm1_mma(
    const float* __restrict__ Ud, const float* __restrict__ wcw,
    const float* __restrict__ wcb,
    const int* __restrict__ qm, const int* __restrict__ dmk) {
    extern __shared__ __nv_bfloat16 dyn[];
    __shared__ float redM[128][4], redS[128][4];
    __shared__ float2 colp[2][128];
    __shared__ int s_qm[128];
    __shared__ float s_sdv[128];
    __shared__ float s_wd[HH];
    GEMM_IDS
    int b = blockIdx.y, m0 = blockIdx.x * 128;
    const float* A = Ud + (size_t)b * DD * HH + (size_t)m0 * HH;
    const __nv_bfloat16* Bh = g_Uqwh + (size_t)b * QQ * HH;
    const __nv_bfloat16* Bl = g_Uqwl + (size_t)b * QQ * HH;
    float acc[4][4][4];
    ACC_INIT(acc)
    float sdp[4] = {0.f, 0.f, 0.f, 0.f};
    if (t < 128) s_qm[t] = qm[b * QQ + t];
    #pragma unroll
    for (int i = t; i < HH; i += 256) s_wd[i] = wcw[i];
    uint32_t sbB0 = smem_u32(dyn) + 40960;

    float4 pref[4];
    #pragma unroll
    for (int v = 0; v < 4; v++) {
        int idx = v * 256 + t;
        pref[v] = *(const float4*)(A + (size_t)(idx >> 3) * HH + (idx & 7) * 4);
    }
    CPA16(sbB0 +         srow  * 80 + kc * 2, Bh + (size_t)srow  * HH + kc);
    CPA16(sbB0 +         srow2 * 80 + kc * 2, Bh + (size_t)srow2 * HH + kc);
    CPA16(sbB0 + 10240 + srow  * 80 + kc * 2, Bl + (size_t)srow  * HH + kc);
    CPA16(sbB0 + 10240 + srow2 * 80 + kc * 2, Bl + (size_t)srow2 * HH + kc);
    CPA_COMMIT();
    __syncthreads();   // s_wd ready

    for (int it = 0; it < HH / 32; it++) {
        CPA_WAIT0();
        __nv_bfloat16* As = dyn + (it & 1) * 10240;
        #pragma unroll
        for (int v = 0; v < 4; v++) {
            int idx = v * 256 + t;
            int row = idx >> 3, cs = (idx & 7) * 4;
            float4 x = pref[v];
            float4 w = *(const float4*)(s_wd + it * 32 + cs);
            sdp[v] += x.x * w.x + x.y * w.y + x.z * w.z + x.w * w.w;
            __nv_bfloat16 h0, l0, h1, l1, h2, l2, h3, l3;
            bsplit(x.x, h0, l0); bsplit(x.y, h1, l1);
            bsplit(x.z, h2, l2); bsplit(x.w, h3, l3);
            *(__nv_bfloat162*)(As + row * 40 + cs)            = __nv_bfloat162(h0, h1);
            *(__nv_bfloat162*)(As + row * 40 + cs + 2)        = __nv_bfloat162(h2, h3);
            *(__nv_bfloat162*)(As + 5120 + row * 40 + cs)     = __nv_bfloat162(l0, l1);
            *(__nv_bfloat162*)(As + 5120 + row * 40 + cs + 2) = __nv_bfloat162(l2, l3);
        }
        __syncthreads();
        if (it + 1 < HH / 32) {
            int k0 = (it + 1) * 32;
            uint32_t sbB = sbB0 + ((it + 1) & 1) * 20480;
            CPA16(sbB +         srow  * 80 + kc * 2, Bh + (size_t)srow  * HH + k0 + kc);
            CPA16(sbB +         srow2 * 80 + kc * 2, Bh + (size_t)srow2 * HH + k0 + kc);
            CPA16(sbB + 10240 + srow  * 80 + kc * 2, Bl + (size_t)srow  * HH + k0 + kc);
            CPA16(sbB + 10240 + srow2 * 80 + kc * 2, Bl + (size_t)srow2 * HH + k0 + kc);
            CPA_COMMIT();
            #pragma unroll
            for (int v = 0; v < 4; v++) {
                int idx = v * 256 + t;
                pref[v] = *(const float4*)(A + (size_t)(idx >> 3) * HH + k0 + (idx & 7) * 4);
            }
        }
        const __nv_bfloat16* cA = dyn + (it & 1) * 10240;
        const __nv_bfloat16* cB = dyn + 20480 + (it & 1) * 10240;
        #pragma unroll
        for (int kb = 0; kb < 32; kb += 16) {
            LOAD_AFRAGS(cA, cA + 5120, 40)
            uint32_t bh[4][2], bl[4][2];
            LOAD_BFRAGS_K(cB, cB + 5120, 40, bh, bl)
            MMA3PASS(acc, bh, bl)
        }
    }

    // s_d reduce
    #pragma unroll
    for (int v = 0; v < 4; v++) {
        float s = sdp[v];
        s += __shfl_xor_sync(0xffffffffu, s, 1);
        s += __shfl_xor_sync(0xffffffffu, s, 2);
        s += __shfl_xor_sync(0xffffffffu, s, 4);
        if ((lane & 7) == 0) s_sdv[v * 32 + (t >> 3)] = s;
    }

    float bias = wcb[0];
    int dmv[4][2];
    #pragma unroll
    for (int i = 0; i < 4; i++)
        #pragma unroll
        for (int rr = 0; rr < 2; rr++)
            dmv[i][rr] = dmk[b * DD + m0 + wm * 64 + i * 16 + rr * 8 + gr];
    __syncthreads();
    float sdv[4][2];
    #pragma unroll
    for (int i = 0; i < 4; i++)
        #pragma unroll
        for (int rr = 0; rr < 2; rr++)
            sdv[i][rr] = s_sdv[wm * 64 + i * 16 + rr * 8 + gr] + bias;

    #pragma unroll
    for (int i = 0; i < 4; i++)
        #pragma unroll
        for (int j = 0; j < 4; j++) {
            int n = wn * 32 + j * 8 + 2 * qp;
            float sq0 = g_sq[b * QQ + n], sq1 = g_sq[b * QQ + n + 1];
            int q0 = s_qm[n] > 0, q1 = s_qm[n + 1] > 0;
            #pragma unroll
            for (int rr = 0; rr < 2; rr++) {
                float s0 = acc[i][j][2 * rr]     + sdv[i][rr] + sq0;
                float s1 = acc[i][j][2 * rr + 1] + sdv[i][rr] + sq1;
                int dm = dmv[i][rr] > 0;
                acc[i][j][2 * rr]     = (dm && q0) ? s0 : -1e30f;
                acc[i][j][2 * rr + 1] = (dm && q1) ? s1 : -1e30f;
            }
        }

    // row softmax max
    float M[4][2];
    #pragma unroll
    for (int i = 0; i < 4; i++)
        #pragma unroll
        for (int rr = 0; rr < 2; rr++) {
            float mx = -1e30f;
            #pragma unroll
            for (int j = 0; j < 4; j++)
                mx = fmaxf(mx, fmaxf(acc[i][j][2 * rr], acc[i][j][2 * rr + 1]));
            mx = fmaxf(mx, __shfl_xor_sync(0xffffffffu, mx, 1));
            mx = fmaxf(mx, __shfl_xor_sync(0xffffffffu, mx, 2));
            if (qp == 0) redM[wm * 64 + i * 16 + rr * 8 + gr][wn] = mx;
        }
    __syncthreads();
    #pragma unroll
    for (int i = 0; i < 4; i++)
        #pragma unroll
        for (int rr = 0; rr < 2; rr++) {
            int r = wm * 64 + i * 16 + rr * 8 + gr;
            M[i][rr] = fmaxf(fmaxf(redM[r][0], redM[r][1]),
                             fmaxf(redM[r][2], redM[r][3]));
        }
    // row softmax sum
    float inv[4][2], Fv[4][2];
    #pragma unroll
    for (int i = 0; i < 4; i++)
        #pragma unroll
        for (int rr = 0; rr < 2; rr++) {
            float s = 0.f;
            #pragma unroll
            for (int j = 0; j < 4; j++) {
                s += __expf(acc[i][j][2 * rr]     - M[i][rr]);
                s += __expf(acc[i][j][2 * rr + 1] - M[i][rr]);
            }
            s += __shfl_xor_sync(0xffffffffu, s, 1);
            s += __shfl_xor_sync(0xffffffffu, s, 2);
            if (qp == 0) redS[wm * 64 + i * 16 + rr * 8 + gr][wn] = s;
        }
    __syncthreads();
    #pragma unroll
    for (int i = 0; i < 4; i++)
        #pragma unroll
        for (int rr = 0; rr < 2; rr++) {
            int r = wm * 64 + i * 16 + rr * 8 + gr;
            float tot = redS[r][0] + redS[r][1] + redS[r][2] + redS[r][3];
            inv[i][rr] = 1.f / tot;
            Fv[i][rr] = tot * __expf(M[i][rr]);   // rowSum * exp(rowMax)
        }
    // P1 + P1F writes
    #pragma unroll
    for (int i = 0; i < 4; i++)
        #pragma unroll
        for (int j = 0; j < 4; j++) {
            int n = wn * 32 + j * 8 + 2 * qp;
            int q0 = s_qm[n] > 0, q1 = s_qm[n + 1] > 0;
            #pragma unroll
            for (int rr = 0; rr < 2; rr++) {
                int m = m0 + wm * 64 + i * 16 + rr * 8 + gr;
                int dm = dmv[i][rr] > 0;
                float p0 = (dm && q0) ? __expf(acc[i][j][2 * rr]     - M[i][rr]) * inv[i][rr] : 0.f;
                float p1 = (dm && q1) ? __expf(acc[i][j][2 * rr + 1] - M[i][rr]) * inv[i][rr] : 0.f;
                size_t o = ((size_t)b * DD + m) * QQ + n;
                *(__nv_bfloat162*)(g_P1h + o) =
                    __nv_bfloat162(__float2bfloat16(p0), __float2bfloat16(p1));
                *(__nv_bfloat162*)(g_P1Fh + o) =
                    __nv_bfloat162(__float2bfloat16(p0 * Fv[i][rr]),
                                   __float2bfloat16(p1 * Fv[i][rr]));
            }
        }
    // column partials
    #pragma unroll
    for (int j = 0; j < 4; j++)
        #pragma unroll
        for (int cc = 0; cc < 2; cc++) {
            float cm = -1e30f;
            #pragma unroll
            for (int i = 0; i < 4; i++)
                #pragma unroll
                for (int rr = 0; rr < 2; rr++)
                    cm = fmaxf(cm, acc[i][j][2 * rr + cc]);
            float cs = 0.f;
            #pragma unroll
            for (int i = 0; i < 4; i++)
                #pragma unroll
                for (int rr = 0; rr < 2; rr++)
                    cs += __expf(acc[i][j][2 * rr + cc] - cm);
            #pragma unroll
            for (int o = 4; o <= 16; o <<= 1) {
                float om = __shfl_xor_sync(0xffffffffu, cm, o);
                float os = __shfl_xor_sync(0xffffffffu, cs, o);
                float nm = fmaxf(cm, om);
                cs = cs * __expf(cm - nm) + os * __expf(om - nm);
                cm = nm;
            }
            if (gr == 0) colp[wm][wn * 32 + j * 8 + 2 * qp + cc] = make_float2(cm, cs);
        }
    __syncthreads();
    if (t < 128) {
        float2 a = colp[0][t], c = colp[1][t];
        float nm = fmaxf(a.x, c.x);
        float s = a.y * __expf(a.x - nm) + c.y * __expf(c.x - nm);
        int idx = (b * 8 + blockIdx.x) * 128 + t;
        g_cmax[idx] = nm; g_csum[idx] = s;
    }
}

// ---------------- GEMM3: T[q,h] = G[q] * sum_d P1Fh[d,q] * Ud[d,h] -----------
// A = P1Fh [d][q] (=[k][m]) via cp.async + ldmatrix.trans on A side.
// stage (elems): A [0,4352) stride 136 | Bh [4352,8704) | Bl [8704,13056).
// stage bytes 26112; x2 = 52224 dyn smem.
__global__ __launch_bounds__(256) void gemm3_mma(const float* __restrict__ Ud,
                                                 const int* __restrict__ qm) {
    extern __shared__ __nv_bfloat16 dyn[];
    __shared__ float s_G[128];
    GEMM_IDS
    (void)srow; (void)srow2;
    int b = blockIdx.y, n0 = blockIdx.x * 128;
    const __nv_bfloat16* Ag = g_P1Fh + (size_t)b * DD * QQ;
    const float* Bg = Ud + (size_t)b * DD * HH + n0;
    float acc[4][4][4];
    ACC_INIT(acc)
    uint32_t sb = smem_u32(dyn);

    // G[q] = exp(-colMax)/colSum (merge 8 block-partials)
    if (t < 128) {
        float m = -1e30f, s = 0.f;
        #pragma unroll
        for (int k = 0; k < 8; k++) {
            float mk = g_cmax[(b * 8 + k) * 128 + t];
            float sk = g_csum[(b * 8 + k) * 128 + t];
            float nm = fmaxf(m, mk);
            s = s * __expf(m - nm) + sk * __expf(mk - nm);
            m = nm;
        }
        float G = 0.f;
        if (qm[b * QQ + t] > 0 && m > -1e29f && s > 0.f)
            G = __expf(-m) / s;
        s_G[t] = G;
    }

    // prologue: A(0) cp.async (32 d-rows x 128 q), B(0) regs
    {
        int c0 = t, c1 = 256 + t;
        CPA16(sb + (c0 >> 4) * 272 + (c0 & 15) * 16, Ag + (size_t)(c0 >> 4) * QQ + (c0 & 15) * 8);
        CPA16(sb + (c1 >> 4) * 272 + (c1 & 15) * 16, Ag + (size_t)(c1 >> 4) * QQ + (c1 & 15) * 8);
    }
    CPA_COMMIT();
    float4 pref[4];
    #pragma unroll
    for (int v = 0; v < 4; v++) {
        int idx = v * 256 + t;
        pref[v] = *(const float4*)(Bg + (size_t)(idx >> 5) * HH + (idx & 31) * 4);
    }

    for (int it = 0; it < DD / 32; it++) {
        CPA_WAIT0();
        __nv_bfloat16* Bs = dyn + (it & 1) * 13056 + 4352;
        #pragma unroll
        for (int v = 0; v < 4; v++) {
            int idx = v * 256 + t;
            int dr = idx >> 5, hc = (idx & 31) * 4;
            float4 x = pref[v];
            __nv_bfloat16 h0, l0, h1, l1, h2, l2, h3, l3;
            bsplit(x.x, h0, l0); bsplit(x.y, h1, l1);
            bsplit(x.z, h2, l2); bsplit(x.w, h3, l3);
            *(__nv_bfloat162*)(Bs + dr * 136 + hc)            = __nv_bfloat162(h0, h1);
            *(__nv_bfloat162*)(Bs + dr * 136 + hc + 2)        = __nv_bfloat162(h2, h3);
            *(__nv_bfloat162*)(Bs + 4352 + dr * 136 + hc)     = __nv_bfloat162(l0, l1);
            *(__nv_bfloat162*)(Bs + 4352 + dr * 136 + hc + 2) = __nv_bfloat162(l2, l3);
        }
        __syncthreads();
        if (it + 1 < DD / 32) {
            int k0 = (it + 1) * 32;
            uint32_t sbA = sb + ((it + 1) & 1) * 26112;
            int c0 = t, c1 = 256 + t;
            CPA16(sbA + (c0 >> 4) * 272 + (c0 & 15) * 16,
                  Ag + (size_t)(k0 + (c0 >> 4)) * QQ + (c0 & 15) * 8);
            CPA16(sbA + (c1 >> 4) * 272 + (c1 & 15) * 16,
                  Ag + (size_t)(k0 + (c1 >> 4)) * QQ + (c1 & 15) * 8);
            CPA_COMMIT();
            #pragma unroll
            for (int v = 0; v < 4; v++) {
                int idx = v * 256 + t;
                pref[v] = *(const float4*)(Bg + (size_t)(k0 + (idx >> 5)) * HH + (idx & 31) * 4);
            }
        }
        uint32_t bA  = sb + (it & 1) * 26112;
        uint32_t bBh = bA + 8704;
        uint32_t bBl = bA + 17408;
        #pragma unroll
        for (int kb = 0; kb < 32; kb += 16) {
            LOAD_AFRAGS_T(bA, 136)
            uint32_t bh[4][2], bl[4][2];
            LOAD_BFRAGS_T(bBh, bBl, 136, bh, bl)
            MMA2PASS(acc, bh, bl)
        }
    }

    // epilogue: scale rows (q) by G, split, store T
    #pragma unroll
    for (int i = 0; i < 4; i++) {
        #pragma unroll
        for (int rr = 0; rr < 2; rr++) {
            int m = wm * 64 + i * 16 + rr * 8 + gr;   // q
            float Gq = s_G[m];
            #pragma unroll
            for (int j = 0; j < 4; j++) {
                int n = n0 + wn * 32 + j * 8 + 2 * qp;
                float a0 = acc[i][j][2 * rr] * Gq, a1 = acc[i][j][2 * rr + 1] * Gq;
                __nv_bfloat16 h0, l0, h1, l1;
                bsplit(a0, h0, l0); bsplit(a1, h1, l1);
                size_t o = ((size_t)b * QQ + m) * HH + n;
                *(__nv_bfloat162*)(g_Th + o) = __nv_bfloat162(h0, h1);
                *(__nv_bfloat162*)(g_Tl + o) = __nv_bfloat162(l0, l1);
            }
        }
    }
}

// ---------------- fused GEMM2+4: all 2-pass, 5 smem tiles --------------------
#define ST24 136
#define TSZ  (128 * ST24)
__global__ __launch_bounds__(256) void gemm24f_mma(
    const float* __restrict__ Ud, float* __restrict__ out) {
    extern __shared__ __nv_bfloat16 dyn[];
    GEMM_IDS
    (void)srow; (void)srow2; (void)kc;
    int b = blockIdx.z, n0 = blockIdx.x * 128, m0 = blockIdx.y * 128;
    const __nv_bfloat16* srcs[5];
    int strides[5];
    srcs[0] = g_P1h  + (size_t)b * DD * QQ + (size_t)m0 * QQ; strides[0] = QQ;
    srcs[1] = g_Uqph + (size_t)b * QQ * HH + n0;              strides[1] = HH;
    srcs[2] = g_Uqpl + (size_t)b * QQ * HH + n0;              strides[2] = HH;
    srcs[3] = g_Th   + (size_t)b * QQ * HH + n0;              strides[3] = HH;
    srcs[4] = g_Tl   + (size_t)b * QQ * HH + n0;              strides[4] = HH;

    uint32_t sb = smem_u32(dyn);
    #pragma unroll
    for (int v = 0; v < 8; v++) {
        int c = v * 256 + t;
        int row = c >> 4, kb8 = (c & 15) * 8;
        #pragma unroll
        for (int s = 0; s < 5; s++)
            CPA16(sb + s * (TSZ * 2) + row * (ST24 * 2) + kb8 * 2,
                  srcs[s] + (size_t)row * strides[s] + kb8);
    }
    CPA_COMMIT();
    CPA_WAIT0();
    __syncthreads();

    float acc2[4][4][4], acc4[4][4][4];
    ACC_INIT(acc2)
    ACC_INIT(acc4)
    const __nv_bfloat16* pA = dyn;
    uint32_t b2h = sb + 1 * (TSZ * 2), b2l = sb + 2 * (TSZ * 2);
    uint32_t b4h = sb + 3 * (TSZ * 2), b4l = sb + 4 * (TSZ * 2);
    #pragma unroll
    for (int s = 0; s < 8; s++) {
        int kb = s * 16;
        LOAD_AFRAGS_H(pA, ST24)
        {
            uint32_t bh[4][2], bl[4][2];
            LOAD_BFRAGS_T(b2h, b2l, ST24, bh, bl)
            MMA2PASS(acc2, bh, bl)
        }
        {
            uint32_t bh[4][2], bl[4][2];
            LOAD_BFRAGS_T(b4h, b4l, ST24, bh, bl)
            MMA2PASS(acc4, bh, bl)
        }
    }

    #pragma unroll
    for (int i = 0; i < 4; i++) {
        int m = m0 + wm * 64 + i * 16 + gr;
        #pragma unroll
        for (int j = 0; j < 4; j++) {
            int n = n0 + wn * 32 + j * 8 + 2 * qp;
            #pragma unroll
            for (int rr = 0; rr < 2; rr++) {
                int mm = m + rr * 8;
                float a2x = acc2[i][j][2 * rr], a2y = acc2[i][j][2 * rr + 1];
                float a4x = acc4[i][j][2 * rr], a4y = acc4[i][j][2 * rr + 1];
                float2 u = *(const float2*)(Ud + ((size_t)b * DD + mm) * HH + n);
                float* ob = out + ((size_t)b * DD + mm) * (size_t)(4 * HH) + n;
                *(float2*)(ob)          = u;
                *(float2*)(ob + HH)     = make_float2(a2x, a2y);
                *(float2*)(ob + 2 * HH) = make_float2(u.x * a2x, u.y * a2y);
                *(float2*)(ob + 3 * HH) = make_float2(u.x * a4x, u.y * a4y);
            }
        }
    }
}

// ---------------------------------------------------------------------------
extern "C" void kernel_launch(void* const* d_in, const int* in_sizes, int n_in,
                              void* d_out, int out_size) {
    const float* Ud  = (const float*)d_in[0];
    const float* Uq  = (const float*)d_in[1];
    const float* wcw = (const float*)d_in[2];
    const float* wcb = (const float*)d_in[3];
    const int*   qm  = (const int*)d_in[4];
    const int*   dmk = (const int*)d_in[5];
    float* out = (float*)d_out;

    cudaFuncSetAttribute(gemm1_mma,   cudaFuncAttributeMaxDynamicSharedMemorySize, 81920);
    cudaFuncSetAttribute(gemm3_mma,   cudaFuncAttributeMaxDynamicSharedMemorySize, 52224);
    cudaFuncSetAttribute(gemm24f_mma, cudaFuncAttributeMaxDynamicSharedMemorySize, 174080);

    conv_uq_kernel<<<BB * QQ, 256>>>(Uq, wcw);

    // logits + row softmax + P1 + exp(S) + col partials + s_d
    gemm1_mma<<<dim3(DD / 128, BB), 256, 81920>>>(Ud, wcw, wcb, qm, dmk);

    // T = G * (exp(S)^T @ Ud)  -- q2d softmax folded in
    gemm3_mma<<<dim3(HH / 128, BB), 256, 52224>>>(Ud, qm);

    // fused A_d2q + A_q2d (both 2-pass), all 4 output slices
    gemm24f_mma<<<dim3(HH / 128, DD / 128, BB), 256, 174080>>>(Ud, out);
}